// round 11
// baseline (speedup 1.0000x reference)
#include <cuda_runtime.h>
#include <cuda_bf16.h>
#include <math.h>
#include <stdint.h>

// ---------------------------------------------------------------------------
// Problem constants
// ---------------------------------------------------------------------------
#define BROWS 1024      // batch
#define CDICT 10000     // dictionary atoms
#define CPAD  10240     // padded dict dim: divisible by 128
#define DM    512       // embedding dim
#define RHO_F 5.0f
#define THR_F 0.002f    // lam / rho
#define EPS_F 1e-12f
#define ADMM_ITERS 100
#define CHEAP_ITERS 75  // 1-product bf16 iters; remainder 3-product polish
#define NS_ITERS 9
#define KSPLIT 4        // loop split-K: 128 CTAs <= 148 SMs (balanced)
#define PSLICES 5

// ---------------------------------------------------------------------------
// Scratch (static device globals -- no cudaMalloc allowed)
// ---------------------------------------------------------------------------
__device__ float          g_Q  [(size_t)BROWS * CPAD];  // Aty, then q (ld=CPAD)
__device__ float          g_U  [(size_t)BROWS * CPAD];  // u
__device__ __nv_bfloat16  g_Vh [(size_t)BROWS * CPAD];  // bf16-hi of v
__device__ __nv_bfloat16  g_Vl [(size_t)BROWS * CPAD];  // bf16-lo of v
__device__ __nv_bfloat16  g_Th [(size_t)BROWS * CPAD];  // Aty split hi (setup)
__device__ __nv_bfloat16  g_Tl [(size_t)BROWS * CPAD];  // Aty split lo (setup)
__device__ __nv_bfloat16  g_Dh [(size_t)CPAD * DM];     // dict hi [CPAD x 512]
__device__ __nv_bfloat16  g_Dl [(size_t)CPAD * DM];
__device__ __nv_bfloat16  g_DTh[(size_t)DM * CPAD];     // D^T hi [512 x CPAD]
__device__ __nv_bfloat16  g_DTl[(size_t)DM * CPAD];
__device__ float          g_E  [(size_t)DM * CPAD];     // E = G^{-1} D^T (fp32)
__device__ __nv_bfloat16  g_Eh [(size_t)DM * CPAD];
__device__ __nv_bfloat16  g_El [(size_t)DM * CPAD];
__device__ float          g_P  [(size_t)PSLICES * BROWS * DM];
__device__ float          g_W  [(size_t)BROWS * DM];
__device__ __nv_bfloat16  g_Wh [(size_t)BROWS * DM];
__device__ __nv_bfloat16  g_Wl [(size_t)BROWS * DM];
__device__ float          g_Y  [(size_t)BROWS * DM];
__device__ __nv_bfloat16  g_Yh [(size_t)BROWS * DM];
__device__ __nv_bfloat16  g_Yl [(size_t)BROWS * DM];
__device__ float g_G [DM * DM];
__device__ float g_XA[DM * DM];
__device__ float g_XB[DM * DM];
__device__ float g_T [DM * DM];
__device__ float g_ninf;
__device__ int   g_cnt[64];              // split-K tile semaphores (32 used)

// ---------------------------------------------------------------------------
// helpers
// ---------------------------------------------------------------------------
__device__ __forceinline__ void split_bf16(float v, __nv_bfloat16& h, __nv_bfloat16& l)
{
    h = __float2bfloat16_rn(v);
    l = __float2bfloat16_rn(v - __bfloat162float(h));
}

__device__ __forceinline__ void mma16(float* c, const unsigned* a,
                                      unsigned b0, unsigned b1)
{
    asm volatile(
        "mma.sync.aligned.m16n8k16.row.col.f32.bf16.bf16.f32 "
        "{%0,%1,%2,%3}, {%4,%5,%6,%7}, {%8,%9}, {%0,%1,%2,%3};"
        : "+f"(c[0]), "+f"(c[1]), "+f"(c[2]), "+f"(c[3])
        : "r"(a[0]), "r"(a[1]), "r"(a[2]), "r"(a[3]), "r"(b0), "r"(b1));
}

__device__ __forceinline__ void ldsm4(unsigned* r, uint32_t a)
{
    asm volatile("ldmatrix.sync.aligned.m8n8.x4.shared.b16 {%0,%1,%2,%3}, [%4];"
                 : "=r"(r[0]), "=r"(r[1]), "=r"(r[2]), "=r"(r[3]) : "r"(a));
}

__device__ __forceinline__ void ldsm4t(unsigned* r, uint32_t a)
{
    asm volatile("ldmatrix.sync.aligned.m8n8.x4.trans.shared.b16 {%0,%1,%2,%3}, [%4];"
                 : "=r"(r[0]), "=r"(r[1]), "=r"(r[2]), "=r"(r[3]) : "r"(a));
}

__device__ __forceinline__ void cp16(uint32_t s, const void* g)
{
    asm volatile("cp.async.cg.shared.global [%0], [%1], 16;"
                 :: "r"(s), "l"(g) : "memory");
}

// ---------------------------------------------------------------------------
// bf16 MMA GEMM, templated on product count and epilogue:
//   PROD==3: acc = Ah*Bh + Ah*Bl + Al*Bh       PROD==1: acc = Ah*Bh
// EPI 0: plain partial store at C + z*M*ldc (split-K, external reduce)
// EPI 1: q = (Qp - acc)/rho -> C (fp32)                      [setup]
// EPI 2: full ADMM: v=Vh+Vl, fp32 Q; writes U, Vh, Vl        [polish]
// EPI 3: cheap ADMM: v=Vh, fp32 Q; writes U, Vh; Vl iff flag [cheap]
// EPI 4: split-K partial + fused semaphore reduce -> Vh (bf16 hi)
// EPI 5: split-K partial + fused semaphore reduce -> Vh, Vl (bf16 hi/lo)
// EPI 6: split-K partial + fused semaphore reduce -> Up (fp32)
// Fused reduce sums slices in fixed order s=0..S-1 (bit-identical to the
// standalone reduce kernels it replaces); last-arriving CTA per tile does it.
// BM=BN=128, BK=32, 256 thr, 8 warps (32x64 warp tile), 2-stage cp.async,
// ldmatrix fragments (conflict-free strides 40 / 136 bf16).
// ---------------------------------------------------------------------------
#define BSTG  37888
#define BSMEM (2 * BSTG)

template<int EPI, int PROD>
__global__ void __launch_bounds__(256, 2)
bmma_gemm(const __nv_bfloat16* __restrict__ Ah, const __nv_bfloat16* __restrict__ Al,
          const __nv_bfloat16* __restrict__ Bh, const __nv_bfloat16* __restrict__ Bl,
          float* __restrict__ C, int M, int N, int Kslice,
          int lda, int ldb, int ldc,
          const float* __restrict__ Qp, float* __restrict__ Up,
          __nv_bfloat16* __restrict__ Vh, __nv_bfloat16* __restrict__ Vl,
          int flag)
{
    extern __shared__ char smd[];
    const int tid  = threadIdx.x;
    const int lane = tid & 31, wid = tid >> 5;
    const int wm = (wid & 3) * 32;
    const int wn = (wid >> 2) * 64;
    const int m0 = blockIdx.y * 128, n0 = blockIdx.x * 128;
    const long k0 = (long)blockIdx.z * Kslice;
    const int nk = Kslice >> 5;

    const int aRow = wm + ((lane >> 3) & 1) * 8 + (lane & 7);
    const int aKof = (lane >> 4) * 8;
    const int bRow = ((lane >> 3) & 1) * 8 + (lane & 7);
    const int bNof = (lane >> 4) * 8;

    float c[2][8][4];
#pragma unroll
    for (int i = 0; i < 2; ++i)
#pragma unroll
        for (int j = 0; j < 8; ++j)
#pragma unroll
            for (int q = 0; q < 4; ++q) c[i][j][q] = 0.0f;

    auto load_tile = [&](int kt, int buf) {
        char* base = smd + buf * BSTG;
        const int kb = kt * 32;
#pragma unroll
        for (int cc = 0; cc < 2; ++cc) {        // A: 128 rows x 4 chunks (8 bf16)
            int ch  = tid * 2 + cc;
            int row = ch >> 2, kc = (ch & 3) * 8;
            uint32_t so = (uint32_t)__cvta_generic_to_shared(
                base + (row * 40 + kc) * 2);
            const long go = (long)(m0 + row) * lda + k0 + kb + kc;
            cp16(so, Ah + go);
            if (PROD == 3) cp16(so + 10240, Al + go);
        }
#pragma unroll
        for (int cc = 0; cc < 2; ++cc) {        // B: 32 rows x 16 chunks
            int ch  = tid * 2 + cc;
            int row = ch >> 4, nc = (ch & 15) * 8;
            uint32_t so = (uint32_t)__cvta_generic_to_shared(
                base + 20480 + (row * 136 + nc) * 2);
            const long go = (long)(k0 + kb + row) * ldb + n0 + nc;
            cp16(so, Bh + go);
            if (PROD == 3) cp16(so + 8704, Bl + go);
        }
    };

    load_tile(0, 0);
    asm volatile("cp.async.commit_group;" ::: "memory");

    for (int kt = 0; kt < nk; ++kt) {
        asm volatile("cp.async.wait_group 0;" ::: "memory");
        __syncthreads();
        if (kt + 1 < nk) load_tile(kt + 1, (kt + 1) & 1);
        asm volatile("cp.async.commit_group;" ::: "memory");

        const uint32_t sb = (uint32_t)__cvta_generic_to_shared(smd + (kt & 1) * BSTG);

#pragma unroll
        for (int ks = 0; ks < 2; ++ks) {
            unsigned ah[2][4], al[2][4];
#pragma unroll
            for (int i = 0; i < 2; ++i) {
                uint32_t ad = sb + ((aRow + i * 16) * 40 + ks * 16 + aKof) * 2;
                ldsm4(ah[i], ad);
                if (PROD == 3) ldsm4(al[i], ad + 10240);
            }
#pragma unroll
            for (int ng = 0; ng < 4; ++ng) {
                unsigned bh[4], bl[4];
                uint32_t bd = sb + 20480 +
                              ((bRow + ks * 16) * 136 + wn + ng * 16 + bNof) * 2;
                ldsm4t(bh, bd);
                if (PROD == 3) ldsm4t(bl, bd + 8704);
#pragma unroll
                for (int jj = 0; jj < 2; ++jj) {
                    const int j = ng * 2 + jj;
#pragma unroll
                    for (int i = 0; i < 2; ++i) {
                        mma16(c[i][j], ah[i], bh[jj * 2], bh[jj * 2 + 1]);
                        if (PROD == 3) {
                            mma16(c[i][j], ah[i], bl[jj * 2], bl[jj * 2 + 1]);
                            mma16(c[i][j], al[i], bh[jj * 2], bh[jj * 2 + 1]);
                        }
                    }
                }
            }
        }
    }

    // ---- epilogue ----
    const int gq = lane >> 2, tq = lane & 3;
#pragma unroll
    for (int i = 0; i < 2; ++i) {
        const int r0 = m0 + wm + i * 16 + gq;
#pragma unroll
        for (int j = 0; j < 8; ++j) {
            const int ccn = n0 + wn + j * 8 + 2 * tq;
            if (ccn >= N) continue;
            if (EPI == 0 || EPI >= 4) {
                float* Cz = C + (long)blockIdx.z * (long)M * ldc;
                *(float2*)&Cz[(long)r0 * ldc + ccn] =
                    make_float2(c[i][j][0], c[i][j][1]);
                *(float2*)&Cz[(long)(r0 + 8) * ldc + ccn] =
                    make_float2(c[i][j][2], c[i][j][3]);
            } else if (EPI == 1) {
#pragma unroll
                for (int rr = 0; rr < 2; ++rr) {
                    const long idx = (long)(r0 + rr * 8) * ldc + ccn;
                    const float ir = 1.0f / RHO_F;
                    float2 qv = *(const float2*)&Qp[idx];
                    *(float2*)&C[idx] = make_float2(
                        (qv.x - c[i][j][rr * 2 + 0]) * ir,
                        (qv.y - c[i][j][rr * 2 + 1]) * ir);
                }
            } else if (EPI == 2) {
#pragma unroll
                for (int rr = 0; rr < 2; ++rr) {
                    const long idx = (long)(r0 + rr * 8) * ldc + ccn;
                    float a0 = c[i][j][rr * 2 + 0], a1 = c[i][j][rr * 2 + 1];
                    float2 qv = *(const float2*)&Qp[idx];
                    float2 uv = *(const float2*)&Up[idx];
                    __nv_bfloat162 vh2 = *(const __nv_bfloat162*)&Vh[idx];
                    __nv_bfloat162 vl2 = *(const __nv_bfloat162*)&Vl[idx];
                    float2 un;
                    __nv_bfloat162 nh, nl;
                    {
                        float v = __bfloat162float(vh2.x) + __bfloat162float(vl2.x);
                        float x = qv.x + v - a0;
                        float z = fmaxf(x + uv.x - THR_F, 0.f);
                        un.x = uv.x + x - z;
                        float vn = flag ? z : (2.f * z - uv.x - x);
                        split_bf16(vn, nh.x, nl.x);
                    }
                    {
                        float v = __bfloat162float(vh2.y) + __bfloat162float(vl2.y);
                        float x = qv.y + v - a1;
                        float z = fmaxf(x + uv.y - THR_F, 0.f);
                        un.y = uv.y + x - z;
                        float vn = flag ? z : (2.f * z - uv.y - x);
                        split_bf16(vn, nh.y, nl.y);
                    }
                    *(float2*)&Up[idx] = un;
                    *(__nv_bfloat162*)&Vh[idx] = nh;
                    *(__nv_bfloat162*)&Vl[idx] = nl;
                }
            } else if (EPI == 3) { // cheap ADMM (v = Vh only, fp32 q; Vl iff flag)
#pragma unroll
                for (int rr = 0; rr < 2; ++rr) {
                    const long idx = (long)(r0 + rr * 8) * ldc + ccn;
                    float a0 = c[i][j][rr * 2 + 0], a1 = c[i][j][rr * 2 + 1];
                    float2 qv = *(const float2*)&Qp[idx];
                    float2 uv = *(const float2*)&Up[idx];
                    __nv_bfloat162 vh2 = *(const __nv_bfloat162*)&Vh[idx];
                    float2 un;
                    __nv_bfloat162 nh, nl;
                    {
                        float x = qv.x + __bfloat162float(vh2.x) - a0;
                        float z = fmaxf(x + uv.x - THR_F, 0.f);
                        un.x = uv.x + x - z;
                        float vn = 2.f * z - uv.x - x;
                        split_bf16(vn, nh.x, nl.x);
                    }
                    {
                        float x = qv.y + __bfloat162float(vh2.y) - a1;
                        float z = fmaxf(x + uv.y - THR_F, 0.f);
                        un.y = uv.y + x - z;
                        float vn = 2.f * z - uv.y - x;
                        split_bf16(vn, nh.y, nl.y);
                    }
                    *(float2*)&Up[idx] = un;
                    *(__nv_bfloat162*)&Vh[idx] = nh;
                    if (flag) *(__nv_bfloat162*)&Vl[idx] = nl;
                }
            }
        }
    }

    // ---- fused split-K semaphore reduce (EPI 4/5/6) ----
    if (EPI >= 4) {
        __shared__ int s_old;
        __syncthreads();
        if (tid == 0) {
            __threadfence();
            s_old = atomicAdd(&g_cnt[blockIdx.y * gridDim.x + blockIdx.x], 1);
        }
        __syncthreads();
        if (s_old == (int)gridDim.z - 1) {
            __threadfence();
            const int S = gridDim.z;
            // tile is always full (N=512 for these launches): 128x128 floats
            for (int e = tid; e < 128 * 64; e += 256) {
                const int r   = e >> 6;          // 0..127
                const int cc2 = e & 63;          // float2 column
                const long base = (long)(m0 + r) * ldc + n0 + cc2 * 2;
                float2 s = *(const float2*)&C[base];
                for (int z = 1; z < S; ++z) {
                    float2 t = *(const float2*)&C[(long)z * M * ldc + base];
                    s.x += t.x; s.y += t.y;
                }
                if (EPI == 6) {
                    *(float2*)&Up[base] = s;
                } else {
                    __nv_bfloat162 h, l;
                    split_bf16(s.x, h.x, l.x);
                    split_bf16(s.y, h.y, l.y);
                    *(__nv_bfloat162*)&Vh[base] = h;
                    if (EPI == 5) *(__nv_bfloat162*)&Vl[base] = l;
                }
            }
            __syncthreads();
            if (tid == 0)
                g_cnt[blockIdx.y * gridDim.x + blockIdx.x] = 0;
        }
    }
}

// ---------------------------------------------------------------------------
// SIMT tiled SGEMM (setup path: G, NS, E -- full fp32 accuracy)
// ---------------------------------------------------------------------------
#define BM 128
#define BN 128
#define BKK 16

template<bool TA, bool TB>
__global__ void __launch_bounds__(256, 2)
gemm_kernel(const float* __restrict__ A, const float* __restrict__ B,
            float* __restrict__ C,
            int M, int N, int Kslice, int lda, int ldb, int ldc)
{
    __shared__ float As[BKK][BM + 4];
    __shared__ float Bs[BKK][BN + 4];

    const int tid = threadIdx.x;
    const int tx  = tid & 15;
    const int ty  = tid >> 4;
    const int m0  = blockIdx.y * BM;
    const int n0  = blockIdx.x * BN;

    const long k0 = (long)blockIdx.z * Kslice;
    if (TA) A += k0 * lda; else A += k0;
    if (TB) B += k0;       else B += k0 * ldb;
    C += (long)blockIdx.z * (long)M * ldc;

    float acc[8][8];
#pragma unroll
    for (int i = 0; i < 8; ++i)
#pragma unroll
        for (int j = 0; j < 8; ++j) acc[i][j] = 0.0f;

    const int nk = Kslice / BKK;
#pragma unroll 1
    for (int kt = 0; kt < nk; ++kt) {
        const int kbase = kt * BKK;
        if (!TA) {
#pragma unroll
            for (int p = 0; p < 2; ++p) {
                const int row = p * 64 + (tid >> 2);
                const int c4  = (tid & 3) * 4;
                float4 v = *(const float4*)&A[(long)(m0 + row) * lda + kbase + c4];
                As[c4 + 0][row] = v.x; As[c4 + 1][row] = v.y;
                As[c4 + 2][row] = v.z; As[c4 + 3][row] = v.w;
            }
        } else {
#pragma unroll
            for (int p = 0; p < 2; ++p) {
                const int kr = p * 8 + (tid >> 5);
                const int m4 = (tid & 31) * 4;
                float4 v = *(const float4*)&A[(long)(kbase + kr) * lda + m0 + m4];
                *(float4*)&As[kr][m4] = v;
            }
        }
        if (!TB) {
#pragma unroll
            for (int p = 0; p < 2; ++p) {
                const int kr  = p * 8 + (tid >> 5);
                const int nn4 = (tid & 31) * 4;
                const int gn  = n0 + nn4;
                float4 v = make_float4(0.f, 0.f, 0.f, 0.f);
                if (gn < N) v = *(const float4*)&B[(long)(kbase + kr) * ldb + gn];
                *(float4*)&Bs[kr][nn4] = v;
            }
        } else {
#pragma unroll
            for (int p = 0; p < 2; ++p) {
                const int nrow = p * 64 + (tid >> 2);
                const int c4   = (tid & 3) * 4;
                const int gn   = n0 + nrow;
                float4 v = make_float4(0.f, 0.f, 0.f, 0.f);
                if (gn < N) v = *(const float4*)&B[(long)gn * ldb + kbase + c4];
                Bs[c4 + 0][nrow] = v.x; Bs[c4 + 1][nrow] = v.y;
                Bs[c4 + 2][nrow] = v.z; Bs[c4 + 3][nrow] = v.w;
            }
        }
        __syncthreads();
#pragma unroll
        for (int kk = 0; kk < BKK; ++kk) {
            float a[8], b[8];
            *(float4*)&a[0] = *(const float4*)&As[kk][ty * 4];
            *(float4*)&a[4] = *(const float4*)&As[kk][64 + ty * 4];
            *(float4*)&b[0] = *(const float4*)&Bs[kk][tx * 4];
            *(float4*)&b[4] = *(const float4*)&Bs[kk][64 + tx * 4];
#pragma unroll
            for (int i = 0; i < 8; ++i)
#pragma unroll
                for (int j = 0; j < 8; ++j)
                    acc[i][j] = fmaf(a[i], b[j], acc[i][j]);
        }
        __syncthreads();
    }

    int rows[8];
#pragma unroll
    for (int i = 0; i < 8; ++i)
        rows[i] = m0 + (i < 4 ? ty * 4 + i : 64 + ty * 4 + (i - 4));

#pragma unroll
    for (int i = 0; i < 8; ++i) {
#pragma unroll
        for (int jg = 0; jg < 2; ++jg) {
            const int cn = n0 + jg * 64 + tx * 4;
            if (cn >= N) continue;
            const long idx = (long)rows[i] * ldc + cn;
            *(float4*)&C[idx] = make_float4(acc[i][jg * 4 + 0], acc[i][jg * 4 + 1],
                                            acc[i][jg * 4 + 2], acc[i][jg * 4 + 3]);
        }
    }
}

// ---------------------------------------------------------------------------
// Transpose + bf16 split: out[i*ldo + j] = split(src[j*lds + i]), i<R, j<C
// ---------------------------------------------------------------------------
__global__ void trans_split_kernel(const float* __restrict__ src, int lds,
                                   __nv_bfloat16* __restrict__ dh,
                                   __nv_bfloat16* __restrict__ dl,
                                   int ldo, int R, int C)
{
    __shared__ float t[32][33];
    const int i0 = blockIdx.x * 32;
    const int j0 = blockIdx.y * 32;
    const int tx = threadIdx.x, ty = threadIdx.y;
    for (int jj = ty; jj < 32; jj += 8) {
        const int j = j0 + jj, i = i0 + tx;
        float v = 0.f;
        if (j < C && i < R) v = src[(long)j * lds + i];
        t[jj][tx] = v;
    }
    __syncthreads();
    for (int ii = ty; ii < 32; ii += 8) {
        const int i = i0 + ii, j = j0 + tx;
        if (i < R && j < C) {
            __nv_bfloat16 h, l;
            split_bf16(t[tx][ii], h, l);
            dh[(long)i * ldo + j] = h;
            dl[(long)i * ldo + j] = l;
        }
    }
}

// ---------------------------------------------------------------------------
// Reductions / splits (setup-only now)
// ---------------------------------------------------------------------------
__global__ void reduce_sum(const float4* __restrict__ P, float4* __restrict__ out,
                           int n4, int S)
{
    int i = blockIdx.x * blockDim.x + threadIdx.x;
    if (i >= n4) return;
    float4 s = P[i];
    for (int k = 1; k < S; ++k) {
        float4 t = P[(long)k * n4 + i];
        s.x += t.x; s.y += t.y; s.z += t.z; s.w += t.w;
    }
    out[i] = s;
}

__global__ void split_mat_bf16(const float2* __restrict__ src,
                               __nv_bfloat162* __restrict__ hi,
                               __nv_bfloat162* __restrict__ lo, long n2)
{
    long i = (long)blockIdx.x * blockDim.x + threadIdx.x;
    if (i >= n2) return;
    float2 v = src[i];
    __nv_bfloat162 h, l;
    split_bf16(v.x, h.x, l.x);
    split_bf16(v.y, h.y, l.y);
    hi[i] = h; lo[i] = l;
}

__global__ void reduce_G(const float* __restrict__ P, float* __restrict__ G, int S)
{
    int i = blockIdx.x * blockDim.x + threadIdx.x;
    if (i >= DM * DM) return;
    float s = 0.f;
    for (int k = 0; k < S; ++k) s += P[(long)k * DM * DM + i];
    if ((i / DM) == (i % DM)) s += RHO_F;
    G[i] = s;
}

__global__ void reduce_ns(const float4* __restrict__ P, const float4* __restrict__ Xc,
                          float4* __restrict__ Xn, int n4, int S)
{
    int i = blockIdx.x * blockDim.x + threadIdx.x;
    if (i >= n4) return;
    float4 s = P[i];
    for (int k = 1; k < S; ++k) {
        float4 t = P[(long)k * n4 + i];
        s.x += t.x; s.y += t.y; s.z += t.z; s.w += t.w;
    }
    float4 x = Xc[i];
    Xn[i] = make_float4(2.f * x.x - s.x, 2.f * x.y - s.y,
                        2.f * x.z - s.z, 2.f * x.w - s.w);
}

__global__ void ninf_kernel(const float* __restrict__ G)
{
    __shared__ float sm[DM];
    const int i = threadIdx.x;
    float s = 0.f;
    for (int j = 0; j < DM; ++j) s += fabsf(G[(long)j * DM + i]);
    sm[i] = s;
    __syncthreads();
    for (int o = DM / 2; o > 0; o >>= 1) {
        if (i < o) sm[i] = fmaxf(sm[i], sm[i + o]);
        __syncthreads();
    }
    if (i == 0) g_ninf = sm[0];
}

__global__ void x0_kernel(float* __restrict__ X)
{
    int i = blockIdx.x * blockDim.x + threadIdx.x;
    if (i >= DM * DM) return;
    float c = 2.0f / (RHO_F + g_ninf);
    X[i] = ((i / DM) == (i % DM)) ? c : 0.0f;
}

// ---------------------------------------------------------------------------
// Row-normalize kernels
// ---------------------------------------------------------------------------
__device__ __forceinline__ float block_sum128(float v, float* red)
{
    for (int o = 16; o > 0; o >>= 1) v += __shfl_xor_sync(0xffffffff, v, o);
    if ((threadIdx.x & 31) == 0) red[threadIdx.x >> 5] = v;
    __syncthreads();
    float tot = red[0] + red[1] + red[2] + red[3];
    __syncthreads();
    return tot;
}

__global__ void norm_center_kernel(const float* __restrict__ img,
                                   const float* __restrict__ mean,
                                   float* __restrict__ out)
{
    __shared__ float red[4];
    const int r = blockIdx.x, t = threadIdx.x;
    float4 v = ((const float4*)(img + (long)r * DM))[t];
    float ss = v.x * v.x + v.y * v.y + v.z * v.z + v.w * v.w;
    float inv = 1.0f / fmaxf(sqrtf(block_sum128(ss, red)), EPS_F);
    float4 mv = ((const float4*)mean)[t];
    float4 c = make_float4(v.x * inv - mv.x, v.y * inv - mv.y,
                           v.z * inv - mv.z, v.w * inv - mv.w);
    float ss2 = c.x * c.x + c.y * c.y + c.z * c.z + c.w * c.w;
    float inv2 = 1.0f / fmaxf(sqrtf(block_sum128(ss2, red)), EPS_F);
    ((float4*)(out + (long)r * DM))[t] =
        make_float4(c.x * inv2, c.y * inv2, c.z * inv2, c.w * inv2);
}

__global__ void norm_rows_kernel(const float* __restrict__ in, float* __restrict__ out)
{
    __shared__ float red[4];
    const int r = blockIdx.x, t = threadIdx.x;
    float4 v = ((const float4*)(in + (long)r * DM))[t];
    float ss = v.x * v.x + v.y * v.y + v.z * v.z + v.w * v.w;
    float inv = 1.0f / fmaxf(sqrtf(block_sum128(ss, red)), EPS_F);
    ((float4*)(out + (long)r * DM))[t] =
        make_float4(v.x * inv, v.y * inv, v.z * inv, v.w * inv);
}

__global__ void final_norm_kernel(const float* __restrict__ rec,
                                  const float* __restrict__ mean,
                                  float* __restrict__ out)
{
    __shared__ float red[4];
    const int r = blockIdx.x, t = threadIdx.x;
    float4 v = ((const float4*)(rec + (long)r * DM))[t];
    float ss = v.x * v.x + v.y * v.y + v.z * v.z + v.w * v.w;
    float inv = 1.0f / fmaxf(sqrtf(block_sum128(ss, red)), EPS_F);
    float4 mv = ((const float4*)mean)[t];
    float4 c = make_float4(v.x * inv + mv.x, v.y * inv + mv.y,
                           v.z * inv + mv.z, v.w * inv + mv.w);
    float ss2 = c.x * c.x + c.y * c.y + c.z * c.z + c.w * c.w;
    float inv2 = 1.0f / fmaxf(sqrtf(block_sum128(ss2, red)), EPS_F);
    ((float4*)(out + (long)r * DM))[t] =
        make_float4(c.x * inv2, c.y * inv2, c.z * inv2, c.w * inv2);
}

// ---------------------------------------------------------------------------
// Host orchestration
// ---------------------------------------------------------------------------
extern "C" void kernel_launch(void* const* d_in, const int* in_sizes, int n_in,
                              void* d_out, int out_size)
{
    const float* dImg  = (const float*)d_in[0];
    const float* dTxt  = (const float*)d_in[1];
    const float* dMean = (const float*)d_in[2];
    const float* dDict = (const float*)d_in[3];
    float* outRecon = (float*)d_out;
    float* outTxt   = (float*)d_out + (long)BROWS * DM;

    float *Q, *U, *E, *P, *W, *Y, *G, *XA, *XB, *T;
    __nv_bfloat16 *Vh, *Vl, *Th, *Tl, *Dh, *Dl, *DTh, *DTl, *Eh, *El,
                  *Wh, *Wl, *Yh, *Yl;
    int* CNT;
    cudaGetSymbolAddress((void**)&Q,   g_Q);
    cudaGetSymbolAddress((void**)&U,   g_U);
    cudaGetSymbolAddress((void**)&Vh,  g_Vh);
    cudaGetSymbolAddress((void**)&Vl,  g_Vl);
    cudaGetSymbolAddress((void**)&Th,  g_Th);
    cudaGetSymbolAddress((void**)&Tl,  g_Tl);
    cudaGetSymbolAddress((void**)&Dh,  g_Dh);
    cudaGetSymbolAddress((void**)&Dl,  g_Dl);
    cudaGetSymbolAddress((void**)&DTh, g_DTh);
    cudaGetSymbolAddress((void**)&DTl, g_DTl);
    cudaGetSymbolAddress((void**)&E,   g_E);
    cudaGetSymbolAddress((void**)&Eh,  g_Eh);
    cudaGetSymbolAddress((void**)&El,  g_El);
    cudaGetSymbolAddress((void**)&P,   g_P);
    cudaGetSymbolAddress((void**)&W,   g_W);
    cudaGetSymbolAddress((void**)&Wh,  g_Wh);
    cudaGetSymbolAddress((void**)&Wl,  g_Wl);
    cudaGetSymbolAddress((void**)&Y,   g_Y);
    cudaGetSymbolAddress((void**)&Yh,  g_Yh);
    cudaGetSymbolAddress((void**)&Yl,  g_Yl);
    cudaGetSymbolAddress((void**)&G,   g_G);
    cudaGetSymbolAddress((void**)&XA,  g_XA);
    cudaGetSymbolAddress((void**)&XB,  g_XB);
    cudaGetSymbolAddress((void**)&T,   g_T);
    cudaGetSymbolAddress((void**)&CNT, g_cnt);

    cudaFuncSetAttribute(bmma_gemm<0, 3>, cudaFuncAttributeMaxDynamicSharedMemorySize, BSMEM);
    cudaFuncSetAttribute(bmma_gemm<1, 3>, cudaFuncAttributeMaxDynamicSharedMemorySize, BSMEM);
    cudaFuncSetAttribute(bmma_gemm<2, 3>, cudaFuncAttributeMaxDynamicSharedMemorySize, BSMEM);
    cudaFuncSetAttribute(bmma_gemm<3, 1>, cudaFuncAttributeMaxDynamicSharedMemorySize, BSMEM);
    cudaFuncSetAttribute(bmma_gemm<4, 1>, cudaFuncAttributeMaxDynamicSharedMemorySize, BSMEM);
    cudaFuncSetAttribute(bmma_gemm<5, 3>, cudaFuncAttributeMaxDynamicSharedMemorySize, BSMEM);
    cudaFuncSetAttribute(bmma_gemm<6, 3>, cudaFuncAttributeMaxDynamicSharedMemorySize, BSMEM);

    const int NT = (CDICT + BN - 1) / BN;   // 79 tiles over N=10000
    const int KSsetup = CDICT / 5;          // 2000 (SIMT setup split-K)
    const int KSmma   = CPAD / KSPLIT;      // 2560 (loop split-K, 4 slices)

    // 0) zero-pad-sensitive buffers + split-K semaphores
    cudaMemsetAsync(CNT, 0, sizeof(int) * 64, 0);
    cudaMemsetAsync(Q,   0, sizeof(float) * (size_t)BROWS * CPAD, 0);
    cudaMemsetAsync(DTh, 0, sizeof(__nv_bfloat16) * (size_t)DM * CPAD, 0);
    cudaMemsetAsync(DTl, 0, sizeof(__nv_bfloat16) * (size_t)DM * CPAD, 0);
    cudaMemsetAsync(Dh,  0, sizeof(__nv_bfloat16) * (size_t)CPAD * DM, 0);
    cudaMemsetAsync(Dl,  0, sizeof(__nv_bfloat16) * (size_t)CPAD * DM, 0);
    cudaMemsetAsync(E,   0, sizeof(float) * (size_t)DM * CPAD, 0);

    // 1) centered inputs + text output; splits of Y and D / D^T
    norm_center_kernel<<<BROWS, 128>>>(dImg, dMean, Y);
    norm_rows_kernel<<<BROWS, 128>>>(dTxt, outTxt);
    split_mat_bf16<<<(BROWS * DM / 2 + 255) / 256, 256>>>(
        (const float2*)Y, (__nv_bfloat162*)Yh, (__nv_bfloat162*)Yl, BROWS * DM / 2);
    split_mat_bf16<<<(int)(((long)CDICT * DM / 2 + 255) / 256), 256>>>(
        (const float2*)dDict, (__nv_bfloat162*)Dh, (__nv_bfloat162*)Dl,
        (long)CDICT * DM / 2);
    trans_split_kernel<<<dim3(16, 313), dim3(32, 8)>>>(
        dDict, DM, DTh, DTl, CPAD, DM, CDICT);

    // 2) Aty = Y @ D^T -> Q (bf16x3 tensor path; Q pads stay zero)
    bmma_gemm<0, 3><<<dim3(NT, 8, 1), 256, BSMEM>>>(
        Yh, Yl, DTh, DTl, Q, BROWS, CDICT, DM, DM, CPAD, CPAD,
        nullptr, nullptr, nullptr, nullptr, 0);

    // 3) G = D^T D + rho I (fp32 SIMT)
    gemm_kernel<true, false><<<dim3(4, 4, 5), 256>>>(
        dDict, dDict, P, DM, DM, KSsetup, DM, DM, DM);
    reduce_G<<<(DM * DM + 255) / 256, 256>>>(P, G, 5);

    // 4) Newton-Schulz inverse (fp32 SIMT)
    ninf_kernel<<<1, DM>>>(G);
    x0_kernel<<<(DM * DM + 255) / 256, 256>>>(XA);
    float* Xc = XA; float* Xn = XB;
    for (int t = 0; t < NS_ITERS; ++t) {
        gemm_kernel<false, false><<<dim3(4, 4, 4), 256>>>(
            G, Xc, P, DM, DM, DM / 4, DM, DM, DM);
        reduce_sum<<<(DM * DM / 4 + 255) / 256, 256>>>(
            (const float4*)P, (float4*)T, DM * DM / 4, 4);
        gemm_kernel<false, false><<<dim3(4, 4, 4), 256>>>(
            Xc, T, P, DM, DM, DM / 4, DM, DM, DM);
        reduce_ns<<<(DM * DM / 4 + 255) / 256, 256>>>(
            (const float4*)P, (const float4*)Xc, (float4*)Xn, DM * DM / 4, 4);
        float* tmp = Xc; Xc = Xn; Xn = tmp;
    }

    // 5) E = G^{-1} @ D^T (fp32 SIMT; ld = CPAD, pads zero) + bf16 split
    gemm_kernel<false, true><<<dim3(NT, 4, 1), 256>>>(
        Xc, dDict, E, DM, CDICT, DM, DM, DM, CPAD);
    split_mat_bf16<<<(int)(((long)DM * CPAD / 2 + 255) / 256), 256>>>(
        (const float2*)E, (__nv_bfloat162*)Eh, (__nv_bfloat162*)El,
        (long)DM * CPAD / 2);

    // 6) q = (Aty - (Aty @ D) @ E) / rho  (bf16x3 tensor path, in place on Q)
    split_mat_bf16<<<(int)(((long)BROWS * CPAD / 2 + 255) / 256), 256>>>(
        (const float2*)Q, (__nv_bfloat162*)Th, (__nv_bfloat162*)Tl,
        (long)BROWS * CPAD / 2);
    bmma_gemm<5, 3><<<dim3(4, 8, KSPLIT), 256, BSMEM>>>(
        Th, Tl, Dh, Dl, P, BROWS, DM, KSmma, CPAD, DM, DM,
        nullptr, nullptr, Wh, Wl, 0);
    bmma_gemm<1, 3><<<dim3(NT, 8, 1), 256, BSMEM>>>(
        Wh, Wl, Eh, El, Q, BROWS, CDICT, DM, DM, CPAD, CPAD,
        Q, nullptr, nullptr, nullptr, 0);

    // 7) ADMM loop: hybrid precision schedule (fused split-K reduce)
    cudaMemsetAsync(Vh, 0, sizeof(__nv_bfloat16) * (size_t)BROWS * CPAD, 0);
    cudaMemsetAsync(Vl, 0, sizeof(__nv_bfloat16) * (size_t)BROWS * CPAD, 0);
    cudaMemsetAsync(U,  0, sizeof(float) * (size_t)BROWS * CPAD, 0);
    for (int it = 0; it < ADMM_ITERS; ++it) {
        if (it < CHEAP_ITERS) {
            const int wl = (it == CHEAP_ITERS - 1) ? 1 : 0;
            bmma_gemm<4, 1><<<dim3(4, 8, KSPLIT), 256, BSMEM>>>(
                Vh, nullptr, Dh, nullptr, P, BROWS, DM, KSmma, CPAD, DM, DM,
                nullptr, nullptr, Wh, nullptr, 0);
            bmma_gemm<3, 1><<<dim3(NT, 8, 1), 256, BSMEM>>>(
                Wh, nullptr, Eh, nullptr, nullptr, BROWS, CDICT, DM, DM, CPAD, CPAD,
                Q, U, Vh, Vl, wl);
        } else {
            const int last = (it == ADMM_ITERS - 1) ? 1 : 0;
            bmma_gemm<5, 3><<<dim3(4, 8, KSPLIT), 256, BSMEM>>>(
                Vh, Vl, Dh, Dl, P, BROWS, DM, KSmma, CPAD, DM, DM,
                nullptr, nullptr, Wh, Wl, 0);
            bmma_gemm<2, 3><<<dim3(NT, 8, 1), 256, BSMEM>>>(
                Wh, Wl, Eh, El, nullptr, BROWS, CDICT, DM, DM, CPAD, CPAD,
                Q, U, Vh, Vl, last);
        }
    }

    // 8) recon = normalize(normalize(z @ D) + mean)   (z in Vh/Vl; accurate)
    bmma_gemm<6, 3><<<dim3(4, 8, KSPLIT), 256, BSMEM>>>(
        Vh, Vl, Dh, Dl, P, BROWS, DM, KSmma, CPAD, DM, DM,
        nullptr, W, nullptr, nullptr, 0);
    final_norm_kernel<<<BROWS, 128>>>(W, dMean, outRecon);
}

// round 12
// speedup vs baseline: 1.0923x; 1.0923x over previous
#include <cuda_runtime.h>
#include <cuda_bf16.h>
#include <math.h>
#include <stdint.h>

// ---------------------------------------------------------------------------
// Problem constants
// ---------------------------------------------------------------------------
#define BROWS 1024      // batch
#define CDICT 10000     // dictionary atoms
#define CPAD  10240     // padded dict dim: divisible by 128
#define DM    512       // embedding dim
#define RHO_F 5.0f
#define THR_F 0.002f    // lam / rho
#define EPS_F 1e-12f
#define ADMM_ITERS 100
#define CHEAP_ITERS 75  // 1-product bf16 iters; remainder 3-product polish
#define NS_ITERS 9
#define KSPLIT 4        // loop split-K: 128 CTAs <= 148 SMs (balanced, 1 wave)
#define GSLICES 25      // G split-K (Kslice=400, 400 CTAs)
#define NSPLIT 8        // NS split-K (Kslice=64, 128 CTAs)

// ---------------------------------------------------------------------------
// Scratch (static device globals -- no cudaMalloc allowed)
// ---------------------------------------------------------------------------
__device__ float          g_Q  [(size_t)BROWS * CPAD];  // Aty, then q (ld=CPAD)
__device__ float          g_U  [(size_t)BROWS * CPAD];  // u
__device__ __nv_bfloat16  g_Vh [(size_t)BROWS * CPAD];  // bf16-hi of v
__device__ __nv_bfloat16  g_Vl [(size_t)BROWS * CPAD];  // bf16-lo of v
__device__ __nv_bfloat16  g_Th [(size_t)BROWS * CPAD];  // Aty split hi (setup)
__device__ __nv_bfloat16  g_Tl [(size_t)BROWS * CPAD];  // Aty split lo (setup)
__device__ __nv_bfloat16  g_Dh [(size_t)CPAD * DM];     // dict hi [CPAD x 512]
__device__ __nv_bfloat16  g_Dl [(size_t)CPAD * DM];
__device__ __nv_bfloat16  g_DTh[(size_t)DM * CPAD];     // D^T hi [512 x CPAD]
__device__ __nv_bfloat16  g_DTl[(size_t)DM * CPAD];
__device__ float          g_E  [(size_t)DM * CPAD];     // E = G^{-1} D^T (fp32)
__device__ __nv_bfloat16  g_Eh [(size_t)DM * CPAD];
__device__ __nv_bfloat16  g_El [(size_t)DM * CPAD];
__device__ float          g_P  [(size_t)GSLICES * DM * DM]; // split-K partials (max user)
__device__ float          g_W  [(size_t)BROWS * DM];
__device__ __nv_bfloat16  g_Wh [(size_t)BROWS * DM];
__device__ __nv_bfloat16  g_Wl [(size_t)BROWS * DM];
__device__ float          g_Y  [(size_t)BROWS * DM];
__device__ __nv_bfloat16  g_Yh [(size_t)BROWS * DM];
__device__ __nv_bfloat16  g_Yl [(size_t)BROWS * DM];
__device__ float g_G [DM * DM];
__device__ float g_XA[DM * DM];
__device__ float g_XB[DM * DM];
__device__ float g_T [DM * DM];
__device__ float g_ninf;
__device__ int   g_cnt[64];              // split-K tile semaphores (32 used, epoch-monotone)

// ---------------------------------------------------------------------------
// helpers
// ---------------------------------------------------------------------------
__device__ __forceinline__ void split_bf16(float v, __nv_bfloat16& h, __nv_bfloat16& l)
{
    h = __float2bfloat16_rn(v);
    l = __float2bfloat16_rn(v - __bfloat162float(h));
}

__device__ __forceinline__ void mma16(float* c, const unsigned* a,
                                      unsigned b0, unsigned b1)
{
    asm volatile(
        "mma.sync.aligned.m16n8k16.row.col.f32.bf16.bf16.f32 "
        "{%0,%1,%2,%3}, {%4,%5,%6,%7}, {%8,%9}, {%0,%1,%2,%3};"
        : "+f"(c[0]), "+f"(c[1]), "+f"(c[2]), "+f"(c[3])
        : "r"(a[0]), "r"(a[1]), "r"(a[2]), "r"(a[3]), "r"(b0), "r"(b1));
}

__device__ __forceinline__ void ldsm4(unsigned* r, uint32_t a)
{
    asm volatile("ldmatrix.sync.aligned.m8n8.x4.shared.b16 {%0,%1,%2,%3}, [%4];"
                 : "=r"(r[0]), "=r"(r[1]), "=r"(r[2]), "=r"(r[3]) : "r"(a));
}

__device__ __forceinline__ void ldsm4t(unsigned* r, uint32_t a)
{
    asm volatile("ldmatrix.sync.aligned.m8n8.x4.trans.shared.b16 {%0,%1,%2,%3}, [%4];"
                 : "=r"(r[0]), "=r"(r[1]), "=r"(r[2]), "=r"(r[3]) : "r"(a));
}

__device__ __forceinline__ void cp16(uint32_t s, const void* g)
{
    asm volatile("cp.async.cg.shared.global [%0], [%1], 16;"
                 :: "r"(s), "l"(g) : "memory");
}

// ---------------------------------------------------------------------------
// bf16 MMA GEMM, templated on product count and epilogue:
//   PROD==3: acc = Ah*Bh + Ah*Bl + Al*Bh       PROD==1: acc = Ah*Bh
// EPI 0: plain partial store at C + z*M*ldc (split-K, external reduce)
// EPI 1: q = (Qp - acc)/rho -> C (fp32)                      [setup]
// EPI 2: full ADMM: v=Vh+Vl, fp32 Q; writes U, Vh, Vl        [polish]
// EPI 3: cheap ADMM: v=Vh, fp32 Q; writes U, Vh; Vl iff flag [cheap]
// EPI 4: split-K + DISTRIBUTED fused reduce -> Vh (bf16 hi)
// EPI 5: split-K + DISTRIBUTED fused reduce -> Vh, Vl (bf16 hi/lo)
// EPI 6: split-K + DISTRIBUTED fused reduce -> Up (fp32)
// EPI>=4: flag = launch epoch. Each CTA arrives on its tile counter, spins
// until count == (epoch+1)*S (counters memset once per kernel_launch, never
// reset mid-graph -> no reset race; 128 CTAs = 1 wave -> no deadlock), then
// CTA z reduces its own 128/S-row band summing slices 0..S-1 in fixed order
// (bit-identical to the standalone reduce kernels it replaces).
// BM=BN=128, BK=32, 256 thr, 8 warps (32x64 warp tile), 2-stage cp.async,
// ldmatrix fragments (conflict-free strides 40 / 136 bf16).
// ---------------------------------------------------------------------------
#define BSTG  37888
#define BSMEM (2 * BSTG)

template<int EPI, int PROD>
__global__ void __launch_bounds__(256, 2)
bmma_gemm(const __nv_bfloat16* __restrict__ Ah, const __nv_bfloat16* __restrict__ Al,
          const __nv_bfloat16* __restrict__ Bh, const __nv_bfloat16* __restrict__ Bl,
          float* __restrict__ C, int M, int N, int Kslice,
          int lda, int ldb, int ldc,
          const float* __restrict__ Qp, float* __restrict__ Up,
          __nv_bfloat16* __restrict__ Vh, __nv_bfloat16* __restrict__ Vl,
          int flag)
{
    extern __shared__ char smd[];
    const int tid  = threadIdx.x;
    const int lane = tid & 31, wid = tid >> 5;
    const int wm = (wid & 3) * 32;
    const int wn = (wid >> 2) * 64;
    const int m0 = blockIdx.y * 128, n0 = blockIdx.x * 128;
    const long k0 = (long)blockIdx.z * Kslice;
    const int nk = Kslice >> 5;

    const int aRow = wm + ((lane >> 3) & 1) * 8 + (lane & 7);
    const int aKof = (lane >> 4) * 8;
    const int bRow = ((lane >> 3) & 1) * 8 + (lane & 7);
    const int bNof = (lane >> 4) * 8;

    float c[2][8][4];
#pragma unroll
    for (int i = 0; i < 2; ++i)
#pragma unroll
        for (int j = 0; j < 8; ++j)
#pragma unroll
            for (int q = 0; q < 4; ++q) c[i][j][q] = 0.0f;

    auto load_tile = [&](int kt, int buf) {
        char* base = smd + buf * BSTG;
        const int kb = kt * 32;
#pragma unroll
        for (int cc = 0; cc < 2; ++cc) {        // A: 128 rows x 4 chunks (8 bf16)
            int ch  = tid * 2 + cc;
            int row = ch >> 2, kc = (ch & 3) * 8;
            uint32_t so = (uint32_t)__cvta_generic_to_shared(
                base + (row * 40 + kc) * 2);
            const long go = (long)(m0 + row) * lda + k0 + kb + kc;
            cp16(so, Ah + go);
            if (PROD == 3) cp16(so + 10240, Al + go);
        }
#pragma unroll
        for (int cc = 0; cc < 2; ++cc) {        // B: 32 rows x 16 chunks
            int ch  = tid * 2 + cc;
            int row = ch >> 4, nc = (ch & 15) * 8;
            uint32_t so = (uint32_t)__cvta_generic_to_shared(
                base + 20480 + (row * 136 + nc) * 2);
            const long go = (long)(k0 + kb + row) * ldb + n0 + nc;
            cp16(so, Bh + go);
            if (PROD == 3) cp16(so + 8704, Bl + go);
        }
    };

    load_tile(0, 0);
    asm volatile("cp.async.commit_group;" ::: "memory");

    for (int kt = 0; kt < nk; ++kt) {
        asm volatile("cp.async.wait_group 0;" ::: "memory");
        __syncthreads();
        if (kt + 1 < nk) load_tile(kt + 1, (kt + 1) & 1);
        asm volatile("cp.async.commit_group;" ::: "memory");

        const uint32_t sb = (uint32_t)__cvta_generic_to_shared(smd + (kt & 1) * BSTG);

#pragma unroll
        for (int ks = 0; ks < 2; ++ks) {
            unsigned ah[2][4], al[2][4];
#pragma unroll
            for (int i = 0; i < 2; ++i) {
                uint32_t ad = sb + ((aRow + i * 16) * 40 + ks * 16 + aKof) * 2;
                ldsm4(ah[i], ad);
                if (PROD == 3) ldsm4(al[i], ad + 10240);
            }
#pragma unroll
            for (int ng = 0; ng < 4; ++ng) {
                unsigned bh[4], bl[4];
                uint32_t bd = sb + 20480 +
                              ((bRow + ks * 16) * 136 + wn + ng * 16 + bNof) * 2;
                ldsm4t(bh, bd);
                if (PROD == 3) ldsm4t(bl, bd + 8704);
#pragma unroll
                for (int jj = 0; jj < 2; ++jj) {
                    const int j = ng * 2 + jj;
#pragma unroll
                    for (int i = 0; i < 2; ++i) {
                        mma16(c[i][j], ah[i], bh[jj * 2], bh[jj * 2 + 1]);
                        if (PROD == 3) {
                            mma16(c[i][j], ah[i], bl[jj * 2], bl[jj * 2 + 1]);
                            mma16(c[i][j], al[i], bh[jj * 2], bh[jj * 2 + 1]);
                        }
                    }
                }
            }
        }
    }

    // ---- epilogue ----
    const int gq = lane >> 2, tq = lane & 3;
#pragma unroll
    for (int i = 0; i < 2; ++i) {
        const int r0 = m0 + wm + i * 16 + gq;
#pragma unroll
        for (int j = 0; j < 8; ++j) {
            const int ccn = n0 + wn + j * 8 + 2 * tq;
            if (ccn >= N) continue;
            if (EPI == 0 || EPI >= 4) {
                float* Cz = C + (long)blockIdx.z * (long)M * ldc;
                *(float2*)&Cz[(long)r0 * ldc + ccn] =
                    make_float2(c[i][j][0], c[i][j][1]);
                *(float2*)&Cz[(long)(r0 + 8) * ldc + ccn] =
                    make_float2(c[i][j][2], c[i][j][3]);
            } else if (EPI == 1) {
#pragma unroll
                for (int rr = 0; rr < 2; ++rr) {
                    const long idx = (long)(r0 + rr * 8) * ldc + ccn;
                    const float ir = 1.0f / RHO_F;
                    float2 qv = *(const float2*)&Qp[idx];
                    *(float2*)&C[idx] = make_float2(
                        (qv.x - c[i][j][rr * 2 + 0]) * ir,
                        (qv.y - c[i][j][rr * 2 + 1]) * ir);
                }
            } else if (EPI == 2) {
#pragma unroll
                for (int rr = 0; rr < 2; ++rr) {
                    const long idx = (long)(r0 + rr * 8) * ldc + ccn;
                    float a0 = c[i][j][rr * 2 + 0], a1 = c[i][j][rr * 2 + 1];
                    float2 qv = *(const float2*)&Qp[idx];
                    float2 uv = *(const float2*)&Up[idx];
                    __nv_bfloat162 vh2 = *(const __nv_bfloat162*)&Vh[idx];
                    __nv_bfloat162 vl2 = *(const __nv_bfloat162*)&Vl[idx];
                    float2 un;
                    __nv_bfloat162 nh, nl;
                    {
                        float v = __bfloat162float(vh2.x) + __bfloat162float(vl2.x);
                        float x = qv.x + v - a0;
                        float z = fmaxf(x + uv.x - THR_F, 0.f);
                        un.x = uv.x + x - z;
                        float vn = flag ? z : (2.f * z - uv.x - x);
                        split_bf16(vn, nh.x, nl.x);
                    }
                    {
                        float v = __bfloat162float(vh2.y) + __bfloat162float(vl2.y);
                        float x = qv.y + v - a1;
                        float z = fmaxf(x + uv.y - THR_F, 0.f);
                        un.y = uv.y + x - z;
                        float vn = flag ? z : (2.f * z - uv.y - x);
                        split_bf16(vn, nh.y, nl.y);
                    }
                    *(float2*)&Up[idx] = un;
                    *(__nv_bfloat162*)&Vh[idx] = nh;
                    *(__nv_bfloat162*)&Vl[idx] = nl;
                }
            } else if (EPI == 3) { // cheap ADMM (v = Vh only, fp32 q; Vl iff flag)
#pragma unroll
                for (int rr = 0; rr < 2; ++rr) {
                    const long idx = (long)(r0 + rr * 8) * ldc + ccn;
                    float a0 = c[i][j][rr * 2 + 0], a1 = c[i][j][rr * 2 + 1];
                    float2 qv = *(const float2*)&Qp[idx];
                    float2 uv = *(const float2*)&Up[idx];
                    __nv_bfloat162 vh2 = *(const __nv_bfloat162*)&Vh[idx];
                    float2 un;
                    __nv_bfloat162 nh, nl;
                    {
                        float x = qv.x + __bfloat162float(vh2.x) - a0;
                        float z = fmaxf(x + uv.x - THR_F, 0.f);
                        un.x = uv.x + x - z;
                        float vn = 2.f * z - uv.x - x;
                        split_bf16(vn, nh.x, nl.x);
                    }
                    {
                        float x = qv.y + __bfloat162float(vh2.y) - a1;
                        float z = fmaxf(x + uv.y - THR_F, 0.f);
                        un.y = uv.y + x - z;
                        float vn = 2.f * z - uv.y - x;
                        split_bf16(vn, nh.y, nl.y);
                    }
                    *(float2*)&Up[idx] = un;
                    *(__nv_bfloat162*)&Vh[idx] = nh;
                    if (flag) *(__nv_bfloat162*)&Vl[idx] = nl;
                }
            }
        }
    }

    // ---- distributed fused split-K reduce (EPI 4/5/6) ----
    if (EPI >= 4) {
        const int tile = blockIdx.y * gridDim.x + blockIdx.x;
        const int S = (int)gridDim.z;
        __threadfence();                 // make this CTA's partial stores visible
        __syncthreads();
        if (tid == 0) {
            atomicAdd(&g_cnt[tile], 1);
            const int target = (flag + 1) * S;
            while (atomicAdd(&g_cnt[tile], 0) < target) { }
            __threadfence();
        }
        __syncthreads();
        // CTA z reduces rows [m0 + z*band, +band), fixed slice order 0..S-1
        const int band = 128 / S;        // 32 for S=4
        const int rb = blockIdx.z * band;
        for (int e = tid; e < band * 64; e += 256) {
            const int r   = rb + (e >> 6);
            const int c2  = e & 63;
            const long base = (long)(m0 + r) * ldc + n0 + c2 * 2;
            float2 s = *(const float2*)&C[base];
            for (int zz = 1; zz < S; ++zz) {
                float2 t = *(const float2*)&C[(long)zz * M * ldc + base];
                s.x += t.x; s.y += t.y;
            }
            if (EPI == 6) {
                *(float2*)&Up[base] = s;
            } else {
                __nv_bfloat162 h, l;
                split_bf16(s.x, h.x, l.x);
                split_bf16(s.y, h.y, l.y);
                *(__nv_bfloat162*)&Vh[base] = h;
                if (EPI == 5) *(__nv_bfloat162*)&Vl[base] = l;
            }
        }
    }
}

// ---------------------------------------------------------------------------
// SIMT tiled SGEMM (setup path: G, NS, E -- full fp32 accuracy)
// ---------------------------------------------------------------------------
#define BM 128
#define BN 128
#define BKK 16

template<bool TA, bool TB>
__global__ void __launch_bounds__(256, 2)
gemm_kernel(const float* __restrict__ A, const float* __restrict__ B,
            float* __restrict__ C,
            int M, int N, int Kslice, int lda, int ldb, int ldc)
{
    __shared__ float As[BKK][BM + 4];
    __shared__ float Bs[BKK][BN + 4];

    const int tid = threadIdx.x;
    const int tx  = tid & 15;
    const int ty  = tid >> 4;
    const int m0  = blockIdx.y * BM;
    const int n0  = blockIdx.x * BN;

    const long k0 = (long)blockIdx.z * Kslice;
    if (TA) A += k0 * lda; else A += k0;
    if (TB) B += k0;       else B += k0 * ldb;
    C += (long)blockIdx.z * (long)M * ldc;

    float acc[8][8];
#pragma unroll
    for (int i = 0; i < 8; ++i)
#pragma unroll
        for (int j = 0; j < 8; ++j) acc[i][j] = 0.0f;

    const int nk = Kslice / BKK;
#pragma unroll 1
    for (int kt = 0; kt < nk; ++kt) {
        const int kbase = kt * BKK;
        if (!TA) {
#pragma unroll
            for (int p = 0; p < 2; ++p) {
                const int row = p * 64 + (tid >> 2);
                const int c4  = (tid & 3) * 4;
                float4 v = *(const float4*)&A[(long)(m0 + row) * lda + kbase + c4];
                As[c4 + 0][row] = v.x; As[c4 + 1][row] = v.y;
                As[c4 + 2][row] = v.z; As[c4 + 3][row] = v.w;
            }
        } else {
#pragma unroll
            for (int p = 0; p < 2; ++p) {
                const int kr = p * 8 + (tid >> 5);
                const int m4 = (tid & 31) * 4;
                float4 v = *(const float4*)&A[(long)(kbase + kr) * lda + m0 + m4];
                *(float4*)&As[kr][m4] = v;
            }
        }
        if (!TB) {
#pragma unroll
            for (int p = 0; p < 2; ++p) {
                const int kr  = p * 8 + (tid >> 5);
                const int nn4 = (tid & 31) * 4;
                const int gn  = n0 + nn4;
                float4 v = make_float4(0.f, 0.f, 0.f, 0.f);
                if (gn < N) v = *(const float4*)&B[(long)(kbase + kr) * ldb + gn];
                *(float4*)&Bs[kr][nn4] = v;
            }
        } else {
#pragma unroll
            for (int p = 0; p < 2; ++p) {
                const int nrow = p * 64 + (tid >> 2);
                const int c4   = (tid & 3) * 4;
                const int gn   = n0 + nrow;
                float4 v = make_float4(0.f, 0.f, 0.f, 0.f);
                if (gn < N) v = *(const float4*)&B[(long)gn * ldb + kbase + c4];
                Bs[c4 + 0][nrow] = v.x; Bs[c4 + 1][nrow] = v.y;
                Bs[c4 + 2][nrow] = v.z; Bs[c4 + 3][nrow] = v.w;
            }
        }
        __syncthreads();
#pragma unroll
        for (int kk = 0; kk < BKK; ++kk) {
            float a[8], b[8];
            *(float4*)&a[0] = *(const float4*)&As[kk][ty * 4];
            *(float4*)&a[4] = *(const float4*)&As[kk][64 + ty * 4];
            *(float4*)&b[0] = *(const float4*)&Bs[kk][tx * 4];
            *(float4*)&b[4] = *(const float4*)&Bs[kk][64 + tx * 4];
#pragma unroll
            for (int i = 0; i < 8; ++i)
#pragma unroll
                for (int j = 0; j < 8; ++j)
                    acc[i][j] = fmaf(a[i], b[j], acc[i][j]);
        }
        __syncthreads();
    }

    int rows[8];
#pragma unroll
    for (int i = 0; i < 8; ++i)
        rows[i] = m0 + (i < 4 ? ty * 4 + i : 64 + ty * 4 + (i - 4));

#pragma unroll
    for (int i = 0; i < 8; ++i) {
#pragma unroll
        for (int jg = 0; jg < 2; ++jg) {
            const int cn = n0 + jg * 64 + tx * 4;
            if (cn >= N) continue;
            const long idx = (long)rows[i] * ldc + cn;
            *(float4*)&C[idx] = make_float4(acc[i][jg * 4 + 0], acc[i][jg * 4 + 1],
                                            acc[i][jg * 4 + 2], acc[i][jg * 4 + 3]);
        }
    }
}

// ---------------------------------------------------------------------------
// Transpose + bf16 split: out[i*ldo + j] = split(src[j*lds + i]), i<R, j<C
// ---------------------------------------------------------------------------
__global__ void trans_split_kernel(const float* __restrict__ src, int lds,
                                   __nv_bfloat16* __restrict__ dh,
                                   __nv_bfloat16* __restrict__ dl,
                                   int ldo, int R, int C)
{
    __shared__ float t[32][33];
    const int i0 = blockIdx.x * 32;
    const int j0 = blockIdx.y * 32;
    const int tx = threadIdx.x, ty = threadIdx.y;
    for (int jj = ty; jj < 32; jj += 8) {
        const int j = j0 + jj, i = i0 + tx;
        float v = 0.f;
        if (j < C && i < R) v = src[(long)j * lds + i];
        t[jj][tx] = v;
    }
    __syncthreads();
    for (int ii = ty; ii < 32; ii += 8) {
        const int i = i0 + ii, j = j0 + tx;
        if (i < R && j < C) {
            __nv_bfloat16 h, l;
            split_bf16(t[tx][ii], h, l);
            dh[(long)i * ldo + j] = h;
            dl[(long)i * ldo + j] = l;
        }
    }
}

// ---------------------------------------------------------------------------
// Reductions / splits (setup-only)
// ---------------------------------------------------------------------------
__global__ void reduce_sum(const float4* __restrict__ P, float4* __restrict__ out,
                           int n4, int S)
{
    int i = blockIdx.x * blockDim.x + threadIdx.x;
    if (i >= n4) return;
    float4 s = P[i];
    for (int k = 1; k < S; ++k) {
        float4 t = P[(long)k * n4 + i];
        s.x += t.x; s.y += t.y; s.z += t.z; s.w += t.w;
    }
    out[i] = s;
}

__global__ void split_mat_bf16(const float2* __restrict__ src,
                               __nv_bfloat162* __restrict__ hi,
                               __nv_bfloat162* __restrict__ lo, long n2)
{
    long i = (long)blockIdx.x * blockDim.x + threadIdx.x;
    if (i >= n2) return;
    float2 v = src[i];
    __nv_bfloat162 h, l;
    split_bf16(v.x, h.x, l.x);
    split_bf16(v.y, h.y, l.y);
    hi[i] = h; lo[i] = l;
}

__global__ void reduce_G(const float* __restrict__ P, float* __restrict__ G, int S)
{
    int i = blockIdx.x * blockDim.x + threadIdx.x;
    if (i >= DM * DM) return;
    float s = 0.f;
    for (int k = 0; k < S; ++k) s += P[(long)k * DM * DM + i];
    if ((i / DM) == (i % DM)) s += RHO_F;
    G[i] = s;
}

__global__ void reduce_ns(const float4* __restrict__ P, const float4* __restrict__ Xc,
                          float4* __restrict__ Xn, int n4, int S)
{
    int i = blockIdx.x * blockDim.x + threadIdx.x;
    if (i >= n4) return;
    float4 s = P[i];
    for (int k = 1; k < S; ++k) {
        float4 t = P[(long)k * n4 + i];
        s.x += t.x; s.y += t.y; s.z += t.z; s.w += t.w;
    }
    float4 x = Xc[i];
    Xn[i] = make_float4(2.f * x.x - s.x, 2.f * x.y - s.y,
                        2.f * x.z - s.z, 2.f * x.w - s.w);
}

__global__ void ninf_kernel(const float* __restrict__ G)
{
    __shared__ float sm[DM];
    const int i = threadIdx.x;
    float s = 0.f;
    for (int j = 0; j < DM; ++j) s += fabsf(G[(long)j * DM + i]);
    sm[i] = s;
    __syncthreads();
    for (int o = DM / 2; o > 0; o >>= 1) {
        if (i < o) sm[i] = fmaxf(sm[i], sm[i + o]);
        __syncthreads();
    }
    if (i == 0) g_ninf = sm[0];
}

__global__ void x0_kernel(float* __restrict__ X)
{
    int i = blockIdx.x * blockDim.x + threadIdx.x;
    if (i >= DM * DM) return;
    float c = 2.0f / (RHO_F + g_ninf);
    X[i] = ((i / DM) == (i % DM)) ? c : 0.0f;
}

// ---------------------------------------------------------------------------
// Row-normalize kernels
// ---------------------------------------------------------------------------
__device__ __forceinline__ float block_sum128(float v, float* red)
{
    for (int o = 16; o > 0; o >>= 1) v += __shfl_xor_sync(0xffffffff, v, o);
    if ((threadIdx.x & 31) == 0) red[threadIdx.x >> 5] = v;
    __syncthreads();
    float tot = red[0] + red[1] + red[2] + red[3];
    __syncthreads();
    return tot;
}

__global__ void norm_center_kernel(const float* __restrict__ img,
                                   const float* __restrict__ mean,
                                   float* __restrict__ out)
{
    __shared__ float red[4];
    const int r = blockIdx.x, t = threadIdx.x;
    float4 v = ((const float4*)(img + (long)r * DM))[t];
    float ss = v.x * v.x + v.y * v.y + v.z * v.z + v.w * v.w;
    float inv = 1.0f / fmaxf(sqrtf(block_sum128(ss, red)), EPS_F);
    float4 mv = ((const float4*)mean)[t];
    float4 c = make_float4(v.x * inv - mv.x, v.y * inv - mv.y,
                           v.z * inv - mv.z, v.w * inv - mv.w);
    float ss2 = c.x * c.x + c.y * c.y + c.z * c.z + c.w * c.w;
    float inv2 = 1.0f / fmaxf(sqrtf(block_sum128(ss2, red)), EPS_F);
    ((float4*)(out + (long)r * DM))[t] =
        make_float4(c.x * inv2, c.y * inv2, c.z * inv2, c.w * inv2);
}

__global__ void norm_rows_kernel(const float* __restrict__ in, float* __restrict__ out)
{
    __shared__ float red[4];
    const int r = blockIdx.x, t = threadIdx.x;
    float4 v = ((const float4*)(in + (long)r * DM))[t];
    float ss = v.x * v.x + v.y * v.y + v.z * v.z + v.w * v.w;
    float inv = 1.0f / fmaxf(sqrtf(block_sum128(ss, red)), EPS_F);
    ((float4*)(out + (long)r * DM))[t] =
        make_float4(v.x * inv, v.y * inv, v.z * inv, v.w * inv);
}

__global__ void final_norm_kernel(const float* __restrict__ rec,
                                  const float* __restrict__ mean,
                                  float* __restrict__ out)
{
    __shared__ float red[4];
    const int r = blockIdx.x, t = threadIdx.x;
    float4 v = ((const float4*)(rec + (long)r * DM))[t];
    float ss = v.x * v.x + v.y * v.y + v.z * v.z + v.w * v.w;
    float inv = 1.0f / fmaxf(sqrtf(block_sum128(ss, red)), EPS_F);
    float4 mv = ((const float4*)mean)[t];
    float4 c = make_float4(v.x * inv + mv.x, v.y * inv + mv.y,
                           v.z * inv + mv.z, v.w * inv + mv.w);
    float ss2 = c.x * c.x + c.y * c.y + c.z * c.z + c.w * c.w;
    float inv2 = 1.0f / fmaxf(sqrtf(block_sum128(ss2, red)), EPS_F);
    ((float4*)(out + (long)r * DM))[t] =
        make_float4(c.x * inv2, c.y * inv2, c.z * inv2, c.w * inv2);
}

// ---------------------------------------------------------------------------
// Host orchestration
// ---------------------------------------------------------------------------
extern "C" void kernel_launch(void* const* d_in, const int* in_sizes, int n_in,
                              void* d_out, int out_size)
{
    const float* dImg  = (const float*)d_in[0];
    const float* dTxt  = (const float*)d_in[1];
    const float* dMean = (const float*)d_in[2];
    const float* dDict = (const float*)d_in[3];
    float* outRecon = (float*)d_out;
    float* outTxt   = (float*)d_out + (long)BROWS * DM;

    float *Q, *U, *E, *P, *W, *Y, *G, *XA, *XB, *T;
    __nv_bfloat16 *Vh, *Vl, *Th, *Tl, *Dh, *Dl, *DTh, *DTl, *Eh, *El,
                  *Wh, *Wl, *Yh, *Yl;
    int* CNT;
    cudaGetSymbolAddress((void**)&Q,   g_Q);
    cudaGetSymbolAddress((void**)&U,   g_U);
    cudaGetSymbolAddress((void**)&Vh,  g_Vh);
    cudaGetSymbolAddress((void**)&Vl,  g_Vl);
    cudaGetSymbolAddress((void**)&Th,  g_Th);
    cudaGetSymbolAddress((void**)&Tl,  g_Tl);
    cudaGetSymbolAddress((void**)&Dh,  g_Dh);
    cudaGetSymbolAddress((void**)&Dl,  g_Dl);
    cudaGetSymbolAddress((void**)&DTh, g_DTh);
    cudaGetSymbolAddress((void**)&DTl, g_DTl);
    cudaGetSymbolAddress((void**)&E,   g_E);
    cudaGetSymbolAddress((void**)&Eh,  g_Eh);
    cudaGetSymbolAddress((void**)&El,  g_El);
    cudaGetSymbolAddress((void**)&P,   g_P);
    cudaGetSymbolAddress((void**)&W,   g_W);
    cudaGetSymbolAddress((void**)&Wh,  g_Wh);
    cudaGetSymbolAddress((void**)&Wl,  g_Wl);
    cudaGetSymbolAddress((void**)&Y,   g_Y);
    cudaGetSymbolAddress((void**)&Yh,  g_Yh);
    cudaGetSymbolAddress((void**)&Yl,  g_Yl);
    cudaGetSymbolAddress((void**)&G,   g_G);
    cudaGetSymbolAddress((void**)&XA,  g_XA);
    cudaGetSymbolAddress((void**)&XB,  g_XB);
    cudaGetSymbolAddress((void**)&T,   g_T);
    cudaGetSymbolAddress((void**)&CNT, g_cnt);

    cudaFuncSetAttribute(bmma_gemm<0, 3>, cudaFuncAttributeMaxDynamicSharedMemorySize, BSMEM);
    cudaFuncSetAttribute(bmma_gemm<1, 3>, cudaFuncAttributeMaxDynamicSharedMemorySize, BSMEM);
    cudaFuncSetAttribute(bmma_gemm<2, 3>, cudaFuncAttributeMaxDynamicSharedMemorySize, BSMEM);
    cudaFuncSetAttribute(bmma_gemm<3, 1>, cudaFuncAttributeMaxDynamicSharedMemorySize, BSMEM);
    cudaFuncSetAttribute(bmma_gemm<4, 1>, cudaFuncAttributeMaxDynamicSharedMemorySize, BSMEM);
    cudaFuncSetAttribute(bmma_gemm<5, 3>, cudaFuncAttributeMaxDynamicSharedMemorySize, BSMEM);
    cudaFuncSetAttribute(bmma_gemm<6, 3>, cudaFuncAttributeMaxDynamicSharedMemorySize, BSMEM);

    const int NT = (CDICT + BN - 1) / BN;   // 79 tiles over N=10000
    const int KSG = CDICT / GSLICES;        // 400 (G split-K, 25 slices)
    const int KSmma = CPAD / KSPLIT;        // 2560 (loop split-K, 4 slices)

    // 0) zero-pad-sensitive buffers + split-K semaphores (epoch counters)
    cudaMemsetAsync(CNT, 0, sizeof(int) * 64, 0);
    cudaMemsetAsync(Q,   0, sizeof(float) * (size_t)BROWS * CPAD, 0);
    cudaMemsetAsync(DTh, 0, sizeof(__nv_bfloat16) * (size_t)DM * CPAD, 0);
    cudaMemsetAsync(DTl, 0, sizeof(__nv_bfloat16) * (size_t)DM * CPAD, 0);
    cudaMemsetAsync(Dh,  0, sizeof(__nv_bfloat16) * (size_t)CPAD * DM, 0);
    cudaMemsetAsync(Dl,  0, sizeof(__nv_bfloat16) * (size_t)CPAD * DM, 0);
    cudaMemsetAsync(E,   0, sizeof(float) * (size_t)DM * CPAD, 0);

    // 1) centered inputs + text output; splits of Y and D / D^T
    norm_center_kernel<<<BROWS, 128>>>(dImg, dMean, Y);
    norm_rows_kernel<<<BROWS, 128>>>(dTxt, outTxt);
    split_mat_bf16<<<(BROWS * DM / 2 + 255) / 256, 256>>>(
        (const float2*)Y, (__nv_bfloat162*)Yh, (__nv_bfloat162*)Yl, BROWS * DM / 2);
    split_mat_bf16<<<(int)(((long)CDICT * DM / 2 + 255) / 256), 256>>>(
        (const float2*)dDict, (__nv_bfloat162*)Dh, (__nv_bfloat162*)Dl,
        (long)CDICT * DM / 2);
    trans_split_kernel<<<dim3(16, 313), dim3(32, 8)>>>(
        dDict, DM, DTh, DTl, CPAD, DM, CDICT);

    // 2) Aty = Y @ D^T -> Q (bf16x3 tensor path; Q pads stay zero)
    bmma_gemm<0, 3><<<dim3(NT, 8, 1), 256, BSMEM>>>(
        Yh, Yl, DTh, DTl, Q, BROWS, CDICT, DM, DM, CPAD, CPAD,
        nullptr, nullptr, nullptr, nullptr, 0);

    // 3) G = D^T D + rho I (fp32 SIMT, 25-way split-K -> 400 CTAs)
    gemm_kernel<true, false><<<dim3(4, 4, GSLICES), 256>>>(
        dDict, dDict, P, DM, DM, KSG, DM, DM, DM);
    reduce_G<<<(DM * DM + 255) / 256, 256>>>(P, G, GSLICES);

    // 4) Newton-Schulz inverse (fp32 SIMT, 8-way split-K -> 128 CTAs)
    ninf_kernel<<<1, DM>>>(G);
    x0_kernel<<<(DM * DM + 255) / 256, 256>>>(XA);
    float* Xc = XA; float* Xn = XB;
    for (int t = 0; t < NS_ITERS; ++t) {
        gemm_kernel<false, false><<<dim3(4, 4, NSPLIT), 256>>>(
            G, Xc, P, DM, DM, DM / NSPLIT, DM, DM, DM);
        reduce_sum<<<(DM * DM / 4 + 255) / 256, 256>>>(
            (const float4*)P, (float4*)T, DM * DM / 4, NSPLIT);
        gemm_kernel<false, false><<<dim3(4, 4, NSPLIT), 256>>>(
            Xc, T, P, DM, DM, DM / NSPLIT, DM, DM, DM);
        reduce_ns<<<(DM * DM / 4 + 255) / 256, 256>>>(
            (const float4*)P, (const float4*)Xc, (float4*)Xn, DM * DM / 4, NSPLIT);
        float* tmp = Xc; Xc = Xn; Xn = tmp;
    }

    // 5) E = G^{-1} @ D^T (fp32 SIMT; ld = CPAD, pads zero) + bf16 split
    gemm_kernel<false, true><<<dim3(NT, 4, 1), 256>>>(
        Xc, dDict, E, DM, CDICT, DM, DM, DM, CPAD);
    split_mat_bf16<<<(int)(((long)DM * CPAD / 2 + 255) / 256), 256>>>(
        (const float2*)E, (__nv_bfloat162*)Eh, (__nv_bfloat162*)El,
        (long)DM * CPAD / 2);

    // 6) q = (Aty - (Aty @ D) @ E) / rho  (bf16x3 tensor path, in place on Q)
    split_mat_bf16<<<(int)(((long)BROWS * CPAD / 2 + 255) / 256), 256>>>(
        (const float2*)Q, (__nv_bfloat162*)Th, (__nv_bfloat162*)Tl,
        (long)BROWS * CPAD / 2);
    bmma_gemm<5, 3><<<dim3(4, 8, KSPLIT), 256, BSMEM>>>(
        Th, Tl, Dh, Dl, P, BROWS, DM, KSmma, CPAD, DM, DM,
        nullptr, nullptr, Wh, Wl, /*epoch=*/0);
    bmma_gemm<1, 3><<<dim3(NT, 8, 1), 256, BSMEM>>>(
        Wh, Wl, Eh, El, Q, BROWS, CDICT, DM, DM, CPAD, CPAD,
        Q, nullptr, nullptr, nullptr, 0);

    // 7) ADMM loop: hybrid precision schedule (distributed fused split-K reduce)
    cudaMemsetAsync(Vh, 0, sizeof(__nv_bfloat16) * (size_t)BROWS * CPAD, 0);
    cudaMemsetAsync(Vl, 0, sizeof(__nv_bfloat16) * (size_t)BROWS * CPAD, 0);
    cudaMemsetAsync(U,  0, sizeof(float) * (size_t)BROWS * CPAD, 0);
    for (int it = 0; it < ADMM_ITERS; ++it) {
        const int epoch = 1 + it;
        if (it < CHEAP_ITERS) {
            const int wl = (it == CHEAP_ITERS - 1) ? 1 : 0;
            bmma_gemm<4, 1><<<dim3(4, 8, KSPLIT), 256, BSMEM>>>(
                Vh, nullptr, Dh, nullptr, P, BROWS, DM, KSmma, CPAD, DM, DM,
                nullptr, nullptr, Wh, nullptr, epoch);
            bmma_gemm<3, 1><<<dim3(NT, 8, 1), 256, BSMEM>>>(
                Wh, nullptr, Eh, nullptr, nullptr, BROWS, CDICT, DM, DM, CPAD, CPAD,
                Q, U, Vh, Vl, wl);
        } else {
            const int last = (it == ADMM_ITERS - 1) ? 1 : 0;
            bmma_gemm<5, 3><<<dim3(4, 8, KSPLIT), 256, BSMEM>>>(
                Vh, Vl, Dh, Dl, P, BROWS, DM, KSmma, CPAD, DM, DM,
                nullptr, nullptr, Wh, Wl, epoch);
            bmma_gemm<2, 3><<<dim3(NT, 8, 1), 256, BSMEM>>>(
                Wh, Wl, Eh, El, nullptr, BROWS, CDICT, DM, DM, CPAD, CPAD,
                Q, U, Vh, Vl, last);
        }
    }

    // 8) recon = normalize(normalize(z @ D) + mean)   (z in Vh/Vl; accurate)
    bmma_gemm<6, 3><<<dim3(4, 8, KSPLIT), 256, BSMEM>>>(
        Vh, Vl, Dh, Dl, P, BROWS, DM, KSmma, CPAD, DM, DM,
        nullptr, W, nullptr, nullptr, /*epoch=*/ADMM_ITERS + 1);
    final_norm_kernel<<<BROWS, 128>>>(W, dMean, outRecon);
}

// round 13
// speedup vs baseline: 1.1653x; 1.0669x over previous
#include <cuda_runtime.h>
#include <cuda_bf16.h>
#include <math.h>
#include <stdint.h>

// ---------------------------------------------------------------------------
// Problem constants
// ---------------------------------------------------------------------------
#define BROWS 1024      // batch
#define CDICT 10000     // dictionary atoms
#define CPAD  10240     // padded dict dim: divisible by 128
#define DM    512       // embedding dim
#define RHO_F 5.0f
#define THR_F 0.002f    // lam / rho
#define EPS_F 1e-12f
#define ADMM_ITERS 100
#define CHEAP_ITERS 75  // 1-product bf16 iters; remainder 3-product polish
#define NS_ITERS 9
#define KSPLIT 4        // loop split-K: 128 CTAs <= 148 SMs (balanced)
#define GSLICES 25      // G split-K (Kslice=400, 400 CTAs)
#define NSPLIT 8        // NS split-K (Kslice=64, 128 CTAs)

// ---------------------------------------------------------------------------
// Scratch (static device globals -- no cudaMalloc allowed)
// ---------------------------------------------------------------------------
__device__ float          g_Q  [(size_t)BROWS * CPAD];  // Aty, then q (ld=CPAD)
__device__ float          g_Z  [(size_t)BROWS * CPAD];  // z state (fp32; replaces u)
__device__ __nv_bfloat16  g_Vh [(size_t)BROWS * CPAD];  // bf16-hi of v
__device__ __nv_bfloat16  g_Vl [(size_t)BROWS * CPAD];  // bf16-lo of v
__device__ __nv_bfloat16  g_Th [(size_t)BROWS * CPAD];  // Aty split hi (setup)
__device__ __nv_bfloat16  g_Tl [(size_t)BROWS * CPAD];  // Aty split lo (setup)
__device__ __nv_bfloat16  g_Dh [(size_t)CPAD * DM];     // dict hi [CPAD x 512]
__device__ __nv_bfloat16  g_Dl [(size_t)CPAD * DM];
__device__ __nv_bfloat16  g_DTh[(size_t)DM * CPAD];     // D^T hi [512 x CPAD]
__device__ __nv_bfloat16  g_DTl[(size_t)DM * CPAD];
__device__ float          g_E  [(size_t)DM * CPAD];     // E = G^{-1} D^T (fp32)
__device__ __nv_bfloat16  g_Eh [(size_t)DM * CPAD];
__device__ __nv_bfloat16  g_El [(size_t)DM * CPAD];
__device__ float          g_P  [(size_t)GSLICES * DM * DM]; // split-K partials
__device__ float          g_W  [(size_t)BROWS * DM];
__device__ __nv_bfloat16  g_Wh [(size_t)BROWS * DM];
__device__ __nv_bfloat16  g_Wl [(size_t)BROWS * DM];
__device__ float          g_Y  [(size_t)BROWS * DM];
__device__ __nv_bfloat16  g_Yh [(size_t)BROWS * DM];
__device__ __nv_bfloat16  g_Yl [(size_t)BROWS * DM];
__device__ float g_G [DM * DM];
__device__ float g_XA[DM * DM];
__device__ float g_XB[DM * DM];
__device__ float g_T [DM * DM];
__device__ float g_ninf;

// ---------------------------------------------------------------------------
// helpers
// ---------------------------------------------------------------------------
__device__ __forceinline__ void split_bf16(float v, __nv_bfloat16& h, __nv_bfloat16& l)
{
    h = __float2bfloat16_rn(v);
    l = __float2bfloat16_rn(v - __bfloat162float(h));
}

__device__ __forceinline__ void mma16(float* c, const unsigned* a,
                                      unsigned b0, unsigned b1)
{
    asm volatile(
        "mma.sync.aligned.m16n8k16.row.col.f32.bf16.bf16.f32 "
        "{%0,%1,%2,%3}, {%4,%5,%6,%7}, {%8,%9}, {%0,%1,%2,%3};"
        : "+f"(c[0]), "+f"(c[1]), "+f"(c[2]), "+f"(c[3])
        : "r"(a[0]), "r"(a[1]), "r"(a[2]), "r"(a[3]), "r"(b0), "r"(b1));
}

__device__ __forceinline__ void ldsm4(unsigned* r, uint32_t a)
{
    asm volatile("ldmatrix.sync.aligned.m8n8.x4.shared.b16 {%0,%1,%2,%3}, [%4];"
                 : "=r"(r[0]), "=r"(r[1]), "=r"(r[2]), "=r"(r[3]) : "r"(a));
}

__device__ __forceinline__ void ldsm4t(unsigned* r, uint32_t a)
{
    asm volatile("ldmatrix.sync.aligned.m8n8.x4.trans.shared.b16 {%0,%1,%2,%3}, [%4];"
                 : "=r"(r[0]), "=r"(r[1]), "=r"(r[2]), "=r"(r[3]) : "r"(a));
}

__device__ __forceinline__ void cp16(uint32_t s, const void* g)
{
    asm volatile("cp.async.cg.shared.global [%0], [%1], 16;"
                 :: "r"(s), "l"(g) : "memory");
}

// ---------------------------------------------------------------------------
// bf16 MMA GEMM, templated on product count and epilogue:
//   PROD==3: acc = Ah*Bh + Ah*Bl + Al*Bh       PROD==1: acc = Ah*Bh
// EPI 0: plain partial store at C + z*M*ldc (split-K, external reduce)
// EPI 1: q = (Qp - acc)/rho -> C (fp32)                              [setup]
// EPI 2: ADMM (z,v)-form, polish: t=Q+Z-acc; z'=max(t-thr,0); Z=z';
//        v' = flag ? z' : 2z'-t; split -> Vh, Vl
// EPI 3: ADMM (z,v)-form, cheap: same math; writes Vh; Vl iff flag
// (u eliminated: u+x == t, so z'=max(t-thr,0), v'=2z'-t exactly as before,
//  with exact fp32 z in place of (rounded v)+u -> strictly more accurate.)
// BM=BN=128, BK=32, 256 thr, 8 warps (32x64 warp tile), 2-stage cp.async,
// ldmatrix fragments (conflict-free strides 40 / 136 bf16).
// ---------------------------------------------------------------------------
#define BSTG  37888
#define BSMEM (2 * BSTG)

template<int EPI, int PROD>
__global__ void __launch_bounds__(256, 2)
bmma_gemm(const __nv_bfloat16* __restrict__ Ah, const __nv_bfloat16* __restrict__ Al,
          const __nv_bfloat16* __restrict__ Bh, const __nv_bfloat16* __restrict__ Bl,
          float* __restrict__ C, int M, int N, int Kslice,
          int lda, int ldb, int ldc,
          const float* __restrict__ Qp, float* __restrict__ Zp,
          __nv_bfloat16* __restrict__ Vh, __nv_bfloat16* __restrict__ Vl,
          int flag)
{
    extern __shared__ char smd[];
    const int tid  = threadIdx.x;
    const int lane = tid & 31, wid = tid >> 5;
    const int wm = (wid & 3) * 32;
    const int wn = (wid >> 2) * 64;
    const int m0 = blockIdx.y * 128, n0 = blockIdx.x * 128;
    const long k0 = (long)blockIdx.z * Kslice;
    const int nk = Kslice >> 5;

    const int aRow = wm + ((lane >> 3) & 1) * 8 + (lane & 7);
    const int aKof = (lane >> 4) * 8;
    const int bRow = ((lane >> 3) & 1) * 8 + (lane & 7);
    const int bNof = (lane >> 4) * 8;

    float c[2][8][4];
#pragma unroll
    for (int i = 0; i < 2; ++i)
#pragma unroll
        for (int j = 0; j < 8; ++j)
#pragma unroll
            for (int q = 0; q < 4; ++q) c[i][j][q] = 0.0f;

    auto load_tile = [&](int kt, int buf) {
        char* base = smd + buf * BSTG;
        const int kb = kt * 32;
#pragma unroll
        for (int cc = 0; cc < 2; ++cc) {        // A: 128 rows x 4 chunks (8 bf16)
            int ch  = tid * 2 + cc;
            int row = ch >> 2, kc = (ch & 3) * 8;
            uint32_t so = (uint32_t)__cvta_generic_to_shared(
                base + (row * 40 + kc) * 2);
            const long go = (long)(m0 + row) * lda + k0 + kb + kc;
            cp16(so, Ah + go);
            if (PROD == 3) cp16(so + 10240, Al + go);
        }
#pragma unroll
        for (int cc = 0; cc < 2; ++cc) {        // B: 32 rows x 16 chunks
            int ch  = tid * 2 + cc;
            int row = ch >> 4, nc = (ch & 15) * 8;
            uint32_t so = (uint32_t)__cvta_generic_to_shared(
                base + 20480 + (row * 136 + nc) * 2);
            const long go = (long)(k0 + kb + row) * ldb + n0 + nc;
            cp16(so, Bh + go);
            if (PROD == 3) cp16(so + 8704, Bl + go);
        }
    };

    load_tile(0, 0);
    asm volatile("cp.async.commit_group;" ::: "memory");

    for (int kt = 0; kt < nk; ++kt) {
        asm volatile("cp.async.wait_group 0;" ::: "memory");
        __syncthreads();
        if (kt + 1 < nk) load_tile(kt + 1, (kt + 1) & 1);
        asm volatile("cp.async.commit_group;" ::: "memory");

        const uint32_t sb = (uint32_t)__cvta_generic_to_shared(smd + (kt & 1) * BSTG);

#pragma unroll
        for (int ks = 0; ks < 2; ++ks) {
            unsigned ah[2][4], al[2][4];
#pragma unroll
            for (int i = 0; i < 2; ++i) {
                uint32_t ad = sb + ((aRow + i * 16) * 40 + ks * 16 + aKof) * 2;
                ldsm4(ah[i], ad);
                if (PROD == 3) ldsm4(al[i], ad + 10240);
            }
#pragma unroll
            for (int ng = 0; ng < 4; ++ng) {
                unsigned bh[4], bl[4];
                uint32_t bd = sb + 20480 +
                              ((bRow + ks * 16) * 136 + wn + ng * 16 + bNof) * 2;
                ldsm4t(bh, bd);
                if (PROD == 3) ldsm4t(bl, bd + 8704);
#pragma unroll
                for (int jj = 0; jj < 2; ++jj) {
                    const int j = ng * 2 + jj;
#pragma unroll
                    for (int i = 0; i < 2; ++i) {
                        mma16(c[i][j], ah[i], bh[jj * 2], bh[jj * 2 + 1]);
                        if (PROD == 3) {
                            mma16(c[i][j], ah[i], bl[jj * 2], bl[jj * 2 + 1]);
                            mma16(c[i][j], al[i], bh[jj * 2], bh[jj * 2 + 1]);
                        }
                    }
                }
            }
        }
    }

    // ---- epilogue ----
    const int gq = lane >> 2, tq = lane & 3;
#pragma unroll
    for (int i = 0; i < 2; ++i) {
        const int r0 = m0 + wm + i * 16 + gq;
#pragma unroll
        for (int j = 0; j < 8; ++j) {
            const int ccn = n0 + wn + j * 8 + 2 * tq;
            if (ccn >= N) continue;
            if (EPI == 0) {
                float* Cz = C + (long)blockIdx.z * (long)M * ldc;
                *(float2*)&Cz[(long)r0 * ldc + ccn] =
                    make_float2(c[i][j][0], c[i][j][1]);
                *(float2*)&Cz[(long)(r0 + 8) * ldc + ccn] =
                    make_float2(c[i][j][2], c[i][j][3]);
            } else if (EPI == 1) {
#pragma unroll
                for (int rr = 0; rr < 2; ++rr) {
                    const long idx = (long)(r0 + rr * 8) * ldc + ccn;
                    const float ir = 1.0f / RHO_F;
                    float2 qv = *(const float2*)&Qp[idx];
                    *(float2*)&C[idx] = make_float2(
                        (qv.x - c[i][j][rr * 2 + 0]) * ir,
                        (qv.y - c[i][j][rr * 2 + 1]) * ir);
                }
            } else if (EPI == 2) {   // polish ADMM, (z,v) form
#pragma unroll
                for (int rr = 0; rr < 2; ++rr) {
                    const long idx = (long)(r0 + rr * 8) * ldc + ccn;
                    float a0 = c[i][j][rr * 2 + 0], a1 = c[i][j][rr * 2 + 1];
                    float2 qv = *(const float2*)&Qp[idx];
                    float2 zv = *(const float2*)&Zp[idx];
                    float2 zn;
                    __nv_bfloat162 nh, nl;
                    {
                        float t = qv.x + zv.x - a0;
                        float z = fmaxf(t - THR_F, 0.f);
                        zn.x = z;
                        float vn = flag ? z : (2.f * z - t);
                        split_bf16(vn, nh.x, nl.x);
                    }
                    {
                        float t = qv.y + zv.y - a1;
                        float z = fmaxf(t - THR_F, 0.f);
                        zn.y = z;
                        float vn = flag ? z : (2.f * z - t);
                        split_bf16(vn, nh.y, nl.y);
                    }
                    *(float2*)&Zp[idx] = zn;
                    *(__nv_bfloat162*)&Vh[idx] = nh;
                    *(__nv_bfloat162*)&Vl[idx] = nl;
                }
            } else if (EPI == 3) {   // cheap ADMM, (z,v) form; Vl iff flag
#pragma unroll
                for (int rr = 0; rr < 2; ++rr) {
                    const long idx = (long)(r0 + rr * 8) * ldc + ccn;
                    float a0 = c[i][j][rr * 2 + 0], a1 = c[i][j][rr * 2 + 1];
                    float2 qv = *(const float2*)&Qp[idx];
                    float2 zv = *(const float2*)&Zp[idx];
                    float2 zn;
                    __nv_bfloat162 nh, nl;
                    {
                        float t = qv.x + zv.x - a0;
                        float z = fmaxf(t - THR_F, 0.f);
                        zn.x = z;
                        float vn = 2.f * z - t;
                        split_bf16(vn, nh.x, nl.x);
                    }
                    {
                        float t = qv.y + zv.y - a1;
                        float z = fmaxf(t - THR_F, 0.f);
                        zn.y = z;
                        float vn = 2.f * z - t;
                        split_bf16(vn, nh.y, nl.y);
                    }
                    *(float2*)&Zp[idx] = zn;
                    *(__nv_bfloat162*)&Vh[idx] = nh;
                    if (flag) *(__nv_bfloat162*)&Vl[idx] = nl;
                }
            }
        }
    }
}

// ---------------------------------------------------------------------------
// SIMT tiled SGEMM (setup path: G, NS, E -- full fp32 accuracy)
// ---------------------------------------------------------------------------
#define BM 128
#define BN 128
#define BKK 16

template<bool TA, bool TB>
__global__ void __launch_bounds__(256, 2)
gemm_kernel(const float* __restrict__ A, const float* __restrict__ B,
            float* __restrict__ C,
            int M, int N, int Kslice, int lda, int ldb, int ldc)
{
    __shared__ float As[BKK][BM + 4];
    __shared__ float Bs[BKK][BN + 4];

    const int tid = threadIdx.x;
    const int tx  = tid & 15;
    const int ty  = tid >> 4;
    const int m0  = blockIdx.y * BM;
    const int n0  = blockIdx.x * BN;

    const long k0 = (long)blockIdx.z * Kslice;
    if (TA) A += k0 * lda; else A += k0;
    if (TB) B += k0;       else B += k0 * ldb;
    C += (long)blockIdx.z * (long)M * ldc;

    float acc[8][8];
#pragma unroll
    for (int i = 0; i < 8; ++i)
#pragma unroll
        for (int j = 0; j < 8; ++j) acc[i][j] = 0.0f;

    const int nk = Kslice / BKK;
#pragma unroll 1
    for (int kt = 0; kt < nk; ++kt) {
        const int kbase = kt * BKK;
        if (!TA) {
#pragma unroll
            for (int p = 0; p < 2; ++p) {
                const int row = p * 64 + (tid >> 2);
                const int c4  = (tid & 3) * 4;
                float4 v = *(const float4*)&A[(long)(m0 + row) * lda + kbase + c4];
                As[c4 + 0][row] = v.x; As[c4 + 1][row] = v.y;
                As[c4 + 2][row] = v.z; As[c4 + 3][row] = v.w;
            }
        } else {
#pragma unroll
            for (int p = 0; p < 2; ++p) {
                const int kr = p * 8 + (tid >> 5);
                const int m4 = (tid & 31) * 4;
                float4 v = *(const float4*)&A[(long)(kbase + kr) * lda + m0 + m4];
                *(float4*)&As[kr][m4] = v;
            }
        }
        if (!TB) {
#pragma unroll
            for (int p = 0; p < 2; ++p) {
                const int kr  = p * 8 + (tid >> 5);
                const int nn4 = (tid & 31) * 4;
                const int gn  = n0 + nn4;
                float4 v = make_float4(0.f, 0.f, 0.f, 0.f);
                if (gn < N) v = *(const float4*)&B[(long)(kbase + kr) * ldb + gn];
                *(float4*)&Bs[kr][nn4] = v;
            }
        } else {
#pragma unroll
            for (int p = 0; p < 2; ++p) {
                const int nrow = p * 64 + (tid >> 2);
                const int c4   = (tid & 3) * 4;
                const int gn   = n0 + nrow;
                float4 v = make_float4(0.f, 0.f, 0.f, 0.f);
                if (gn < N) v = *(const float4*)&B[(long)gn * ldb + kbase + c4];
                Bs[c4 + 0][nrow] = v.x; Bs[c4 + 1][nrow] = v.y;
                Bs[c4 + 2][nrow] = v.z; Bs[c4 + 3][nrow] = v.w;
            }
        }
        __syncthreads();
#pragma unroll
        for (int kk = 0; kk < BKK; ++kk) {
            float a[8], b[8];
            *(float4*)&a[0] = *(const float4*)&As[kk][ty * 4];
            *(float4*)&a[4] = *(const float4*)&As[kk][64 + ty * 4];
            *(float4*)&b[0] = *(const float4*)&Bs[kk][tx * 4];
            *(float4*)&b[4] = *(const float4*)&Bs[kk][64 + tx * 4];
#pragma unroll
            for (int i = 0; i < 8; ++i)
#pragma unroll
                for (int j = 0; j < 8; ++j)
                    acc[i][j] = fmaf(a[i], b[j], acc[i][j]);
        }
        __syncthreads();
    }

    int rows[8];
#pragma unroll
    for (int i = 0; i < 8; ++i)
        rows[i] = m0 + (i < 4 ? ty * 4 + i : 64 + ty * 4 + (i - 4));

#pragma unroll
    for (int i = 0; i < 8; ++i) {
#pragma unroll
        for (int jg = 0; jg < 2; ++jg) {
            const int cn = n0 + jg * 64 + tx * 4;
            if (cn >= N) continue;
            const long idx = (long)rows[i] * ldc + cn;
            *(float4*)&C[idx] = make_float4(acc[i][jg * 4 + 0], acc[i][jg * 4 + 1],
                                            acc[i][jg * 4 + 2], acc[i][jg * 4 + 3]);
        }
    }
}

// ---------------------------------------------------------------------------
// Transpose + bf16 split: out[i*ldo + j] = split(src[j*lds + i]), i<R, j<C
// ---------------------------------------------------------------------------
__global__ void trans_split_kernel(const float* __restrict__ src, int lds,
                                   __nv_bfloat16* __restrict__ dh,
                                   __nv_bfloat16* __restrict__ dl,
                                   int ldo, int R, int C)
{
    __shared__ float t[32][33];
    const int i0 = blockIdx.x * 32;
    const int j0 = blockIdx.y * 32;
    const int tx = threadIdx.x, ty = threadIdx.y;
    for (int jj = ty; jj < 32; jj += 8) {
        const int j = j0 + jj, i = i0 + tx;
        float v = 0.f;
        if (j < C && i < R) v = src[(long)j * lds + i];
        t[jj][tx] = v;
    }
    __syncthreads();
    for (int ii = ty; ii < 32; ii += 8) {
        const int i = i0 + ii, j = j0 + tx;
        if (i < R && j < C) {
            __nv_bfloat16 h, l;
            split_bf16(t[tx][ii], h, l);
            dh[(long)i * ldo + j] = h;
            dl[(long)i * ldo + j] = l;
        }
    }
}

// ---------------------------------------------------------------------------
// Reductions / splits
// ---------------------------------------------------------------------------
__global__ void reduce_sum(const float4* __restrict__ P, float4* __restrict__ out,
                           int n4, int S)
{
    int i = blockIdx.x * blockDim.x + threadIdx.x;
    if (i >= n4) return;
    float4 s = P[i];
    for (int k = 1; k < S; ++k) {
        float4 t = P[(long)k * n4 + i];
        s.x += t.x; s.y += t.y; s.z += t.z; s.w += t.w;
    }
    out[i] = s;
}

__global__ void reduce_split_hl(const float2* __restrict__ P,
                                __nv_bfloat162* __restrict__ Wh,
                                __nv_bfloat162* __restrict__ Wl,
                                int n2, int S)
{
    int i = blockIdx.x * blockDim.x + threadIdx.x;
    if (i >= n2) return;
    float2 s = P[i];
    for (int k = 1; k < S; ++k) {
        float2 t = P[(long)k * n2 + i];
        s.x += t.x; s.y += t.y;
    }
    __nv_bfloat162 h, l;
    split_bf16(s.x, h.x, l.x);
    split_bf16(s.y, h.y, l.y);
    Wh[i] = h; Wl[i] = l;
}

__global__ void reduce_split_h(const float2* __restrict__ P,
                               __nv_bfloat162* __restrict__ Wh,
                               int n2, int S)
{
    int i = blockIdx.x * blockDim.x + threadIdx.x;
    if (i >= n2) return;
    float2 s = P[i];
    for (int k = 1; k < S; ++k) {
        float2 t = P[(long)k * n2 + i];
        s.x += t.x; s.y += t.y;
    }
    __nv_bfloat162 h;
    h.x = __float2bfloat16_rn(s.x);
    h.y = __float2bfloat16_rn(s.y);
    Wh[i] = h;
}

__global__ void split_mat_bf16(const float2* __restrict__ src,
                               __nv_bfloat162* __restrict__ hi,
                               __nv_bfloat162* __restrict__ lo, long n2)
{
    long i = (long)blockIdx.x * blockDim.x + threadIdx.x;
    if (i >= n2) return;
    float2 v = src[i];
    __nv_bfloat162 h, l;
    split_bf16(v.x, h.x, l.x);
    split_bf16(v.y, h.y, l.y);
    hi[i] = h; lo[i] = l;
}

__global__ void reduce_G(const float* __restrict__ P, float* __restrict__ G, int S)
{
    int i = blockIdx.x * blockDim.x + threadIdx.x;
    if (i >= DM * DM) return;
    float s = 0.f;
    for (int k = 0; k < S; ++k) s += P[(long)k * DM * DM + i];
    if ((i / DM) == (i % DM)) s += RHO_F;
    G[i] = s;
}

__global__ void reduce_ns(const float4* __restrict__ P, const float4* __restrict__ Xc,
                          float4* __restrict__ Xn, int n4, int S)
{
    int i = blockIdx.x * blockDim.x + threadIdx.x;
    if (i >= n4) return;
    float4 s = P[i];
    for (int k = 1; k < S; ++k) {
        float4 t = P[(long)k * n4 + i];
        s.x += t.x; s.y += t.y; s.z += t.z; s.w += t.w;
    }
    float4 x = Xc[i];
    Xn[i] = make_float4(2.f * x.x - s.x, 2.f * x.y - s.y,
                        2.f * x.z - s.z, 2.f * x.w - s.w);
}

__global__ void ninf_kernel(const float* __restrict__ G)
{
    __shared__ float sm[DM];
    const int i = threadIdx.x;
    float s = 0.f;
    for (int j = 0; j < DM; ++j) s += fabsf(G[(long)j * DM + i]);
    sm[i] = s;
    __syncthreads();
    for (int o = DM / 2; o > 0; o >>= 1) {
        if (i < o) sm[i] = fmaxf(sm[i], sm[i + o]);
        __syncthreads();
    }
    if (i == 0) g_ninf = sm[0];
}

__global__ void x0_kernel(float* __restrict__ X)
{
    int i = blockIdx.x * blockDim.x + threadIdx.x;
    if (i >= DM * DM) return;
    float c = 2.0f / (RHO_F + g_ninf);
    X[i] = ((i / DM) == (i % DM)) ? c : 0.0f;
}

// ---------------------------------------------------------------------------
// Row-normalize kernels
// ---------------------------------------------------------------------------
__device__ __forceinline__ float block_sum128(float v, float* red)
{
    for (int o = 16; o > 0; o >>= 1) v += __shfl_xor_sync(0xffffffff, v, o);
    if ((threadIdx.x & 31) == 0) red[threadIdx.x >> 5] = v;
    __syncthreads();
    float tot = red[0] + red[1] + red[2] + red[3];
    __syncthreads();
    return tot;
}

__global__ void norm_center_kernel(const float* __restrict__ img,
                                   const float* __restrict__ mean,
                                   float* __restrict__ out)
{
    __shared__ float red[4];
    const int r = blockIdx.x, t = threadIdx.x;
    float4 v = ((const float4*)(img + (long)r * DM))[t];
    float ss = v.x * v.x + v.y * v.y + v.z * v.z + v.w * v.w;
    float inv = 1.0f / fmaxf(sqrtf(block_sum128(ss, red)), EPS_F);
    float4 mv = ((const float4*)mean)[t];
    float4 c = make_float4(v.x * inv - mv.x, v.y * inv - mv.y,
                           v.z * inv - mv.z, v.w * inv - mv.w);
    float ss2 = c.x * c.x + c.y * c.y + c.z * c.z + c.w * c.w;
    float inv2 = 1.0f / fmaxf(sqrtf(block_sum128(ss2, red)), EPS_F);
    ((float4*)(out + (long)r * DM))[t] =
        make_float4(c.x * inv2, c.y * inv2, c.z * inv2, c.w * inv2);
}

__global__ void norm_rows_kernel(const float* __restrict__ in, float* __restrict__ out)
{
    __shared__ float red[4];
    const int r = blockIdx.x, t = threadIdx.x;
    float4 v = ((const float4*)(in + (long)r * DM))[t];
    float ss = v.x * v.x + v.y * v.y + v.z * v.z + v.w * v.w;
    float inv = 1.0f / fmaxf(sqrtf(block_sum128(ss, red)), EPS_F);
    ((float4*)(out + (long)r * DM))[t] =
        make_float4(v.x * inv, v.y * inv, v.z * inv, v.w * inv);
}

__global__ void final_norm_kernel(const float* __restrict__ rec,
                                  const float* __restrict__ mean,
                                  float* __restrict__ out)
{
    __shared__ float red[4];
    const int r = blockIdx.x, t = threadIdx.x;
    float4 v = ((const float4*)(rec + (long)r * DM))[t];
    float ss = v.x * v.x + v.y * v.y + v.z * v.z + v.w * v.w;
    float inv = 1.0f / fmaxf(sqrtf(block_sum128(ss, red)), EPS_F);
    float4 mv = ((const float4*)mean)[t];
    float4 c = make_float4(v.x * inv + mv.x, v.y * inv + mv.y,
                           v.z * inv + mv.z, v.w * inv + mv.w);
    float ss2 = c.x * c.x + c.y * c.y + c.z * c.z + c.w * c.w;
    float inv2 = 1.0f / fmaxf(sqrtf(block_sum128(ss2, red)), EPS_F);
    ((float4*)(out + (long)r * DM))[t] =
        make_float4(c.x * inv2, c.y * inv2, c.z * inv2, c.w * inv2);
}

// ---------------------------------------------------------------------------
// Host orchestration
// ---------------------------------------------------------------------------
extern "C" void kernel_launch(void* const* d_in, const int* in_sizes, int n_in,
                              void* d_out, int out_size)
{
    const float* dImg  = (const float*)d_in[0];
    const float* dTxt  = (const float*)d_in[1];
    const float* dMean = (const float*)d_in[2];
    const float* dDict = (const float*)d_in[3];
    float* outRecon = (float*)d_out;
    float* outTxt   = (float*)d_out + (long)BROWS * DM;

    float *Q, *Z, *E, *P, *W, *Y, *G, *XA, *XB, *T;
    __nv_bfloat16 *Vh, *Vl, *Th, *Tl, *Dh, *Dl, *DTh, *DTl, *Eh, *El,
                  *Wh, *Wl, *Yh, *Yl;
    cudaGetSymbolAddress((void**)&Q,   g_Q);
    cudaGetSymbolAddress((void**)&Z,   g_Z);
    cudaGetSymbolAddress((void**)&Vh,  g_Vh);
    cudaGetSymbolAddress((void**)&Vl,  g_Vl);
    cudaGetSymbolAddress((void**)&Th,  g_Th);
    cudaGetSymbolAddress((void**)&Tl,  g_Tl);
    cudaGetSymbolAddress((void**)&Dh,  g_Dh);
    cudaGetSymbolAddress((void**)&Dl,  g_Dl);
    cudaGetSymbolAddress((void**)&DTh, g_DTh);
    cudaGetSymbolAddress((void**)&DTl, g_DTl);
    cudaGetSymbolAddress((void**)&E,   g_E);
    cudaGetSymbolAddress((void**)&Eh,  g_Eh);
    cudaGetSymbolAddress((void**)&El,  g_El);
    cudaGetSymbolAddress((void**)&P,   g_P);
    cudaGetSymbolAddress((void**)&W,   g_W);
    cudaGetSymbolAddress((void**)&Wh,  g_Wh);
    cudaGetSymbolAddress((void**)&Wl,  g_Wl);
    cudaGetSymbolAddress((void**)&Y,   g_Y);
    cudaGetSymbolAddress((void**)&Yh,  g_Yh);
    cudaGetSymbolAddress((void**)&Yl,  g_Yl);
    cudaGetSymbolAddress((void**)&G,   g_G);
    cudaGetSymbolAddress((void**)&XA,  g_XA);
    cudaGetSymbolAddress((void**)&XB,  g_XB);
    cudaGetSymbolAddress((void**)&T,   g_T);

    cudaFuncSetAttribute(bmma_gemm<0, 3>, cudaFuncAttributeMaxDynamicSharedMemorySize, BSMEM);
    cudaFuncSetAttribute(bmma_gemm<1, 3>, cudaFuncAttributeMaxDynamicSharedMemorySize, BSMEM);
    cudaFuncSetAttribute(bmma_gemm<2, 3>, cudaFuncAttributeMaxDynamicSharedMemorySize, BSMEM);
    cudaFuncSetAttribute(bmma_gemm<0, 1>, cudaFuncAttributeMaxDynamicSharedMemorySize, BSMEM);
    cudaFuncSetAttribute(bmma_gemm<3, 1>, cudaFuncAttributeMaxDynamicSharedMemorySize, BSMEM);

    const int NT = (CDICT + BN - 1) / BN;   // 79 tiles over N=10000
    const int KSG = CDICT / GSLICES;        // 400 (G split-K, 25 slices)
    const int KSmma = CPAD / KSPLIT;        // 2560 (loop split-K, 4 slices)

    // 0) zero-pad-sensitive buffers
    cudaMemsetAsync(Q,   0, sizeof(float) * (size_t)BROWS * CPAD, 0);
    cudaMemsetAsync(DTh, 0, sizeof(__nv_bfloat16) * (size_t)DM * CPAD, 0);
    cudaMemsetAsync(DTl, 0, sizeof(__nv_bfloat16) * (size_t)DM * CPAD, 0);
    cudaMemsetAsync(Dh,  0, sizeof(__nv_bfloat16) * (size_t)CPAD * DM, 0);
    cudaMemsetAsync(Dl,  0, sizeof(__nv_bfloat16) * (size_t)CPAD * DM, 0);
    cudaMemsetAsync(E,   0, sizeof(float) * (size_t)DM * CPAD, 0);

    // 1) centered inputs + text output; splits of Y and D / D^T
    norm_center_kernel<<<BROWS, 128>>>(dImg, dMean, Y);
    norm_rows_kernel<<<BROWS, 128>>>(dTxt, outTxt);
    split_mat_bf16<<<(BROWS * DM / 2 + 255) / 256, 256>>>(
        (const float2*)Y, (__nv_bfloat162*)Yh, (__nv_bfloat162*)Yl, BROWS * DM / 2);
    split_mat_bf16<<<(int)(((long)CDICT * DM / 2 + 255) / 256), 256>>>(
        (const float2*)dDict, (__nv_bfloat162*)Dh, (__nv_bfloat162*)Dl,
        (long)CDICT * DM / 2);
    trans_split_kernel<<<dim3(16, 313), dim3(32, 8)>>>(
        dDict, DM, DTh, DTl, CPAD, DM, CDICT);

    // 2) Aty = Y @ D^T -> Q (bf16x3 tensor path; Q pads stay zero)
    bmma_gemm<0, 3><<<dim3(NT, 8, 1), 256, BSMEM>>>(
        Yh, Yl, DTh, DTl, Q, BROWS, CDICT, DM, DM, CPAD, CPAD,
        nullptr, nullptr, nullptr, nullptr, 0);

    // 3) G = D^T D + rho I (fp32 SIMT, 25-way split-K -> 400 CTAs)
    gemm_kernel<true, false><<<dim3(4, 4, GSLICES), 256>>>(
        dDict, dDict, P, DM, DM, KSG, DM, DM, DM);
    reduce_G<<<(DM * DM + 255) / 256, 256>>>(P, G, GSLICES);

    // 4) Newton-Schulz inverse (fp32 SIMT, 8-way split-K -> 128 CTAs)
    ninf_kernel<<<1, DM>>>(G);
    x0_kernel<<<(DM * DM + 255) / 256, 256>>>(XA);
    float* Xc = XA; float* Xn = XB;
    for (int t = 0; t < NS_ITERS; ++t) {
        gemm_kernel<false, false><<<dim3(4, 4, NSPLIT), 256>>>(
            G, Xc, P, DM, DM, DM / NSPLIT, DM, DM, DM);
        reduce_sum<<<(DM * DM / 4 + 255) / 256, 256>>>(
            (const float4*)P, (float4*)T, DM * DM / 4, NSPLIT);
        gemm_kernel<false, false><<<dim3(4, 4, NSPLIT), 256>>>(
            Xc, T, P, DM, DM, DM / NSPLIT, DM, DM, DM);
        reduce_ns<<<(DM * DM / 4 + 255) / 256, 256>>>(
            (const float4*)P, (const float4*)Xc, (float4*)Xn, DM * DM / 4, NSPLIT);
        float* tmp = Xc; Xc = Xn; Xn = tmp;
    }

    // 5) E = G^{-1} @ D^T (fp32 SIMT; ld = CPAD, pads zero) + bf16 split
    gemm_kernel<false, true><<<dim3(NT, 4, 1), 256>>>(
        Xc, dDict, E, DM, CDICT, DM, DM, DM, CPAD);
    split_mat_bf16<<<(int)(((long)DM * CPAD / 2 + 255) / 256), 256>>>(
        (const float2*)E, (__nv_bfloat162*)Eh, (__nv_bfloat162*)El,
        (long)DM * CPAD / 2);

    // 6) q = (Aty - (Aty @ D) @ E) / rho  (bf16x3 tensor path, in place on Q)
    split_mat_bf16<<<(int)(((long)BROWS * CPAD / 2 + 255) / 256), 256>>>(
        (const float2*)Q, (__nv_bfloat162*)Th, (__nv_bfloat162*)Tl,
        (long)BROWS * CPAD / 2);
    bmma_gemm<0, 3><<<dim3(4, 8, KSPLIT), 256, BSMEM>>>(
        Th, Tl, Dh, Dl, P, BROWS, DM, KSmma, CPAD, DM, DM,
        nullptr, nullptr, nullptr, nullptr, 0);
    reduce_split_hl<<<(BROWS * DM / 2 + 255) / 256, 256>>>(
        (const float2*)P, (__nv_bfloat162*)Wh, (__nv_bfloat162*)Wl,
        BROWS * DM / 2, KSPLIT);
    bmma_gemm<1, 3><<<dim3(NT, 8, 1), 256, BSMEM>>>(
        Wh, Wl, Eh, El, Q, BROWS, CDICT, DM, DM, CPAD, CPAD,
        Q, nullptr, nullptr, nullptr, 0);

    // 7) ADMM loop, (z, v) state form: t = q + z - (vD)E;
    //    z' = max(t - thr, 0); v' = 2z' - t.  u is never materialized.
    cudaMemsetAsync(Vh, 0, sizeof(__nv_bfloat16) * (size_t)BROWS * CPAD, 0);
    cudaMemsetAsync(Vl, 0, sizeof(__nv_bfloat16) * (size_t)BROWS * CPAD, 0);
    cudaMemsetAsync(Z,  0, sizeof(float) * (size_t)BROWS * CPAD, 0);
    for (int it = 0; it < ADMM_ITERS; ++it) {
        if (it < CHEAP_ITERS) {
            const int wl = (it == CHEAP_ITERS - 1) ? 1 : 0;
            bmma_gemm<0, 1><<<dim3(4, 8, KSPLIT), 256, BSMEM>>>(
                Vh, nullptr, Dh, nullptr, P, BROWS, DM, KSmma, CPAD, DM, DM,
                nullptr, nullptr, nullptr, nullptr, 0);
            reduce_split_h<<<(BROWS * DM / 2 + 255) / 256, 256>>>(
                (const float2*)P, (__nv_bfloat162*)Wh, BROWS * DM / 2, KSPLIT);
            bmma_gemm<3, 1><<<dim3(NT, 8, 1), 256, BSMEM>>>(
                Wh, nullptr, Eh, nullptr, nullptr, BROWS, CDICT, DM, DM, CPAD, CPAD,
                Q, Z, Vh, Vl, wl);
        } else {
            const int last = (it == ADMM_ITERS - 1) ? 1 : 0;
            bmma_gemm<0, 3><<<dim3(4, 8, KSPLIT), 256, BSMEM>>>(
                Vh, Vl, Dh, Dl, P, BROWS, DM, KSmma, CPAD, DM, DM,
                nullptr, nullptr, nullptr, nullptr, 0);
            reduce_split_hl<<<(BROWS * DM / 2 + 255) / 256, 256>>>(
                (const float2*)P, (__nv_bfloat162*)Wh, (__nv_bfloat162*)Wl,
                BROWS * DM / 2, KSPLIT);
            bmma_gemm<2, 3><<<dim3(NT, 8, 1), 256, BSMEM>>>(
                Wh, Wl, Eh, El, nullptr, BROWS, CDICT, DM, DM, CPAD, CPAD,
                Q, Z, Vh, Vl, last);
        }
    }

    // 8) recon = normalize(normalize(z @ D) + mean)   (z in Vh/Vl; accurate)
    bmma_gemm<0, 3><<<dim3(4, 8, KSPLIT), 256, BSMEM>>>(
        Vh, Vl, Dh, Dl, P, BROWS, DM, KSmma, CPAD, DM, DM,
        nullptr, nullptr, nullptr, nullptr, 0);
    reduce_sum<<<(BROWS * DM / 4 + 255) / 256, 256>>>(
        (const float4*)P, (float4*)W, BROWS * DM / 4, KSPLIT);
    final_norm_kernel<<<BROWS, 128>>>(W, dMean, outRecon);
}

// round 14
// speedup vs baseline: 1.2258x; 1.0519x over previous
#include <cuda_runtime.h>
#include <cuda_bf16.h>
#include <math.h>
#include <stdint.h>

// ---------------------------------------------------------------------------
// Problem constants
// ---------------------------------------------------------------------------
#define BROWS 1024      // batch
#define CDICT 10000     // dictionary atoms
#define CPAD  10240     // padded dict dim: divisible by 128
#define DM    512       // embedding dim
#define RHO_F 5.0f
#define THR_F 0.002f    // lam / rho
#define EPS_F 1e-12f
#define ADMM_ITERS 100
#define CHEAP_ITERS 85  // 1-product bf16 iters; remainder 3-product polish
#define NS_ITERS 9
#define KSPLIT 4        // loop split-K: 128 CTAs <= 148 SMs (balanced)
#define GSLICES 25      // G split-K (Kslice=400, 400 CTAs)
#define NSPLIT 8        // NS split-K (Kslice=64, 128 CTAs)

// ---------------------------------------------------------------------------
// Scratch (static device globals -- no cudaMalloc allowed)
// ---------------------------------------------------------------------------
__device__ float          g_Q  [(size_t)BROWS * CPAD];  // Aty, then q (ld=CPAD)
__device__ float          g_Z  [(size_t)BROWS * CPAD];  // z state (fp32; replaces u)
__device__ __nv_bfloat16  g_Vh [(size_t)BROWS * CPAD];  // bf16-hi of v
__device__ __nv_bfloat16  g_Vl [(size_t)BROWS * CPAD];  // bf16-lo of v
__device__ __nv_bfloat16  g_Th [(size_t)BROWS * CPAD];  // Aty split hi (setup)
__device__ __nv_bfloat16  g_Tl [(size_t)BROWS * CPAD];  // Aty split lo (setup)
__device__ __nv_bfloat16  g_Dh [(size_t)CPAD * DM];     // dict hi [CPAD x 512]
__device__ __nv_bfloat16  g_Dl [(size_t)CPAD * DM];
__device__ __nv_bfloat16  g_DTh[(size_t)DM * CPAD];     // D^T hi [512 x CPAD]
__device__ __nv_bfloat16  g_DTl[(size_t)DM * CPAD];
__device__ float          g_E  [(size_t)DM * CPAD];     // E = G^{-1} D^T (fp32)
__device__ __nv_bfloat16  g_Eh [(size_t)DM * CPAD];
__device__ __nv_bfloat16  g_El [(size_t)DM * CPAD];
__device__ float          g_P  [(size_t)GSLICES * DM * DM]; // split-K partials
__device__ float          g_W  [(size_t)BROWS * DM];
__device__ __nv_bfloat16  g_Wh [(size_t)BROWS * DM];
__device__ __nv_bfloat16  g_Wl [(size_t)BROWS * DM];
__device__ float          g_Y  [(size_t)BROWS * DM];
__device__ __nv_bfloat16  g_Yh [(size_t)BROWS * DM];
__device__ __nv_bfloat16  g_Yl [(size_t)BROWS * DM];
__device__ float g_G [DM * DM];
__device__ float g_XA[DM * DM];
__device__ float g_XB[DM * DM];
__device__ float g_T [DM * DM];
__device__ float g_ninf;

// ---------------------------------------------------------------------------
// helpers
// ---------------------------------------------------------------------------
__device__ __forceinline__ void split_bf16(float v, __nv_bfloat16& h, __nv_bfloat16& l)
{
    h = __float2bfloat16_rn(v);
    l = __float2bfloat16_rn(v - __bfloat162float(h));
}

__device__ __forceinline__ void mma16(float* c, const unsigned* a,
                                      unsigned b0, unsigned b1)
{
    asm volatile(
        "mma.sync.aligned.m16n8k16.row.col.f32.bf16.bf16.f32 "
        "{%0,%1,%2,%3}, {%4,%5,%6,%7}, {%8,%9}, {%0,%1,%2,%3};"
        : "+f"(c[0]), "+f"(c[1]), "+f"(c[2]), "+f"(c[3])
        : "r"(a[0]), "r"(a[1]), "r"(a[2]), "r"(a[3]), "r"(b0), "r"(b1));
}

__device__ __forceinline__ void ldsm4(unsigned* r, uint32_t a)
{
    asm volatile("ldmatrix.sync.aligned.m8n8.x4.shared.b16 {%0,%1,%2,%3}, [%4];"
                 : "=r"(r[0]), "=r"(r[1]), "=r"(r[2]), "=r"(r[3]) : "r"(a));
}

__device__ __forceinline__ void ldsm4t(unsigned* r, uint32_t a)
{
    asm volatile("ldmatrix.sync.aligned.m8n8.x4.trans.shared.b16 {%0,%1,%2,%3}, [%4];"
                 : "=r"(r[0]), "=r"(r[1]), "=r"(r[2]), "=r"(r[3]) : "r"(a));
}

__device__ __forceinline__ void cp16(uint32_t s, const void* g)
{
    asm volatile("cp.async.cg.shared.global [%0], [%1], 16;"
                 :: "r"(s), "l"(g) : "memory");
}

// ---------------------------------------------------------------------------
// bf16 MMA GEMM, templated on product count and epilogue:
//   PROD==3: acc = Ah*Bh + Ah*Bl + Al*Bh       PROD==1: acc = Ah*Bh
// EPI 0: plain partial store at C + z*M*ldc (split-K, external reduce)
// EPI 1: q = (Qp - acc)/rho -> C (fp32)                              [setup]
// EPI 2: ADMM (z,v)-form, polish: t=Q+Z-acc; z'=max(t-thr,0); Z=z';
//        v' = flag ? z' : 2z'-t; split -> Vh, Vl
// EPI 3: ADMM (z,v)-form, cheap: same math; writes Vh; Vl iff flag
// BM=BN=128, BK=32, 256 thr, 8 warps (32x64 warp tile), 2-stage cp.async,
// ldmatrix fragments (conflict-free strides 40 / 136 bf16).
// ---------------------------------------------------------------------------
#define BSTG  37888
#define BSMEM (2 * BSTG)

template<int EPI, int PROD>
__global__ void __launch_bounds__(256, 2)
bmma_gemm(const __nv_bfloat16* __restrict__ Ah, const __nv_bfloat16* __restrict__ Al,
          const __nv_bfloat16* __restrict__ Bh, const __nv_bfloat16* __restrict__ Bl,
          float* __restrict__ C, int M, int N, int Kslice,
          int lda, int ldb, int ldc,
          const float* __restrict__ Qp, float* __restrict__ Zp,
          __nv_bfloat16* __restrict__ Vh, __nv_bfloat16* __restrict__ Vl,
          int flag)
{
    extern __shared__ char smd[];
    const int tid  = threadIdx.x;
    const int lane = tid & 31, wid = tid >> 5;
    const int wm = (wid & 3) * 32;
    const int wn = (wid >> 2) * 64;
    const int m0 = blockIdx.y * 128, n0 = blockIdx.x * 128;
    const long k0 = (long)blockIdx.z * Kslice;
    const int nk = Kslice >> 5;

    const int aRow = wm + ((lane >> 3) & 1) * 8 + (lane & 7);
    const int aKof = (lane >> 4) * 8;
    const int bRow = ((lane >> 3) & 1) * 8 + (lane & 7);
    const int bNof = (lane >> 4) * 8;

    float c[2][8][4];
#pragma unroll
    for (int i = 0; i < 2; ++i)
#pragma unroll
        for (int j = 0; j < 8; ++j)
#pragma unroll
            for (int q = 0; q < 4; ++q) c[i][j][q] = 0.0f;

    auto load_tile = [&](int kt, int buf) {
        char* base = smd + buf * BSTG;
        const int kb = kt * 32;
#pragma unroll
        for (int cc = 0; cc < 2; ++cc) {        // A: 128 rows x 4 chunks (8 bf16)
            int ch  = tid * 2 + cc;
            int row = ch >> 2, kc = (ch & 3) * 8;
            uint32_t so = (uint32_t)__cvta_generic_to_shared(
                base + (row * 40 + kc) * 2);
            const long go = (long)(m0 + row) * lda + k0 + kb + kc;
            cp16(so, Ah + go);
            if (PROD == 3) cp16(so + 10240, Al + go);
        }
#pragma unroll
        for (int cc = 0; cc < 2; ++cc) {        // B: 32 rows x 16 chunks
            int ch  = tid * 2 + cc;
            int row = ch >> 4, nc = (ch & 15) * 8;
            uint32_t so = (uint32_t)__cvta_generic_to_shared(
                base + 20480 + (row * 136 + nc) * 2);
            const long go = (long)(k0 + kb + row) * ldb + n0 + nc;
            cp16(so, Bh + go);
            if (PROD == 3) cp16(so + 8704, Bl + go);
        }
    };

    load_tile(0, 0);
    asm volatile("cp.async.commit_group;" ::: "memory");

    for (int kt = 0; kt < nk; ++kt) {
        asm volatile("cp.async.wait_group 0;" ::: "memory");
        __syncthreads();
        if (kt + 1 < nk) load_tile(kt + 1, (kt + 1) & 1);
        asm volatile("cp.async.commit_group;" ::: "memory");

        const uint32_t sb = (uint32_t)__cvta_generic_to_shared(smd + (kt & 1) * BSTG);

#pragma unroll
        for (int ks = 0; ks < 2; ++ks) {
            unsigned ah[2][4], al[2][4];
#pragma unroll
            for (int i = 0; i < 2; ++i) {
                uint32_t ad = sb + ((aRow + i * 16) * 40 + ks * 16 + aKof) * 2;
                ldsm4(ah[i], ad);
                if (PROD == 3) ldsm4(al[i], ad + 10240);
            }
#pragma unroll
            for (int ng = 0; ng < 4; ++ng) {
                unsigned bh[4], bl[4];
                uint32_t bd = sb + 20480 +
                              ((bRow + ks * 16) * 136 + wn + ng * 16 + bNof) * 2;
                ldsm4t(bh, bd);
                if (PROD == 3) ldsm4t(bl, bd + 8704);
#pragma unroll
                for (int jj = 0; jj < 2; ++jj) {
                    const int j = ng * 2 + jj;
#pragma unroll
                    for (int i = 0; i < 2; ++i) {
                        mma16(c[i][j], ah[i], bh[jj * 2], bh[jj * 2 + 1]);
                        if (PROD == 3) {
                            mma16(c[i][j], ah[i], bl[jj * 2], bl[jj * 2 + 1]);
                            mma16(c[i][j], al[i], bh[jj * 2], bh[jj * 2 + 1]);
                        }
                    }
                }
            }
        }
    }

    // ---- epilogue ----
    const int gq = lane >> 2, tq = lane & 3;
#pragma unroll
    for (int i = 0; i < 2; ++i) {
        const int r0 = m0 + wm + i * 16 + gq;
#pragma unroll
        for (int j = 0; j < 8; ++j) {
            const int ccn = n0 + wn + j * 8 + 2 * tq;
            if (ccn >= N) continue;
            if (EPI == 0) {
                float* Cz = C + (long)blockIdx.z * (long)M * ldc;
                *(float2*)&Cz[(long)r0 * ldc + ccn] =
                    make_float2(c[i][j][0], c[i][j][1]);
                *(float2*)&Cz[(long)(r0 + 8) * ldc + ccn] =
                    make_float2(c[i][j][2], c[i][j][3]);
            } else if (EPI == 1) {
#pragma unroll
                for (int rr = 0; rr < 2; ++rr) {
                    const long idx = (long)(r0 + rr * 8) * ldc + ccn;
                    const float ir = 1.0f / RHO_F;
                    float2 qv = *(const float2*)&Qp[idx];
                    *(float2*)&C[idx] = make_float2(
                        (qv.x - c[i][j][rr * 2 + 0]) * ir,
                        (qv.y - c[i][j][rr * 2 + 1]) * ir);
                }
            } else if (EPI == 2) {   // polish ADMM, (z,v) form
#pragma unroll
                for (int rr = 0; rr < 2; ++rr) {
                    const long idx = (long)(r0 + rr * 8) * ldc + ccn;
                    float a0 = c[i][j][rr * 2 + 0], a1 = c[i][j][rr * 2 + 1];
                    float2 qv = *(const float2*)&Qp[idx];
                    float2 zv = *(const float2*)&Zp[idx];
                    float2 zn;
                    __nv_bfloat162 nh, nl;
                    {
                        float t = qv.x + zv.x - a0;
                        float z = fmaxf(t - THR_F, 0.f);
                        zn.x = z;
                        float vn = flag ? z : (2.f * z - t);
                        split_bf16(vn, nh.x, nl.x);
                    }
                    {
                        float t = qv.y + zv.y - a1;
                        float z = fmaxf(t - THR_F, 0.f);
                        zn.y = z;
                        float vn = flag ? z : (2.f * z - t);
                        split_bf16(vn, nh.y, nl.y);
                    }
                    *(float2*)&Zp[idx] = zn;
                    *(__nv_bfloat162*)&Vh[idx] = nh;
                    *(__nv_bfloat162*)&Vl[idx] = nl;
                }
            } else if (EPI == 3) {   // cheap ADMM, (z,v) form; Vl iff flag
#pragma unroll
                for (int rr = 0; rr < 2; ++rr) {
                    const long idx = (long)(r0 + rr * 8) * ldc + ccn;
                    float a0 = c[i][j][rr * 2 + 0], a1 = c[i][j][rr * 2 + 1];
                    float2 qv = *(const float2*)&Qp[idx];
                    float2 zv = *(const float2*)&Zp[idx];
                    float2 zn;
                    __nv_bfloat162 nh, nl;
                    {
                        float t = qv.x + zv.x - a0;
                        float z = fmaxf(t - THR_F, 0.f);
                        zn.x = z;
                        float vn = 2.f * z - t;
                        split_bf16(vn, nh.x, nl.x);
                    }
                    {
                        float t = qv.y + zv.y - a1;
                        float z = fmaxf(t - THR_F, 0.f);
                        zn.y = z;
                        float vn = 2.f * z - t;
                        split_bf16(vn, nh.y, nl.y);
                    }
                    *(float2*)&Zp[idx] = zn;
                    *(__nv_bfloat162*)&Vh[idx] = nh;
                    if (flag) *(__nv_bfloat162*)&Vl[idx] = nl;
                }
            }
        }
    }
}

// ---------------------------------------------------------------------------
// SIMT tiled SGEMM (setup path: G, NS, E -- full fp32 accuracy)
// ---------------------------------------------------------------------------
#define BM 128
#define BN 128
#define BKK 16

template<bool TA, bool TB>
__global__ void __launch_bounds__(256, 2)
gemm_kernel(const float* __restrict__ A, const float* __restrict__ B,
            float* __restrict__ C,
            int M, int N, int Kslice, int lda, int ldb, int ldc)
{
    __shared__ float As[BKK][BM + 4];
    __shared__ float Bs[BKK][BN + 4];

    const int tid = threadIdx.x;
    const int tx  = tid & 15;
    const int ty  = tid >> 4;
    const int m0  = blockIdx.y * BM;
    const int n0  = blockIdx.x * BN;

    const long k0 = (long)blockIdx.z * Kslice;
    if (TA) A += k0 * lda; else A += k0;
    if (TB) B += k0;       else B += k0 * ldb;
    C += (long)blockIdx.z * (long)M * ldc;

    float acc[8][8];
#pragma unroll
    for (int i = 0; i < 8; ++i)
#pragma unroll
        for (int j = 0; j < 8; ++j) acc[i][j] = 0.0f;

    const int nk = Kslice / BKK;
#pragma unroll 1
    for (int kt = 0; kt < nk; ++kt) {
        const int kbase = kt * BKK;
        if (!TA) {
#pragma unroll
            for (int p = 0; p < 2; ++p) {
                const int row = p * 64 + (tid >> 2);
                const int c4  = (tid & 3) * 4;
                float4 v = *(const float4*)&A[(long)(m0 + row) * lda + kbase + c4];
                As[c4 + 0][row] = v.x; As[c4 + 1][row] = v.y;
                As[c4 + 2][row] = v.z; As[c4 + 3][row] = v.w;
            }
        } else {
#pragma unroll
            for (int p = 0; p < 2; ++p) {
                const int kr = p * 8 + (tid >> 5);
                const int m4 = (tid & 31) * 4;
                float4 v = *(const float4*)&A[(long)(kbase + kr) * lda + m0 + m4];
                *(float4*)&As[kr][m4] = v;
            }
        }
        if (!TB) {
#pragma unroll
            for (int p = 0; p < 2; ++p) {
                const int kr  = p * 8 + (tid >> 5);
                const int nn4 = (tid & 31) * 4;
                const int gn  = n0 + nn4;
                float4 v = make_float4(0.f, 0.f, 0.f, 0.f);
                if (gn < N) v = *(const float4*)&B[(long)(kbase + kr) * ldb + gn];
                *(float4*)&Bs[kr][nn4] = v;
            }
        } else {
#pragma unroll
            for (int p = 0; p < 2; ++p) {
                const int nrow = p * 64 + (tid >> 2);
                const int c4   = (tid & 3) * 4;
                const int gn   = n0 + nrow;
                float4 v = make_float4(0.f, 0.f, 0.f, 0.f);
                if (gn < N) v = *(const float4*)&B[(long)gn * ldb + kbase + c4];
                Bs[c4 + 0][nrow] = v.x; Bs[c4 + 1][nrow] = v.y;
                Bs[c4 + 2][nrow] = v.z; Bs[c4 + 3][nrow] = v.w;
            }
        }
        __syncthreads();
#pragma unroll
        for (int kk = 0; kk < BKK; ++kk) {
            float a[8], b[8];
            *(float4*)&a[0] = *(const float4*)&As[kk][ty * 4];
            *(float4*)&a[4] = *(const float4*)&As[kk][64 + ty * 4];
            *(float4*)&b[0] = *(const float4*)&Bs[kk][tx * 4];
            *(float4*)&b[4] = *(const float4*)&Bs[kk][64 + tx * 4];
#pragma unroll
            for (int i = 0; i < 8; ++i)
#pragma unroll
                for (int j = 0; j < 8; ++j)
                    acc[i][j] = fmaf(a[i], b[j], acc[i][j]);
        }
        __syncthreads();
    }

    int rows[8];
#pragma unroll
    for (int i = 0; i < 8; ++i)
        rows[i] = m0 + (i < 4 ? ty * 4 + i : 64 + ty * 4 + (i - 4));

#pragma unroll
    for (int i = 0; i < 8; ++i) {
#pragma unroll
        for (int jg = 0; jg < 2; ++jg) {
            const int cn = n0 + jg * 64 + tx * 4;
            if (cn >= N) continue;
            const long idx = (long)rows[i] * ldc + cn;
            *(float4*)&C[idx] = make_float4(acc[i][jg * 4 + 0], acc[i][jg * 4 + 1],
                                            acc[i][jg * 4 + 2], acc[i][jg * 4 + 3]);
        }
    }
}

// ---------------------------------------------------------------------------
// Transpose + bf16 split: out[i*ldo + j] = split(src[j*lds + i]), i<R, j<C
// ---------------------------------------------------------------------------
__global__ void trans_split_kernel(const float* __restrict__ src, int lds,
                                   __nv_bfloat16* __restrict__ dh,
                                   __nv_bfloat16* __restrict__ dl,
                                   int ldo, int R, int C)
{
    __shared__ float t[32][33];
    const int i0 = blockIdx.x * 32;
    const int j0 = blockIdx.y * 32;
    const int tx = threadIdx.x, ty = threadIdx.y;
    for (int jj = ty; jj < 32; jj += 8) {
        const int j = j0 + jj, i = i0 + tx;
        float v = 0.f;
        if (j < C && i < R) v = src[(long)j * lds + i];
        t[jj][tx] = v;
    }
    __syncthreads();
    for (int ii = ty; ii < 32; ii += 8) {
        const int i = i0 + ii, j = j0 + tx;
        if (i < R && j < C) {
            __nv_bfloat16 h, l;
            split_bf16(t[tx][ii], h, l);
            dh[(long)i * ldo + j] = h;
            dl[(long)i * ldo + j] = l;
        }
    }
}

// ---------------------------------------------------------------------------
// Reductions / splits
// ---------------------------------------------------------------------------
__global__ void reduce_sum(const float4* __restrict__ P, float4* __restrict__ out,
                           int n4, int S)
{
    int i = blockIdx.x * blockDim.x + threadIdx.x;
    if (i >= n4) return;
    float4 s = P[i];
    for (int k = 1; k < S; ++k) {
        float4 t = P[(long)k * n4 + i];
        s.x += t.x; s.y += t.y; s.z += t.z; s.w += t.w;
    }
    out[i] = s;
}

__global__ void reduce_split_hl(const float2* __restrict__ P,
                                __nv_bfloat162* __restrict__ Wh,
                                __nv_bfloat162* __restrict__ Wl,
                                int n2, int S)
{
    int i = blockIdx.x * blockDim.x + threadIdx.x;
    if (i >= n2) return;
    float2 s = P[i];
    for (int k = 1; k < S; ++k) {
        float2 t = P[(long)k * n2 + i];
        s.x += t.x; s.y += t.y;
    }
    __nv_bfloat162 h, l;
    split_bf16(s.x, h.x, l.x);
    split_bf16(s.y, h.y, l.y);
    Wh[i] = h; Wl[i] = l;
}

__global__ void reduce_split_h(const float2* __restrict__ P,
                               __nv_bfloat162* __restrict__ Wh,
                               int n2, int S)
{
    int i = blockIdx.x * blockDim.x + threadIdx.x;
    if (i >= n2) return;
    float2 s = P[i];
    for (int k = 1; k < S; ++k) {
        float2 t = P[(long)k * n2 + i];
        s.x += t.x; s.y += t.y;
    }
    __nv_bfloat162 h;
    h.x = __float2bfloat16_rn(s.x);
    h.y = __float2bfloat16_rn(s.y);
    Wh[i] = h;
}

__global__ void split_mat_bf16(const float2* __restrict__ src,
                               __nv_bfloat162* __restrict__ hi,
                               __nv_bfloat162* __restrict__ lo, long n2)
{
    long i = (long)blockIdx.x * blockDim.x + threadIdx.x;
    if (i >= n2) return;
    float2 v = src[i];
    __nv_bfloat162 h, l;
    split_bf16(v.x, h.x, l.x);
    split_bf16(v.y, h.y, l.y);
    hi[i] = h; lo[i] = l;
}

__global__ void reduce_G(const float* __restrict__ P, float* __restrict__ G, int S)
{
    int i = blockIdx.x * blockDim.x + threadIdx.x;
    if (i >= DM * DM) return;
    float s = 0.f;
    for (int k = 0; k < S; ++k) s += P[(long)k * DM * DM + i];
    if ((i / DM) == (i % DM)) s += RHO_F;
    G[i] = s;
}

__global__ void reduce_ns(const float4* __restrict__ P, const float4* __restrict__ Xc,
                          float4* __restrict__ Xn, int n4, int S)
{
    int i = blockIdx.x * blockDim.x + threadIdx.x;
    if (i >= n4) return;
    float4 s = P[i];
    for (int k = 1; k < S; ++k) {
        float4 t = P[(long)k * n4 + i];
        s.x += t.x; s.y += t.y; s.z += t.z; s.w += t.w;
    }
    float4 x = Xc[i];
    Xn[i] = make_float4(2.f * x.x - s.x, 2.f * x.y - s.y,
                        2.f * x.z - s.z, 2.f * x.w - s.w);
}

__global__ void ninf_kernel(const float* __restrict__ G)
{
    __shared__ float sm[DM];
    const int i = threadIdx.x;
    float s = 0.f;
    for (int j = 0; j < DM; ++j) s += fabsf(G[(long)j * DM + i]);
    sm[i] = s;
    __syncthreads();
    for (int o = DM / 2; o > 0; o >>= 1) {
        if (i < o) sm[i] = fmaxf(sm[i], sm[i + o]);
        __syncthreads();
    }
    if (i == 0) g_ninf = sm[0];
}

__global__ void x0_kernel(float* __restrict__ X)
{
    int i = blockIdx.x * blockDim.x + threadIdx.x;
    if (i >= DM * DM) return;
    float c = 2.0f / (RHO_F + g_ninf);
    X[i] = ((i / DM) == (i % DM)) ? c : 0.0f;
}

// ---------------------------------------------------------------------------
// Row-normalize kernels
// ---------------------------------------------------------------------------
__device__ __forceinline__ float block_sum128(float v, float* red)
{
    for (int o = 16; o > 0; o >>= 1) v += __shfl_xor_sync(0xffffffff, v, o);
    if ((threadIdx.x & 31) == 0) red[threadIdx.x >> 5] = v;
    __syncthreads();
    float tot = red[0] + red[1] + red[2] + red[3];
    __syncthreads();
    return tot;
}

__global__ void norm_center_kernel(const float* __restrict__ img,
                                   const float* __restrict__ mean,
                                   float* __restrict__ out)
{
    __shared__ float red[4];
    const int r = blockIdx.x, t = threadIdx.x;
    float4 v = ((const float4*)(img + (long)r * DM))[t];
    float ss = v.x * v.x + v.y * v.y + v.z * v.z + v.w * v.w;
    float inv = 1.0f / fmaxf(sqrtf(block_sum128(ss, red)), EPS_F);
    float4 mv = ((const float4*)mean)[t];
    float4 c = make_float4(v.x * inv - mv.x, v.y * inv - mv.y,
                           v.z * inv - mv.z, v.w * inv - mv.w);
    float ss2 = c.x * c.x + c.y * c.y + c.z * c.z + c.w * c.w;
    float inv2 = 1.0f / fmaxf(sqrtf(block_sum128(ss2, red)), EPS_F);
    ((float4*)(out + (long)r * DM))[t] =
        make_float4(c.x * inv2, c.y * inv2, c.z * inv2, c.w * inv2);
}

__global__ void norm_rows_kernel(const float* __restrict__ in, float* __restrict__ out)
{
    __shared__ float red[4];
    const int r = blockIdx.x, t = threadIdx.x;
    float4 v = ((const float4*)(in + (long)r * DM))[t];
    float ss = v.x * v.x + v.y * v.y + v.z * v.z + v.w * v.w;
    float inv = 1.0f / fmaxf(sqrtf(block_sum128(ss, red)), EPS_F);
    ((float4*)(out + (long)r * DM))[t] =
        make_float4(v.x * inv, v.y * inv, v.z * inv, v.w * inv);
}

__global__ void final_norm_kernel(const float* __restrict__ rec,
                                  const float* __restrict__ mean,
                                  float* __restrict__ out)
{
    __shared__ float red[4];
    const int r = blockIdx.x, t = threadIdx.x;
    float4 v = ((const float4*)(rec + (long)r * DM))[t];
    float ss = v.x * v.x + v.y * v.y + v.z * v.z + v.w * v.w;
    float inv = 1.0f / fmaxf(sqrtf(block_sum128(ss, red)), EPS_F);
    float4 mv = ((const float4*)mean)[t];
    float4 c = make_float4(v.x * inv + mv.x, v.y * inv + mv.y,
                           v.z * inv + mv.z, v.w * inv + mv.w);
    float ss2 = c.x * c.x + c.y * c.y + c.z * c.z + c.w * c.w;
    float inv2 = 1.0f / fmaxf(sqrtf(block_sum128(ss2, red)), EPS_F);
    ((float4*)(out + (long)r * DM))[t] =
        make_float4(c.x * inv2, c.y * inv2, c.z * inv2, c.w * inv2);
}

// ---------------------------------------------------------------------------
// Host orchestration
// ---------------------------------------------------------------------------
extern "C" void kernel_launch(void* const* d_in, const int* in_sizes, int n_in,
                              void* d_out, int out_size)
{
    const float* dImg  = (const float*)d_in[0];
    const float* dTxt  = (const float*)d_in[1];
    const float* dMean = (const float*)d_in[2];
    const float* dDict = (const float*)d_in[3];
    float* outRecon = (float*)d_out;
    float* outTxt   = (float*)d_out + (long)BROWS * DM;

    float *Q, *Z, *E, *P, *W, *Y, *G, *XA, *XB, *T;
    __nv_bfloat16 *Vh, *Vl, *Th, *Tl, *Dh, *Dl, *DTh, *DTl, *Eh, *El,
                  *Wh, *Wl, *Yh, *Yl;
    cudaGetSymbolAddress((void**)&Q,   g_Q);
    cudaGetSymbolAddress((void**)&Z,   g_Z);
    cudaGetSymbolAddress((void**)&Vh,  g_Vh);
    cudaGetSymbolAddress((void**)&Vl,  g_Vl);
    cudaGetSymbolAddress((void**)&Th,  g_Th);
    cudaGetSymbolAddress((void**)&Tl,  g_Tl);
    cudaGetSymbolAddress((void**)&Dh,  g_Dh);
    cudaGetSymbolAddress((void**)&Dl,  g_Dl);
    cudaGetSymbolAddress((void**)&DTh, g_DTh);
    cudaGetSymbolAddress((void**)&DTl, g_DTl);
    cudaGetSymbolAddress((void**)&E,   g_E);
    cudaGetSymbolAddress((void**)&Eh,  g_Eh);
    cudaGetSymbolAddress((void**)&El,  g_El);
    cudaGetSymbolAddress((void**)&P,   g_P);
    cudaGetSymbolAddress((void**)&W,   g_W);
    cudaGetSymbolAddress((void**)&Wh,  g_Wh);
    cudaGetSymbolAddress((void**)&Wl,  g_Wl);
    cudaGetSymbolAddress((void**)&Y,   g_Y);
    cudaGetSymbolAddress((void**)&Yh,  g_Yh);
    cudaGetSymbolAddress((void**)&Yl,  g_Yl);
    cudaGetSymbolAddress((void**)&G,   g_G);
    cudaGetSymbolAddress((void**)&XA,  g_XA);
    cudaGetSymbolAddress((void**)&XB,  g_XB);
    cudaGetSymbolAddress((void**)&T,   g_T);

    cudaFuncSetAttribute(bmma_gemm<0, 3>, cudaFuncAttributeMaxDynamicSharedMemorySize, BSMEM);
    cudaFuncSetAttribute(bmma_gemm<1, 3>, cudaFuncAttributeMaxDynamicSharedMemorySize, BSMEM);
    cudaFuncSetAttribute(bmma_gemm<2, 3>, cudaFuncAttributeMaxDynamicSharedMemorySize, BSMEM);
    cudaFuncSetAttribute(bmma_gemm<0, 1>, cudaFuncAttributeMaxDynamicSharedMemorySize, BSMEM);
    cudaFuncSetAttribute(bmma_gemm<3, 1>, cudaFuncAttributeMaxDynamicSharedMemorySize, BSMEM);

    const int NT = (CDICT + BN - 1) / BN;   // 79 tiles over N=10000
    const int KSG = CDICT / GSLICES;        // 400 (G split-K, 25 slices)
    const int KSmma = CPAD / KSPLIT;        // 2560 (loop split-K, 4 slices)

    // 0) zero-pad-sensitive buffers
    cudaMemsetAsync(Q,   0, sizeof(float) * (size_t)BROWS * CPAD, 0);
    cudaMemsetAsync(DTh, 0, sizeof(__nv_bfloat16) * (size_t)DM * CPAD, 0);
    cudaMemsetAsync(DTl, 0, sizeof(__nv_bfloat16) * (size_t)DM * CPAD, 0);
    cudaMemsetAsync(Dh,  0, sizeof(__nv_bfloat16) * (size_t)CPAD * DM, 0);
    cudaMemsetAsync(Dl,  0, sizeof(__nv_bfloat16) * (size_t)CPAD * DM, 0);
    cudaMemsetAsync(E,   0, sizeof(float) * (size_t)DM * CPAD, 0);

    // 1) centered inputs + text output; splits of Y and D / D^T
    norm_center_kernel<<<BROWS, 128>>>(dImg, dMean, Y);
    norm_rows_kernel<<<BROWS, 128>>>(dTxt, outTxt);
    split_mat_bf16<<<(BROWS * DM / 2 + 255) / 256, 256>>>(
        (const float2*)Y, (__nv_bfloat162*)Yh, (__nv_bfloat162*)Yl, BROWS * DM / 2);
    split_mat_bf16<<<(int)(((long)CDICT * DM / 2 + 255) / 256), 256>>>(
        (const float2*)dDict, (__nv_bfloat162*)Dh, (__nv_bfloat162*)Dl,
        (long)CDICT * DM / 2);
    trans_split_kernel<<<dim3(16, 313), dim3(32, 8)>>>(
        dDict, DM, DTh, DTl, CPAD, DM, CDICT);

    // 2) Aty = Y @ D^T -> Q (bf16x3 tensor path; Q pads stay zero)
    bmma_gemm<0, 3><<<dim3(NT, 8, 1), 256, BSMEM>>>(
        Yh, Yl, DTh, DTl, Q, BROWS, CDICT, DM, DM, CPAD, CPAD,
        nullptr, nullptr, nullptr, nullptr, 0);

    // 3) G = D^T D + rho I (fp32 SIMT, 25-way split-K -> 400 CTAs)
    gemm_kernel<true, false><<<dim3(4, 4, GSLICES), 256>>>(
        dDict, dDict, P, DM, DM, KSG, DM, DM, DM);
    reduce_G<<<(DM * DM + 255) / 256, 256>>>(P, G, GSLICES);

    // 4) Newton-Schulz inverse (fp32 SIMT, 8-way split-K -> 128 CTAs)
    ninf_kernel<<<1, DM>>>(G);
    x0_kernel<<<(DM * DM + 255) / 256, 256>>>(XA);
    float* Xc = XA; float* Xn = XB;
    for (int t = 0; t < NS_ITERS; ++t) {
        gemm_kernel<false, false><<<dim3(4, 4, NSPLIT), 256>>>(
            G, Xc, P, DM, DM, DM / NSPLIT, DM, DM, DM);
        reduce_sum<<<(DM * DM / 4 + 255) / 256, 256>>>(
            (const float4*)P, (float4*)T, DM * DM / 4, NSPLIT);
        gemm_kernel<false, false><<<dim3(4, 4, NSPLIT), 256>>>(
            Xc, T, P, DM, DM, DM / NSPLIT, DM, DM, DM);
        reduce_ns<<<(DM * DM / 4 + 255) / 256, 256>>>(
            (const float4*)P, (const float4*)Xc, (float4*)Xn, DM * DM / 4, NSPLIT);
        float* tmp = Xc; Xc = Xn; Xn = tmp;
    }

    // 5) E = G^{-1} @ D^T (fp32 SIMT; ld = CPAD, pads zero) + bf16 split
    gemm_kernel<false, true><<<dim3(NT, 4, 1), 256>>>(
        Xc, dDict, E, DM, CDICT, DM, DM, DM, CPAD);
    split_mat_bf16<<<(int)(((long)DM * CPAD / 2 + 255) / 256), 256>>>(
        (const float2*)E, (__nv_bfloat162*)Eh, (__nv_bfloat162*)El,
        (long)DM * CPAD / 2);

    // 6) q = (Aty - (Aty @ D) @ E) / rho  (bf16x3 tensor path, in place on Q)
    split_mat_bf16<<<(int)(((long)BROWS * CPAD / 2 + 255) / 256), 256>>>(
        (const float2*)Q, (__nv_bfloat162*)Th, (__nv_bfloat162*)Tl,
        (long)BROWS * CPAD / 2);
    bmma_gemm<0, 3><<<dim3(4, 8, KSPLIT), 256, BSMEM>>>(
        Th, Tl, Dh, Dl, P, BROWS, DM, KSmma, CPAD, DM, DM,
        nullptr, nullptr, nullptr, nullptr, 0);
    reduce_split_hl<<<(BROWS * DM / 2 + 255) / 256, 256>>>(
        (const float2*)P, (__nv_bfloat162*)Wh, (__nv_bfloat162*)Wl,
        BROWS * DM / 2, KSPLIT);
    bmma_gemm<1, 3><<<dim3(NT, 8, 1), 256, BSMEM>>>(
        Wh, Wl, Eh, El, Q, BROWS, CDICT, DM, DM, CPAD, CPAD,
        Q, nullptr, nullptr, nullptr, 0);

    // 7) ADMM loop, (z, v) state form: t = q + z - (vD)E;
    //    z' = max(t - thr, 0); v' = 2z' - t.  u is never materialized.
    cudaMemsetAsync(Vh, 0, sizeof(__nv_bfloat16) * (size_t)BROWS * CPAD, 0);
    cudaMemsetAsync(Vl, 0, sizeof(__nv_bfloat16) * (size_t)BROWS * CPAD, 0);
    cudaMemsetAsync(Z,  0, sizeof(float) * (size_t)BROWS * CPAD, 0);
    for (int it = 0; it < ADMM_ITERS; ++it) {
        if (it < CHEAP_ITERS) {
            const int wl = (it == CHEAP_ITERS - 1) ? 1 : 0;
            bmma_gemm<0, 1><<<dim3(4, 8, KSPLIT), 256, BSMEM>>>(
                Vh, nullptr, Dh, nullptr, P, BROWS, DM, KSmma, CPAD, DM, DM,
                nullptr, nullptr, nullptr, nullptr, 0);
            reduce_split_h<<<(BROWS * DM / 2 + 255) / 256, 256>>>(
                (const float2*)P, (__nv_bfloat162*)Wh, BROWS * DM / 2, KSPLIT);
            bmma_gemm<3, 1><<<dim3(NT, 8, 1), 256, BSMEM>>>(
                Wh, nullptr, Eh, nullptr, nullptr, BROWS, CDICT, DM, DM, CPAD, CPAD,
                Q, Z, Vh, Vl, wl);
        } else {
            const int last = (it == ADMM_ITERS - 1) ? 1 : 0;
            bmma_gemm<0, 3><<<dim3(4, 8, KSPLIT), 256, BSMEM>>>(
                Vh, Vl, Dh, Dl, P, BROWS, DM, KSmma, CPAD, DM, DM,
                nullptr, nullptr, nullptr, nullptr, 0);
            reduce_split_hl<<<(BROWS * DM / 2 + 255) / 256, 256>>>(
                (const float2*)P, (__nv_bfloat162*)Wh, (__nv_bfloat162*)Wl,
                BROWS * DM / 2, KSPLIT);
            bmma_gemm<2, 3><<<dim3(NT, 8, 1), 256, BSMEM>>>(
                Wh, Wl, Eh, El, nullptr, BROWS, CDICT, DM, DM, CPAD, CPAD,
                Q, Z, Vh, Vl, last);
        }
    }

    // 8) recon = normalize(normalize(z @ D) + mean)   (z in Vh/Vl; accurate)
    bmma_gemm<0, 3><<<dim3(4, 8, KSPLIT), 256, BSMEM>>>(
        Vh, Vl, Dh, Dl, P, BROWS, DM, KSmma, CPAD, DM, DM,
        nullptr, nullptr, nullptr, nullptr, 0);
    reduce_sum<<<(BROWS * DM / 4 + 255) / 256, 256>>>(
        (const float4*)P, (float4*)W, BROWS * DM / 4, KSPLIT);
    final_norm_kernel<<<BROWS, 128>>>(W, dMean, outRecon);
}

// round 15
// speedup vs baseline: 1.2726x; 1.0382x over previous
#include <cuda_runtime.h>
#include <cuda_bf16.h>
#include <math.h>
#include <stdint.h>

// ---------------------------------------------------------------------------
// Problem constants
// ---------------------------------------------------------------------------
#define BROWS 1024      // batch
#define CDICT 10000     // dictionary atoms
#define CPAD  10240     // padded dict dim: divisible by 128
#define DM    512       // embedding dim
#define RHO_F 5.0f
#define THR_F 0.002f    // lam / rho
#define EPS_F 1e-12f
#define ADMM_ITERS 100
#define CHEAP_ITERS 90  // 1-product bf16 iters; remainder 3-product polish
#define NS_ITERS 8
#define KSPLIT 4        // loop split-K: 128 CTAs <= 148 SMs (balanced)
#define GSLICES 25      // G split-K (Kslice=400, 400 CTAs)
#define NSPLIT 8        // NS split-K (Kslice=64, 128 CTAs)

// ---------------------------------------------------------------------------
// Scratch (static device globals -- no cudaMalloc allowed)
// ---------------------------------------------------------------------------
__device__ float          g_Q  [(size_t)BROWS * CPAD];  // Aty, then q (ld=CPAD)
__device__ float          g_Z  [(size_t)BROWS * CPAD];  // z state (fp32)
__device__ __nv_bfloat16  g_Vh [(size_t)BROWS * CPAD];  // bf16-hi of v
__device__ __nv_bfloat16  g_Vl [(size_t)BROWS * CPAD];  // bf16-lo of v
__device__ __nv_bfloat16  g_Th [(size_t)BROWS * CPAD];  // Aty split hi (setup)
__device__ __nv_bfloat16  g_Tl [(size_t)BROWS * CPAD];  // Aty split lo (setup)
__device__ __nv_bfloat16  g_Dh [(size_t)CPAD * DM];     // dict hi [CPAD x 512]
__device__ __nv_bfloat16  g_Dl [(size_t)CPAD * DM];
__device__ __nv_bfloat16  g_DTh[(size_t)DM * CPAD];     // D^T hi [512 x CPAD]
__device__ __nv_bfloat16  g_DTl[(size_t)DM * CPAD];
__device__ float          g_E  [(size_t)DM * CPAD];     // E = G^{-1} D^T (fp32)
__device__ __nv_bfloat16  g_Eh [(size_t)DM * CPAD];
__device__ __nv_bfloat16  g_El [(size_t)DM * CPAD];
__device__ float          g_P  [(size_t)GSLICES * DM * DM]; // split-K partials
__device__ float          g_W  [(size_t)BROWS * DM];
__device__ __nv_bfloat16  g_Wh [(size_t)BROWS * DM];
__device__ __nv_bfloat16  g_Wl [(size_t)BROWS * DM];
__device__ float          g_Y  [(size_t)BROWS * DM];
__device__ __nv_bfloat16  g_Yh [(size_t)BROWS * DM];
__device__ __nv_bfloat16  g_Yl [(size_t)BROWS * DM];
__device__ float g_G [DM * DM];
__device__ float g_XA[DM * DM];
__device__ float g_XB[DM * DM];
__device__ float g_T [DM * DM];
__device__ float g_ninf;

// ---------------------------------------------------------------------------
// helpers
// ---------------------------------------------------------------------------
__device__ __forceinline__ void split_bf16(float v, __nv_bfloat16& h, __nv_bfloat16& l)
{
    h = __float2bfloat16_rn(v);
    l = __float2bfloat16_rn(v - __bfloat162float(h));
}

__device__ __forceinline__ void mma16(float* c, const unsigned* a,
                                      unsigned b0, unsigned b1)
{
    asm volatile(
        "mma.sync.aligned.m16n8k16.row.col.f32.bf16.bf16.f32 "
        "{%0,%1,%2,%3}, {%4,%5,%6,%7}, {%8,%9}, {%0,%1,%2,%3};"
        : "+f"(c[0]), "+f"(c[1]), "+f"(c[2]), "+f"(c[3])
        : "r"(a[0]), "r"(a[1]), "r"(a[2]), "r"(a[3]), "r"(b0), "r"(b1));
}

__device__ __forceinline__ void ldsm4(unsigned* r, uint32_t a)
{
    asm volatile("ldmatrix.sync.aligned.m8n8.x4.shared.b16 {%0,%1,%2,%3}, [%4];"
                 : "=r"(r[0]), "=r"(r[1]), "=r"(r[2]), "=r"(r[3]) : "r"(a));
}

__device__ __forceinline__ void ldsm4t(unsigned* r, uint32_t a)
{
    asm volatile("ldmatrix.sync.aligned.m8n8.x4.trans.shared.b16 {%0,%1,%2,%3}, [%4];"
                 : "=r"(r[0]), "=r"(r[1]), "=r"(r[2]), "=r"(r[3]) : "r"(a));
}

__device__ __forceinline__ void cp16(uint32_t s, const void* g)
{
    asm volatile("cp.async.cg.shared.global [%0], [%1], 16;"
                 :: "r"(s), "l"(g) : "memory");
}

// ---------------------------------------------------------------------------
// bf16 MMA GEMM, templated on product count and epilogue:
//   PROD==3: acc = Ah*Bh + Ah*Bl + Al*Bh       PROD==1: acc = Ah*Bh
// EPI 0: plain partial store at C + z*M*ldc (split-K, external reduce)
// EPI 1: q = (Qp - acc)/rho -> C (fp32)                              [setup]
// EPI 2: ADMM (z,v)-form, polish: t=Q+Z-acc; z'=max(t-thr,0); Z=z';
//        v' = flag ? z' : 2z'-t; split -> Vh, Vl
// EPI 3: ADMM (z,v)-form, cheap: same math; writes Vh; Vl iff flag
// BM=BN=128, BK=32, 256 thr, 8 warps (32x64 warp tile), 2-stage cp.async,
// ldmatrix fragments (conflict-free strides 40 / 136 bf16).
// ---------------------------------------------------------------------------
#define BSTG  37888
#define BSMEM (2 * BSTG)

template<int EPI, int PROD>
__global__ void __launch_bounds__(256, 2)
bmma_gemm(const __nv_bfloat16* __restrict__ Ah, const __nv_bfloat16* __restrict__ Al,
          const __nv_bfloat16* __restrict__ Bh, const __nv_bfloat16* __restrict__ Bl,
          float* __restrict__ C, int M, int N, int Kslice,
          int lda, int ldb, int ldc,
          const float* __restrict__ Qp, float* __restrict__ Zp,
          __nv_bfloat16* __restrict__ Vh, __nv_bfloat16* __restrict__ Vl,
          int flag)
{
    extern __shared__ char smd[];
    const int tid  = threadIdx.x;
    const int lane = tid & 31, wid = tid >> 5;
    const int wm = (wid & 3) * 32;
    const int wn = (wid >> 2) * 64;
    const int m0 = blockIdx.y * 128, n0 = blockIdx.x * 128;
    const long k0 = (long)blockIdx.z * Kslice;
    const int nk = Kslice >> 5;

    const int aRow = wm + ((lane >> 3) & 1) * 8 + (lane & 7);
    const int aKof = (lane >> 4) * 8;
    const int bRow = ((lane >> 3) & 1) * 8 + (lane & 7);
    const int bNof = (lane >> 4) * 8;

    float c[2][8][4];
#pragma unroll
    for (int i = 0; i < 2; ++i)
#pragma unroll
        for (int j = 0; j < 8; ++j)
#pragma unroll
            for (int q = 0; q < 4; ++q) c[i][j][q] = 0.0f;

    auto load_tile = [&](int kt, int buf) {
        char* base = smd + buf * BSTG;
        const int kb = kt * 32;
#pragma unroll
        for (int cc = 0; cc < 2; ++cc) {        // A: 128 rows x 4 chunks (8 bf16)
            int ch  = tid * 2 + cc;
            int row = ch >> 2, kc = (ch & 3) * 8;
            uint32_t so = (uint32_t)__cvta_generic_to_shared(
                base + (row * 40 + kc) * 2);
            const long go = (long)(m0 + row) * lda + k0 + kb + kc;
            cp16(so, Ah + go);
            if (PROD == 3) cp16(so + 10240, Al + go);
        }
#pragma unroll
        for (int cc = 0; cc < 2; ++cc) {        // B: 32 rows x 16 chunks
            int ch  = tid * 2 + cc;
            int row = ch >> 4, nc = (ch & 15) * 8;
            uint32_t so = (uint32_t)__cvta_generic_to_shared(
                base + 20480 + (row * 136 + nc) * 2);
            const long go = (long)(k0 + kb + row) * ldb + n0 + nc;
            cp16(so, Bh + go);
            if (PROD == 3) cp16(so + 8704, Bl + go);
        }
    };

    load_tile(0, 0);
    asm volatile("cp.async.commit_group;" ::: "memory");

    for (int kt = 0; kt < nk; ++kt) {
        asm volatile("cp.async.wait_group 0;" ::: "memory");
        __syncthreads();
        if (kt + 1 < nk) load_tile(kt + 1, (kt + 1) & 1);
        asm volatile("cp.async.commit_group;" ::: "memory");

        const uint32_t sb = (uint32_t)__cvta_generic_to_shared(smd + (kt & 1) * BSTG);

#pragma unroll
        for (int ks = 0; ks < 2; ++ks) {
            unsigned ah[2][4], al[2][4];
#pragma unroll
            for (int i = 0; i < 2; ++i) {
                uint32_t ad = sb + ((aRow + i * 16) * 40 + ks * 16 + aKof) * 2;
                ldsm4(ah[i], ad);
                if (PROD == 3) ldsm4(al[i], ad + 10240);
            }
#pragma unroll
            for (int ng = 0; ng < 4; ++ng) {
                unsigned bh[4], bl[4];
                uint32_t bd = sb + 20480 +
                              ((bRow + ks * 16) * 136 + wn + ng * 16 + bNof) * 2;
                ldsm4t(bh, bd);
                if (PROD == 3) ldsm4t(bl, bd + 8704);
#pragma unroll
                for (int jj = 0; jj < 2; ++jj) {
                    const int j = ng * 2 + jj;
#pragma unroll
                    for (int i = 0; i < 2; ++i) {
                        mma16(c[i][j], ah[i], bh[jj * 2], bh[jj * 2 + 1]);
                        if (PROD == 3) {
                            mma16(c[i][j], ah[i], bl[jj * 2], bl[jj * 2 + 1]);
                            mma16(c[i][j], al[i], bh[jj * 2], bh[jj * 2 + 1]);
                        }
                    }
                }
            }
        }
    }

    // ---- epilogue ----
    const int gq = lane >> 2, tq = lane & 3;
#pragma unroll
    for (int i = 0; i < 2; ++i) {
        const int r0 = m0 + wm + i * 16 + gq;
#pragma unroll
        for (int j = 0; j < 8; ++j) {
            const int ccn = n0 + wn + j * 8 + 2 * tq;
            if (ccn >= N) continue;
            if (EPI == 0) {
                float* Cz = C + (long)blockIdx.z * (long)M * ldc;
                *(float2*)&Cz[(long)r0 * ldc + ccn] =
                    make_float2(c[i][j][0], c[i][j][1]);
                *(float2*)&Cz[(long)(r0 + 8) * ldc + ccn] =
                    make_float2(c[i][j][2], c[i][j][3]);
            } else if (EPI == 1) {
#pragma unroll
                for (int rr = 0; rr < 2; ++rr) {
                    const long idx = (long)(r0 + rr * 8) * ldc + ccn;
                    const float ir = 1.0f / RHO_F;
                    float2 qv = *(const float2*)&Qp[idx];
                    *(float2*)&C[idx] = make_float2(
                        (qv.x - c[i][j][rr * 2 + 0]) * ir,
                        (qv.y - c[i][j][rr * 2 + 1]) * ir);
                }
            } else if (EPI == 2) {   // polish ADMM, (z,v) form
#pragma unroll
                for (int rr = 0; rr < 2; ++rr) {
                    const long idx = (long)(r0 + rr * 8) * ldc + ccn;
                    float a0 = c[i][j][rr * 2 + 0], a1 = c[i][j][rr * 2 + 1];
                    float2 qv = *(const float2*)&Qp[idx];
                    float2 zv = *(const float2*)&Zp[idx];
                    float2 zn;
                    __nv_bfloat162 nh, nl;
                    {
                        float t = qv.x + zv.x - a0;
                        float z = fmaxf(t - THR_F, 0.f);
                        zn.x = z;
                        float vn = flag ? z : (2.f * z - t);
                        split_bf16(vn, nh.x, nl.x);
                    }
                    {
                        float t = qv.y + zv.y - a1;
                        float z = fmaxf(t - THR_F, 0.f);
                        zn.y = z;
                        float vn = flag ? z : (2.f * z - t);
                        split_bf16(vn, nh.y, nl.y);
                    }
                    *(float2*)&Zp[idx] = zn;
                    *(__nv_bfloat162*)&Vh[idx] = nh;
                    *(__nv_bfloat162*)&Vl[idx] = nl;
                }
            } else if (EPI == 3) {   // cheap ADMM, (z,v) form; Vl iff flag
#pragma unroll
                for (int rr = 0; rr < 2; ++rr) {
                    const long idx = (long)(r0 + rr * 8) * ldc + ccn;
                    float a0 = c[i][j][rr * 2 + 0], a1 = c[i][j][rr * 2 + 1];
                    float2 qv = *(const float2*)&Qp[idx];
                    float2 zv = *(const float2*)&Zp[idx];
                    float2 zn;
                    __nv_bfloat162 nh, nl;
                    {
                        float t = qv.x + zv.x - a0;
                        float z = fmaxf(t - THR_F, 0.f);
                        zn.x = z;
                        float vn = 2.f * z - t;
                        split_bf16(vn, nh.x, nl.x);
                    }
                    {
                        float t = qv.y + zv.y - a1;
                        float z = fmaxf(t - THR_F, 0.f);
                        zn.y = z;
                        float vn = 2.f * z - t;
                        split_bf16(vn, nh.y, nl.y);
                    }
                    *(float2*)&Zp[idx] = zn;
                    *(__nv_bfloat162*)&Vh[idx] = nh;
                    if (flag) *(__nv_bfloat162*)&Vl[idx] = nl;
                }
            }
        }
    }
}

// ---------------------------------------------------------------------------
// SIMT tiled SGEMM (setup path: G, NS -- full fp32 accuracy)
// ---------------------------------------------------------------------------
#define BM 128
#define BN 128
#define BKK 16

template<bool TA, bool TB>
__global__ void __launch_bounds__(256, 2)
gemm_kernel(const float* __restrict__ A, const float* __restrict__ B,
            float* __restrict__ C,
            int M, int N, int Kslice, int lda, int ldb, int ldc)
{
    __shared__ float As[BKK][BM + 4];
    __shared__ float Bs[BKK][BN + 4];

    const int tid = threadIdx.x;
    const int tx  = tid & 15;
    const int ty  = tid >> 4;
    const int m0  = blockIdx.y * BM;
    const int n0  = blockIdx.x * BN;

    const long k0 = (long)blockIdx.z * Kslice;
    if (TA) A += k0 * lda; else A += k0;
    if (TB) B += k0;       else B += k0 * ldb;
    C += (long)blockIdx.z * (long)M * ldc;

    float acc[8][8];
#pragma unroll
    for (int i = 0; i < 8; ++i)
#pragma unroll
        for (int j = 0; j < 8; ++j) acc[i][j] = 0.0f;

    const int nk = Kslice / BKK;
#pragma unroll 1
    for (int kt = 0; kt < nk; ++kt) {
        const int kbase = kt * BKK;
        if (!TA) {
#pragma unroll
            for (int p = 0; p < 2; ++p) {
                const int row = p * 64 + (tid >> 2);
                const int c4  = (tid & 3) * 4;
                float4 v = *(const float4*)&A[(long)(m0 + row) * lda + kbase + c4];
                As[c4 + 0][row] = v.x; As[c4 + 1][row] = v.y;
                As[c4 + 2][row] = v.z; As[c4 + 3][row] = v.w;
            }
        } else {
#pragma unroll
            for (int p = 0; p < 2; ++p) {
                const int kr = p * 8 + (tid >> 5);
                const int m4 = (tid & 31) * 4;
                float4 v = *(const float4*)&A[(long)(kbase + kr) * lda + m0 + m4];
                *(float4*)&As[kr][m4] = v;
            }
        }
        if (!TB) {
#pragma unroll
            for (int p = 0; p < 2; ++p) {
                const int kr  = p * 8 + (tid >> 5);
                const int nn4 = (tid & 31) * 4;
                const int gn  = n0 + nn4;
                float4 v = make_float4(0.f, 0.f, 0.f, 0.f);
                if (gn < N) v = *(const float4*)&B[(long)(kbase + kr) * ldb + gn];
                *(float4*)&Bs[kr][nn4] = v;
            }
        } else {
#pragma unroll
            for (int p = 0; p < 2; ++p) {
                const int nrow = p * 64 + (tid >> 2);
                const int c4   = (tid & 3) * 4;
                const int gn   = n0 + nrow;
                float4 v = make_float4(0.f, 0.f, 0.f, 0.f);
                if (gn < N) v = *(const float4*)&B[(long)gn * ldb + kbase + c4];
                Bs[c4 + 0][nrow] = v.x; Bs[c4 + 1][nrow] = v.y;
                Bs[c4 + 2][nrow] = v.z; Bs[c4 + 3][nrow] = v.w;
            }
        }
        __syncthreads();
#pragma unroll
        for (int kk = 0; kk < BKK; ++kk) {
            float a[8], b[8];
            *(float4*)&a[0] = *(const float4*)&As[kk][ty * 4];
            *(float4*)&a[4] = *(const float4*)&As[kk][64 + ty * 4];
            *(float4*)&b[0] = *(const float4*)&Bs[kk][tx * 4];
            *(float4*)&b[4] = *(const float4*)&Bs[kk][64 + tx * 4];
#pragma unroll
            for (int i = 0; i < 8; ++i)
#pragma unroll
                for (int j = 0; j < 8; ++j)
                    acc[i][j] = fmaf(a[i], b[j], acc[i][j]);
        }
        __syncthreads();
    }

    int rows[8];
#pragma unroll
    for (int i = 0; i < 8; ++i)
        rows[i] = m0 + (i < 4 ? ty * 4 + i : 64 + ty * 4 + (i - 4));

#pragma unroll
    for (int i = 0; i < 8; ++i) {
#pragma unroll
        for (int jg = 0; jg < 2; ++jg) {
            const int cn = n0 + jg * 64 + tx * 4;
            if (cn >= N) continue;
            const long idx = (long)rows[i] * ldc + cn;
            *(float4*)&C[idx] = make_float4(acc[i][jg * 4 + 0], acc[i][jg * 4 + 1],
                                            acc[i][jg * 4 + 2], acc[i][jg * 4 + 3]);
        }
    }
}

// ---------------------------------------------------------------------------
// Transpose + bf16 split: out[i*ldo + j] = split(src[j*lds + i]), i<R, j<C
// ---------------------------------------------------------------------------
__global__ void trans_split_kernel(const float* __restrict__ src, int lds,
                                   __nv_bfloat16* __restrict__ dh,
                                   __nv_bfloat16* __restrict__ dl,
                                   int ldo, int R, int C)
{
    __shared__ float t[32][33];
    const int i0 = blockIdx.x * 32;
    const int j0 = blockIdx.y * 32;
    const int tx = threadIdx.x, ty = threadIdx.y;
    for (int jj = ty; jj < 32; jj += 8) {
        const int j = j0 + jj, i = i0 + tx;
        float v = 0.f;
        if (j < C && i < R) v = src[(long)j * lds + i];
        t[jj][tx] = v;
    }
    __syncthreads();
    for (int ii = ty; ii < 32; ii += 8) {
        const int i = i0 + ii, j = j0 + tx;
        if (i < R && j < C) {
            __nv_bfloat16 h, l;
            split_bf16(t[tx][ii], h, l);
            dh[(long)i * ldo + j] = h;
            dl[(long)i * ldo + j] = l;
        }
    }
}

// ---------------------------------------------------------------------------
// Reductions / splits
// ---------------------------------------------------------------------------
__global__ void reduce_sum(const float4* __restrict__ P, float4* __restrict__ out,
                           int n4, int S)
{
    int i = blockIdx.x * blockDim.x + threadIdx.x;
    if (i >= n4) return;
    float4 s = P[i];
    for (int k = 1; k < S; ++k) {
        float4 t = P[(long)k * n4 + i];
        s.x += t.x; s.y += t.y; s.z += t.z; s.w += t.w;
    }
    out[i] = s;
}

__global__ void reduce_split_hl(const float2* __restrict__ P,
                                __nv_bfloat162* __restrict__ Wh,
                                __nv_bfloat162* __restrict__ Wl,
                                int n2, int S)
{
    int i = blockIdx.x * blockDim.x + threadIdx.x;
    if (i >= n2) return;
    float2 s = P[i];
    for (int k = 1; k < S; ++k) {
        float2 t = P[(long)k * n2 + i];
        s.x += t.x; s.y += t.y;
    }
    __nv_bfloat162 h, l;
    split_bf16(s.x, h.x, l.x);
    split_bf16(s.y, h.y, l.y);
    Wh[i] = h; Wl[i] = l;
}

__global__ void reduce_split_h(const float2* __restrict__ P,
                               __nv_bfloat162* __restrict__ Wh,
                               int n2, int S)
{
    int i = blockIdx.x * blockDim.x + threadIdx.x;
    if (i >= n2) return;
    float2 s = P[i];
    for (int k = 1; k < S; ++k) {
        float2 t = P[(long)k * n2 + i];
        s.x += t.x; s.y += t.y;
    }
    __nv_bfloat162 h;
    h.x = __float2bfloat16_rn(s.x);
    h.y = __float2bfloat16_rn(s.y);
    Wh[i] = h;
}

__global__ void split_mat_bf16(const float2* __restrict__ src,
                               __nv_bfloat162* __restrict__ hi,
                               __nv_bfloat162* __restrict__ lo, long n2)
{
    long i = (long)blockIdx.x * blockDim.x + threadIdx.x;
    if (i >= n2) return;
    float2 v = src[i];
    __nv_bfloat162 h, l;
    split_bf16(v.x, h.x, l.x);
    split_bf16(v.y, h.y, l.y);
    hi[i] = h; lo[i] = l;
}

__global__ void reduce_G(const float* __restrict__ P, float* __restrict__ G, int S)
{
    int i = blockIdx.x * blockDim.x + threadIdx.x;
    if (i >= DM * DM) return;
    float s = 0.f;
    for (int k = 0; k < S; ++k) s += P[(long)k * DM * DM + i];
    if ((i / DM) == (i % DM)) s += RHO_F;
    G[i] = s;
}

__global__ void reduce_ns(const float4* __restrict__ P, const float4* __restrict__ Xc,
                          float4* __restrict__ Xn, int n4, int S)
{
    int i = blockIdx.x * blockDim.x + threadIdx.x;
    if (i >= n4) return;
    float4 s = P[i];
    for (int k = 1; k < S; ++k) {
        float4 t = P[(long)k * n4 + i];
        s.x += t.x; s.y += t.y; s.z += t.z; s.w += t.w;
    }
    float4 x = Xc[i];
    Xn[i] = make_float4(2.f * x.x - s.x, 2.f * x.y - s.y,
                        2.f * x.z - s.z, 2.f * x.w - s.w);
}

__global__ void ninf_kernel(const float* __restrict__ G)
{
    __shared__ float sm[DM];
    const int i = threadIdx.x;
    float s = 0.f;
    for (int j = 0; j < DM; ++j) s += fabsf(G[(long)j * DM + i]);
    sm[i] = s;
    __syncthreads();
    for (int o = DM / 2; o > 0; o >>= 1) {
        if (i < o) sm[i] = fmaxf(sm[i], sm[i + o]);
        __syncthreads();
    }
    if (i == 0) g_ninf = sm[0];
}

__global__ void x0_kernel(float* __restrict__ X)
{
    int i = blockIdx.x * blockDim.x + threadIdx.x;
    if (i >= DM * DM) return;
    float c = 2.0f / (RHO_F + g_ninf);
    X[i] = ((i / DM) == (i % DM)) ? c : 0.0f;
}

// ---------------------------------------------------------------------------
// Row-normalize kernels
// ---------------------------------------------------------------------------
__device__ __forceinline__ float block_sum128(float v, float* red)
{
    for (int o = 16; o > 0; o >>= 1) v += __shfl_xor_sync(0xffffffff, v, o);
    if ((threadIdx.x & 31) == 0) red[threadIdx.x >> 5] = v;
    __syncthreads();
    float tot = red[0] + red[1] + red[2] + red[3];
    __syncthreads();
    return tot;
}

__global__ void norm_center_kernel(const float* __restrict__ img,
                                   const float* __restrict__ mean,
                                   float* __restrict__ out)
{
    __shared__ float red[4];
    const int r = blockIdx.x, t = threadIdx.x;
    float4 v = ((const float4*)(img + (long)r * DM))[t];
    float ss = v.x * v.x + v.y * v.y + v.z * v.z + v.w * v.w;
    float inv = 1.0f / fmaxf(sqrtf(block_sum128(ss, red)), EPS_F);
    float4 mv = ((const float4*)mean)[t];
    float4 c = make_float4(v.x * inv - mv.x, v.y * inv - mv.y,
                           v.z * inv - mv.z, v.w * inv - mv.w);
    float ss2 = c.x * c.x + c.y * c.y + c.z * c.z + c.w * c.w;
    float inv2 = 1.0f / fmaxf(sqrtf(block_sum128(ss2, red)), EPS_F);
    ((float4*)(out + (long)r * DM))[t] =
        make_float4(c.x * inv2, c.y * inv2, c.z * inv2, c.w * inv2);
}

__global__ void norm_rows_kernel(const float* __restrict__ in, float* __restrict__ out)
{
    __shared__ float red[4];
    const int r = blockIdx.x, t = threadIdx.x;
    float4 v = ((const float4*)(in + (long)r * DM))[t];
    float ss = v.x * v.x + v.y * v.y + v.z * v.z + v.w * v.w;
    float inv = 1.0f / fmaxf(sqrtf(block_sum128(ss, red)), EPS_F);
    ((float4*)(out + (long)r * DM))[t] =
        make_float4(v.x * inv, v.y * inv, v.z * inv, v.w * inv);
}

__global__ void final_norm_kernel(const float* __restrict__ rec,
                                  const float* __restrict__ mean,
                                  float* __restrict__ out)
{
    __shared__ float red[4];
    const int r = blockIdx.x, t = threadIdx.x;
    float4 v = ((const float4*)(rec + (long)r * DM))[t];
    float ss = v.x * v.x + v.y * v.y + v.z * v.z + v.w * v.w;
    float inv = 1.0f / fmaxf(sqrtf(block_sum128(ss, red)), EPS_F);
    float4 mv = ((const float4*)mean)[t];
    float4 c = make_float4(v.x * inv + mv.x, v.y * inv + mv.y,
                           v.z * inv + mv.z, v.w * inv + mv.w);
    float ss2 = c.x * c.x + c.y * c.y + c.z * c.z + c.w * c.w;
    float inv2 = 1.0f / fmaxf(sqrtf(block_sum128(ss2, red)), EPS_F);
    ((float4*)(out + (long)r * DM))[t] =
        make_float4(c.x * inv2, c.y * inv2, c.z * inv2, c.w * inv2);
}

// ---------------------------------------------------------------------------
// Host orchestration
// ---------------------------------------------------------------------------
extern "C" void kernel_launch(void* const* d_in, const int* in_sizes, int n_in,
                              void* d_out, int out_size)
{
    const float* dImg  = (const float*)d_in[0];
    const float* dTxt  = (const float*)d_in[1];
    const float* dMean = (const float*)d_in[2];
    const float* dDict = (const float*)d_in[3];
    float* outRecon = (float*)d_out;
    float* outTxt   = (float*)d_out + (long)BROWS * DM;

    float *Q, *Z, *E, *P, *W, *Y, *G, *XA, *XB, *T;
    __nv_bfloat16 *Vh, *Vl, *Th, *Tl, *Dh, *Dl, *DTh, *DTl, *Eh, *El,
                  *Wh, *Wl, *Yh, *Yl;
    cudaGetSymbolAddress((void**)&Q,   g_Q);
    cudaGetSymbolAddress((void**)&Z,   g_Z);
    cudaGetSymbolAddress((void**)&Vh,  g_Vh);
    cudaGetSymbolAddress((void**)&Vl,  g_Vl);
    cudaGetSymbolAddress((void**)&Th,  g_Th);
    cudaGetSymbolAddress((void**)&Tl,  g_Tl);
    cudaGetSymbolAddress((void**)&Dh,  g_Dh);
    cudaGetSymbolAddress((void**)&Dl,  g_Dl);
    cudaGetSymbolAddress((void**)&DTh, g_DTh);
    cudaGetSymbolAddress((void**)&DTl, g_DTl);
    cudaGetSymbolAddress((void**)&E,   g_E);
    cudaGetSymbolAddress((void**)&Eh,  g_Eh);
    cudaGetSymbolAddress((void**)&El,  g_El);
    cudaGetSymbolAddress((void**)&P,   g_P);
    cudaGetSymbolAddress((void**)&W,   g_W);
    cudaGetSymbolAddress((void**)&Wh,  g_Wh);
    cudaGetSymbolAddress((void**)&Wl,  g_Wl);
    cudaGetSymbolAddress((void**)&Y,   g_Y);
    cudaGetSymbolAddress((void**)&Yh,  g_Yh);
    cudaGetSymbolAddress((void**)&Yl,  g_Yl);
    cudaGetSymbolAddress((void**)&G,   g_G);
    cudaGetSymbolAddress((void**)&XA,  g_XA);
    cudaGetSymbolAddress((void**)&XB,  g_XB);
    cudaGetSymbolAddress((void**)&T,   g_T);

    cudaFuncSetAttribute(bmma_gemm<0, 3>, cudaFuncAttributeMaxDynamicSharedMemorySize, BSMEM);
    cudaFuncSetAttribute(bmma_gemm<1, 3>, cudaFuncAttributeMaxDynamicSharedMemorySize, BSMEM);
    cudaFuncSetAttribute(bmma_gemm<2, 3>, cudaFuncAttributeMaxDynamicSharedMemorySize, BSMEM);
    cudaFuncSetAttribute(bmma_gemm<0, 1>, cudaFuncAttributeMaxDynamicSharedMemorySize, BSMEM);
    cudaFuncSetAttribute(bmma_gemm<3, 1>, cudaFuncAttributeMaxDynamicSharedMemorySize, BSMEM);

    const int NT = (CDICT + BN - 1) / BN;   // 79 tiles over N=10000
    const int KSG = CDICT / GSLICES;        // 400 (G split-K, 25 slices)
    const int KSmma = CPAD / KSPLIT;        // 2560 (loop split-K, 4 slices)

    // 0) zero-pad-sensitive buffers
    cudaMemsetAsync(Q,   0, sizeof(float) * (size_t)BROWS * CPAD, 0);
    cudaMemsetAsync(DTh, 0, sizeof(__nv_bfloat16) * (size_t)DM * CPAD, 0);
    cudaMemsetAsync(DTl, 0, sizeof(__nv_bfloat16) * (size_t)DM * CPAD, 0);
    cudaMemsetAsync(Dh,  0, sizeof(__nv_bfloat16) * (size_t)CPAD * DM, 0);
    cudaMemsetAsync(Dl,  0, sizeof(__nv_bfloat16) * (size_t)CPAD * DM, 0);
    cudaMemsetAsync(E,   0, sizeof(float) * (size_t)DM * CPAD, 0);

    // 1) centered inputs + text output; splits of Y and D / D^T
    norm_center_kernel<<<BROWS, 128>>>(dImg, dMean, Y);
    norm_rows_kernel<<<BROWS, 128>>>(dTxt, outTxt);
    split_mat_bf16<<<(BROWS * DM / 2 + 255) / 256, 256>>>(
        (const float2*)Y, (__nv_bfloat162*)Yh, (__nv_bfloat162*)Yl, BROWS * DM / 2);
    split_mat_bf16<<<(int)(((long)CDICT * DM / 2 + 255) / 256), 256>>>(
        (const float2*)dDict, (__nv_bfloat162*)Dh, (__nv_bfloat162*)Dl,
        (long)CDICT * DM / 2);
    trans_split_kernel<<<dim3(16, 313), dim3(32, 8)>>>(
        dDict, DM, DTh, DTl, CPAD, DM, CDICT);

    // 2) Aty = Y @ D^T -> Q (bf16x3 tensor path; Q pads stay zero)
    bmma_gemm<0, 3><<<dim3(NT, 8, 1), 256, BSMEM>>>(
        Yh, Yl, DTh, DTl, Q, BROWS, CDICT, DM, DM, CPAD, CPAD,
        nullptr, nullptr, nullptr, nullptr, 0);

    // 3) G = D^T D + rho I (fp32 SIMT, 25-way split-K -> 400 CTAs)
    gemm_kernel<true, false><<<dim3(4, 4, GSLICES), 256>>>(
        dDict, dDict, P, DM, DM, KSG, DM, DM, DM);
    reduce_G<<<(DM * DM + 255) / 256, 256>>>(P, G, GSLICES);

    // 4) Newton-Schulz inverse (fp32 SIMT, 8-way split-K -> 128 CTAs)
    ninf_kernel<<<1, DM>>>(G);
    x0_kernel<<<(DM * DM + 255) / 256, 256>>>(XA);
    float* Xc = XA; float* Xn = XB;
    for (int t = 0; t < NS_ITERS; ++t) {
        gemm_kernel<false, false><<<dim3(4, 4, NSPLIT), 256>>>(
            G, Xc, P, DM, DM, DM / NSPLIT, DM, DM, DM);
        reduce_sum<<<(DM * DM / 4 + 255) / 256, 256>>>(
            (const float4*)P, (float4*)T, DM * DM / 4, NSPLIT);
        gemm_kernel<false, false><<<dim3(4, 4, NSPLIT), 256>>>(
            Xc, T, P, DM, DM, DM / NSPLIT, DM, DM, DM);
        reduce_ns<<<(DM * DM / 4 + 255) / 256, 256>>>(
            (const float4*)P, (const float4*)Xc, (float4*)Xn, DM * DM / 4, NSPLIT);
        float* tmp = Xc; Xc = Xn; Xn = tmp;
    }

    // 5) E = G^{-1} @ D^T via bf16x3 tensor path (E only ever consumed as
    //    bf16 hi/lo, so the ~1e-5 bf16x3 error is below the split's own
    //    truncation).  Xc split into the currently-idle Wh/Wl buffers.
    split_mat_bf16<<<(DM * DM / 2 + 255) / 256, 256>>>(
        (const float2*)Xc, (__nv_bfloat162*)Wh, (__nv_bfloat162*)Wl, DM * DM / 2);
    bmma_gemm<0, 3><<<dim3(NT, 4, 1), 256, BSMEM>>>(
        Wh, Wl, DTh, DTl, E, DM, CDICT, DM, DM, CPAD, CPAD,
        nullptr, nullptr, nullptr, nullptr, 0);
    split_mat_bf16<<<(int)(((long)DM * CPAD / 2 + 255) / 256), 256>>>(
        (const float2*)E, (__nv_bfloat162*)Eh, (__nv_bfloat162*)El,
        (long)DM * CPAD / 2);

    // 6) q = (Aty - (Aty @ D) @ E) / rho  (bf16x3 tensor path, in place on Q)
    split_mat_bf16<<<(int)(((long)BROWS * CPAD / 2 + 255) / 256), 256>>>(
        (const float2*)Q, (__nv_bfloat162*)Th, (__nv_bfloat162*)Tl,
        (long)BROWS * CPAD / 2);
    bmma_gemm<0, 3><<<dim3(4, 8, KSPLIT), 256, BSMEM>>>(
        Th, Tl, Dh, Dl, P, BROWS, DM, KSmma, CPAD, DM, DM,
        nullptr, nullptr, nullptr, nullptr, 0);
    reduce_split_hl<<<(BROWS * DM / 2 + 255) / 256, 256>>>(
        (const float2*)P, (__nv_bfloat162*)Wh, (__nv_bfloat162*)Wl,
        BROWS * DM / 2, KSPLIT);
    bmma_gemm<1, 3><<<dim3(NT, 8, 1), 256, BSMEM>>>(
        Wh, Wl, Eh, El, Q, BROWS, CDICT, DM, DM, CPAD, CPAD,
        Q, nullptr, nullptr, nullptr, 0);

    // 7) ADMM loop, (z, v) state form: t = q + z - (vD)E;
    //    z' = max(t - thr, 0); v' = 2z' - t.  u is never materialized.
    cudaMemsetAsync(Vh, 0, sizeof(__nv_bfloat16) * (size_t)BROWS * CPAD, 0);
    cudaMemsetAsync(Vl, 0, sizeof(__nv_bfloat16) * (size_t)BROWS * CPAD, 0);
    cudaMemsetAsync(Z,  0, sizeof(float) * (size_t)BROWS * CPAD, 0);
    for (int it = 0; it < ADMM_ITERS; ++it) {
        if (it < CHEAP_ITERS) {
            const int wl = (it == CHEAP_ITERS - 1) ? 1 : 0;
            bmma_gemm<0, 1><<<dim3(4, 8, KSPLIT), 256, BSMEM>>>(
                Vh, nullptr, Dh, nullptr, P, BROWS, DM, KSmma, CPAD, DM, DM,
                nullptr, nullptr, nullptr, nullptr, 0);
            reduce_split_h<<<(BROWS * DM / 2 + 255) / 256, 256>>>(
                (const float2*)P, (__nv_bfloat162*)Wh, BROWS * DM / 2, KSPLIT);
            bmma_gemm<3, 1><<<dim3(NT, 8, 1), 256, BSMEM>>>(
                Wh, nullptr, Eh, nullptr, nullptr, BROWS, CDICT, DM, DM, CPAD, CPAD,
                Q, Z, Vh, Vl, wl);
        } else {
            const int last = (it == ADMM_ITERS - 1) ? 1 : 0;
            bmma_gemm<0, 3><<<dim3(4, 8, KSPLIT), 256, BSMEM>>>(
                Vh, Vl, Dh, Dl, P, BROWS, DM, KSmma, CPAD, DM, DM,
                nullptr, nullptr, nullptr, nullptr, 0);
            reduce_split_hl<<<(BROWS * DM / 2 + 255) / 256, 256>>>(
                (const float2*)P, (__nv_bfloat162*)Wh, (__nv_bfloat162*)Wl,
                BROWS * DM / 2, KSPLIT);
            bmma_gemm<2, 3><<<dim3(NT, 8, 1), 256, BSMEM>>>(
                Wh, Wl, Eh, El, nullptr, BROWS, CDICT, DM, DM, CPAD, CPAD,
                Q, Z, Vh, Vl, last);
        }
    }

    // 8) recon = normalize(normalize(z @ D) + mean)   (z in Vh/Vl; accurate)
    bmma_gemm<0, 3><<<dim3(4, 8, KSPLIT), 256, BSMEM>>>(
        Vh, Vl, Dh, Dl, P, BROWS, DM, KSmma, CPAD, DM, DM,
        nullptr, nullptr, nullptr, nullptr, 0);
    reduce_sum<<<(BROWS * DM / 4 + 255) / 256, 256>>>(
        (const float4*)P, (float4*)W, BROWS * DM / 4, KSPLIT);
    final_norm_kernel<<<BROWS, 128>>>(W, dMean, outRecon);
}

// round 16
// speedup vs baseline: 1.3039x; 1.0246x over previous
#include <cuda_runtime.h>
#include <cuda_bf16.h>
#include <math.h>
#include <stdint.h>

// ---------------------------------------------------------------------------
// Problem constants
// ---------------------------------------------------------------------------
#define BROWS 1024      // batch
#define CDICT 10000     // dictionary atoms
#define CPAD  10240     // padded dict dim: divisible by 128
#define DM    512       // embedding dim
#define RHO_F 5.0f
#define THR_F 0.002f    // lam / rho
#define EPS_F 1e-12f
#define ADMM_ITERS 100
#define CHEAP_ITERS 95  // 1-product bf16 iters; remainder 3-product polish
#define NS_ITERS 8
#define KSPLIT 4        // loop split-K: 128 CTAs <= 148 SMs (balanced)
#define GSLICES 25      // G split-K (Kslice=400, 400 CTAs)
#define NSPLIT 8        // NS split-K (Kslice=64, 128 CTAs)

// ---------------------------------------------------------------------------
// Scratch (static device globals -- no cudaMalloc allowed)
// ---------------------------------------------------------------------------
__device__ float          g_Q  [(size_t)BROWS * CPAD];  // Aty, then q (ld=CPAD)
__device__ float          g_Z  [(size_t)BROWS * CPAD];  // z state (fp32)
__device__ __nv_bfloat16  g_Vh [(size_t)BROWS * CPAD];  // bf16-hi of v
__device__ __nv_bfloat16  g_Vl [(size_t)BROWS * CPAD];  // bf16-lo of v
__device__ __nv_bfloat16  g_Th [(size_t)BROWS * CPAD];  // Aty split hi (setup)
__device__ __nv_bfloat16  g_Tl [(size_t)BROWS * CPAD];  // Aty split lo (setup)
__device__ __nv_bfloat16  g_Dh [(size_t)CPAD * DM];     // dict hi [CPAD x 512]
__device__ __nv_bfloat16  g_Dl [(size_t)CPAD * DM];
__device__ __nv_bfloat16  g_DTh[(size_t)DM * CPAD];     // D^T hi [512 x CPAD]
__device__ __nv_bfloat16  g_DTl[(size_t)DM * CPAD];
__device__ float          g_E  [(size_t)DM * CPAD];     // E = G^{-1} D^T (fp32)
__device__ __nv_bfloat16  g_Eh [(size_t)DM * CPAD];
__device__ __nv_bfloat16  g_El [(size_t)DM * CPAD];
__device__ float          g_P  [(size_t)GSLICES * DM * DM]; // split-K partials
__device__ float          g_W  [(size_t)BROWS * DM];
__device__ __nv_bfloat16  g_Wh [(size_t)BROWS * DM];
__device__ __nv_bfloat16  g_Wl [(size_t)BROWS * DM];
__device__ float          g_Y  [(size_t)BROWS * DM];
__device__ __nv_bfloat16  g_Yh [(size_t)BROWS * DM];
__device__ __nv_bfloat16  g_Yl [(size_t)BROWS * DM];
__device__ float g_G [DM * DM];
__device__ float g_XA[DM * DM];
__device__ float g_XB[DM * DM];
__device__ float g_T [DM * DM];
__device__ float g_ninf;

// ---------------------------------------------------------------------------
// helpers
// ---------------------------------------------------------------------------
__device__ __forceinline__ void split_bf16(float v, __nv_bfloat16& h, __nv_bfloat16& l)
{
    h = __float2bfloat16_rn(v);
    l = __float2bfloat16_rn(v - __bfloat162float(h));
}

__device__ __forceinline__ void mma16(float* c, const unsigned* a,
                                      unsigned b0, unsigned b1)
{
    asm volatile(
        "mma.sync.aligned.m16n8k16.row.col.f32.bf16.bf16.f32 "
        "{%0,%1,%2,%3}, {%4,%5,%6,%7}, {%8,%9}, {%0,%1,%2,%3};"
        : "+f"(c[0]), "+f"(c[1]), "+f"(c[2]), "+f"(c[3])
        : "r"(a[0]), "r"(a[1]), "r"(a[2]), "r"(a[3]), "r"(b0), "r"(b1));
}

__device__ __forceinline__ void ldsm4(unsigned* r, uint32_t a)
{
    asm volatile("ldmatrix.sync.aligned.m8n8.x4.shared.b16 {%0,%1,%2,%3}, [%4];"
                 : "=r"(r[0]), "=r"(r[1]), "=r"(r[2]), "=r"(r[3]) : "r"(a));
}

__device__ __forceinline__ void ldsm4t(unsigned* r, uint32_t a)
{
    asm volatile("ldmatrix.sync.aligned.m8n8.x4.trans.shared.b16 {%0,%1,%2,%3}, [%4];"
                 : "=r"(r[0]), "=r"(r[1]), "=r"(r[2]), "=r"(r[3]) : "r"(a));
}

__device__ __forceinline__ void cp16(uint32_t s, const void* g)
{
    asm volatile("cp.async.cg.shared.global [%0], [%1], 16;"
                 :: "r"(s), "l"(g) : "memory");
}

// ---------------------------------------------------------------------------
// bf16 MMA GEMM, templated on product count and epilogue:
//   PROD==3: acc = Ah*Bh + Ah*Bl + Al*Bh       PROD==1: acc = Ah*Bh
// EPI 0: plain partial store at C + z*M*ldc (split-K, external reduce)
// EPI 1: q = (Qp - acc)/rho -> C (fp32)                              [setup]
// EPI 2: ADMM (z,v)-form, polish: t=Q+Z-acc; z'=max(t-thr,0); Z=z';
//        v' = flag ? z' : 2z'-t; split -> Vh, Vl
// EPI 3: ADMM (z,v)-form, cheap: same math; writes Vh; Vl iff flag
// BM=BN=128, BK=32, 256 thr, 8 warps (32x64 warp tile), 2-stage cp.async,
// ldmatrix fragments (conflict-free strides 40 / 136 bf16).
// ---------------------------------------------------------------------------
#define BSTG  37888
#define BSMEM (2 * BSTG)

template<int EPI, int PROD>
__global__ void __launch_bounds__(256, 2)
bmma_gemm(const __nv_bfloat16* __restrict__ Ah, const __nv_bfloat16* __restrict__ Al,
          const __nv_bfloat16* __restrict__ Bh, const __nv_bfloat16* __restrict__ Bl,
          float* __restrict__ C, int M, int N, int Kslice,
          int lda, int ldb, int ldc,
          const float* __restrict__ Qp, float* __restrict__ Zp,
          __nv_bfloat16* __restrict__ Vh, __nv_bfloat16* __restrict__ Vl,
          int flag)
{
    extern __shared__ char smd[];
    const int tid  = threadIdx.x;
    const int lane = tid & 31, wid = tid >> 5;
    const int wm = (wid & 3) * 32;
    const int wn = (wid >> 2) * 64;
    const int m0 = blockIdx.y * 128, n0 = blockIdx.x * 128;
    const long k0 = (long)blockIdx.z * Kslice;
    const int nk = Kslice >> 5;

    const int aRow = wm + ((lane >> 3) & 1) * 8 + (lane & 7);
    const int aKof = (lane >> 4) * 8;
    const int bRow = ((lane >> 3) & 1) * 8 + (lane & 7);
    const int bNof = (lane >> 4) * 8;

    float c[2][8][4];
#pragma unroll
    for (int i = 0; i < 2; ++i)
#pragma unroll
        for (int j = 0; j < 8; ++j)
#pragma unroll
            for (int q = 0; q < 4; ++q) c[i][j][q] = 0.0f;

    auto load_tile = [&](int kt, int buf) {
        char* base = smd + buf * BSTG;
        const int kb = kt * 32;
#pragma unroll
        for (int cc = 0; cc < 2; ++cc) {        // A: 128 rows x 4 chunks (8 bf16)
            int ch  = tid * 2 + cc;
            int row = ch >> 2, kc = (ch & 3) * 8;
            uint32_t so = (uint32_t)__cvta_generic_to_shared(
                base + (row * 40 + kc) * 2);
            const long go = (long)(m0 + row) * lda + k0 + kb + kc;
            cp16(so, Ah + go);
            if (PROD == 3) cp16(so + 10240, Al + go);
        }
#pragma unroll
        for (int cc = 0; cc < 2; ++cc) {        // B: 32 rows x 16 chunks
            int ch  = tid * 2 + cc;
            int row = ch >> 4, nc = (ch & 15) * 8;
            uint32_t so = (uint32_t)__cvta_generic_to_shared(
                base + 20480 + (row * 136 + nc) * 2);
            const long go = (long)(k0 + kb + row) * ldb + n0 + nc;
            cp16(so, Bh + go);
            if (PROD == 3) cp16(so + 8704, Bl + go);
        }
    };

    load_tile(0, 0);
    asm volatile("cp.async.commit_group;" ::: "memory");

    for (int kt = 0; kt < nk; ++kt) {
        asm volatile("cp.async.wait_group 0;" ::: "memory");
        __syncthreads();
        if (kt + 1 < nk) load_tile(kt + 1, (kt + 1) & 1);
        asm volatile("cp.async.commit_group;" ::: "memory");

        const uint32_t sb = (uint32_t)__cvta_generic_to_shared(smd + (kt & 1) * BSTG);

#pragma unroll
        for (int ks = 0; ks < 2; ++ks) {
            unsigned ah[2][4], al[2][4];
#pragma unroll
            for (int i = 0; i < 2; ++i) {
                uint32_t ad = sb + ((aRow + i * 16) * 40 + ks * 16 + aKof) * 2;
                ldsm4(ah[i], ad);
                if (PROD == 3) ldsm4(al[i], ad + 10240);
            }
#pragma unroll
            for (int ng = 0; ng < 4; ++ng) {
                unsigned bh[4], bl[4];
                uint32_t bd = sb + 20480 +
                              ((bRow + ks * 16) * 136 + wn + ng * 16 + bNof) * 2;
                ldsm4t(bh, bd);
                if (PROD == 3) ldsm4t(bl, bd + 8704);
#pragma unroll
                for (int jj = 0; jj < 2; ++jj) {
                    const int j = ng * 2 + jj;
#pragma unroll
                    for (int i = 0; i < 2; ++i) {
                        mma16(c[i][j], ah[i], bh[jj * 2], bh[jj * 2 + 1]);
                        if (PROD == 3) {
                            mma16(c[i][j], ah[i], bl[jj * 2], bl[jj * 2 + 1]);
                            mma16(c[i][j], al[i], bh[jj * 2], bh[jj * 2 + 1]);
                        }
                    }
                }
            }
        }
    }

    // ---- epilogue ----
    const int gq = lane >> 2, tq = lane & 3;
#pragma unroll
    for (int i = 0; i < 2; ++i) {
        const int r0 = m0 + wm + i * 16 + gq;
#pragma unroll
        for (int j = 0; j < 8; ++j) {
            const int ccn = n0 + wn + j * 8 + 2 * tq;
            if (ccn >= N) continue;
            if (EPI == 0) {
                float* Cz = C + (long)blockIdx.z * (long)M * ldc;
                *(float2*)&Cz[(long)r0 * ldc + ccn] =
                    make_float2(c[i][j][0], c[i][j][1]);
                *(float2*)&Cz[(long)(r0 + 8) * ldc + ccn] =
                    make_float2(c[i][j][2], c[i][j][3]);
            } else if (EPI == 1) {
#pragma unroll
                for (int rr = 0; rr < 2; ++rr) {
                    const long idx = (long)(r0 + rr * 8) * ldc + ccn;
                    const float ir = 1.0f / RHO_F;
                    float2 qv = *(const float2*)&Qp[idx];
                    *(float2*)&C[idx] = make_float2(
                        (qv.x - c[i][j][rr * 2 + 0]) * ir,
                        (qv.y - c[i][j][rr * 2 + 1]) * ir);
                }
            } else if (EPI == 2) {   // polish ADMM, (z,v) form
#pragma unroll
                for (int rr = 0; rr < 2; ++rr) {
                    const long idx = (long)(r0 + rr * 8) * ldc + ccn;
                    float a0 = c[i][j][rr * 2 + 0], a1 = c[i][j][rr * 2 + 1];
                    float2 qv = *(const float2*)&Qp[idx];
                    float2 zv = *(const float2*)&Zp[idx];
                    float2 zn;
                    __nv_bfloat162 nh, nl;
                    {
                        float t = qv.x + zv.x - a0;
                        float z = fmaxf(t - THR_F, 0.f);
                        zn.x = z;
                        float vn = flag ? z : (2.f * z - t);
                        split_bf16(vn, nh.x, nl.x);
                    }
                    {
                        float t = qv.y + zv.y - a1;
                        float z = fmaxf(t - THR_F, 0.f);
                        zn.y = z;
                        float vn = flag ? z : (2.f * z - t);
                        split_bf16(vn, nh.y, nl.y);
                    }
                    *(float2*)&Zp[idx] = zn;
                    *(__nv_bfloat162*)&Vh[idx] = nh;
                    *(__nv_bfloat162*)&Vl[idx] = nl;
                }
            } else if (EPI == 3) {   // cheap ADMM, (z,v) form; Vl iff flag
#pragma unroll
                for (int rr = 0; rr < 2; ++rr) {
                    const long idx = (long)(r0 + rr * 8) * ldc + ccn;
                    float a0 = c[i][j][rr * 2 + 0], a1 = c[i][j][rr * 2 + 1];
                    float2 qv = *(const float2*)&Qp[idx];
                    float2 zv = *(const float2*)&Zp[idx];
                    float2 zn;
                    __nv_bfloat162 nh, nl;
                    {
                        float t = qv.x + zv.x - a0;
                        float z = fmaxf(t - THR_F, 0.f);
                        zn.x = z;
                        float vn = 2.f * z - t;
                        split_bf16(vn, nh.x, nl.x);
                    }
                    {
                        float t = qv.y + zv.y - a1;
                        float z = fmaxf(t - THR_F, 0.f);
                        zn.y = z;
                        float vn = 2.f * z - t;
                        split_bf16(vn, nh.y, nl.y);
                    }
                    *(float2*)&Zp[idx] = zn;
                    *(__nv_bfloat162*)&Vh[idx] = nh;
                    if (flag) *(__nv_bfloat162*)&Vl[idx] = nl;
                }
            }
        }
    }
}

// ---------------------------------------------------------------------------
// SIMT tiled SGEMM (setup path: G, NS -- full fp32 accuracy)
// ---------------------------------------------------------------------------
#define BM 128
#define BN 128
#define BKK 16

template<bool TA, bool TB>
__global__ void __launch_bounds__(256, 2)
gemm_kernel(const float* __restrict__ A, const float* __restrict__ B,
            float* __restrict__ C,
            int M, int N, int Kslice, int lda, int ldb, int ldc)
{
    __shared__ float As[BKK][BM + 4];
    __shared__ float Bs[BKK][BN + 4];

    const int tid = threadIdx.x;
    const int tx  = tid & 15;
    const int ty  = tid >> 4;
    const int m0  = blockIdx.y * BM;
    const int n0  = blockIdx.x * BN;

    const long k0 = (long)blockIdx.z * Kslice;
    if (TA) A += k0 * lda; else A += k0;
    if (TB) B += k0;       else B += k0 * ldb;
    C += (long)blockIdx.z * (long)M * ldc;

    float acc[8][8];
#pragma unroll
    for (int i = 0; i < 8; ++i)
#pragma unroll
        for (int j = 0; j < 8; ++j) acc[i][j] = 0.0f;

    const int nk = Kslice / BKK;
#pragma unroll 1
    for (int kt = 0; kt < nk; ++kt) {
        const int kbase = kt * BKK;
        if (!TA) {
#pragma unroll
            for (int p = 0; p < 2; ++p) {
                const int row = p * 64 + (tid >> 2);
                const int c4  = (tid & 3) * 4;
                float4 v = *(const float4*)&A[(long)(m0 + row) * lda + kbase + c4];
                As[c4 + 0][row] = v.x; As[c4 + 1][row] = v.y;
                As[c4 + 2][row] = v.z; As[c4 + 3][row] = v.w;
            }
        } else {
#pragma unroll
            for (int p = 0; p < 2; ++p) {
                const int kr = p * 8 + (tid >> 5);
                const int m4 = (tid & 31) * 4;
                float4 v = *(const float4*)&A[(long)(kbase + kr) * lda + m0 + m4];
                *(float4*)&As[kr][m4] = v;
            }
        }
        if (!TB) {
#pragma unroll
            for (int p = 0; p < 2; ++p) {
                const int kr  = p * 8 + (tid >> 5);
                const int nn4 = (tid & 31) * 4;
                const int gn  = n0 + nn4;
                float4 v = make_float4(0.f, 0.f, 0.f, 0.f);
                if (gn < N) v = *(const float4*)&B[(long)(kbase + kr) * ldb + gn];
                *(float4*)&Bs[kr][nn4] = v;
            }
        } else {
#pragma unroll
            for (int p = 0; p < 2; ++p) {
                const int nrow = p * 64 + (tid >> 2);
                const int c4   = (tid & 3) * 4;
                const int gn   = n0 + nrow;
                float4 v = make_float4(0.f, 0.f, 0.f, 0.f);
                if (gn < N) v = *(const float4*)&B[(long)gn * ldb + kbase + c4];
                Bs[c4 + 0][nrow] = v.x; Bs[c4 + 1][nrow] = v.y;
                Bs[c4 + 2][nrow] = v.z; Bs[c4 + 3][nrow] = v.w;
            }
        }
        __syncthreads();
#pragma unroll
        for (int kk = 0; kk < BKK; ++kk) {
            float a[8], b[8];
            *(float4*)&a[0] = *(const float4*)&As[kk][ty * 4];
            *(float4*)&a[4] = *(const float4*)&As[kk][64 + ty * 4];
            *(float4*)&b[0] = *(const float4*)&Bs[kk][tx * 4];
            *(float4*)&b[4] = *(const float4*)&Bs[kk][64 + tx * 4];
#pragma unroll
            for (int i = 0; i < 8; ++i)
#pragma unroll
                for (int j = 0; j < 8; ++j)
                    acc[i][j] = fmaf(a[i], b[j], acc[i][j]);
        }
        __syncthreads();
    }

    int rows[8];
#pragma unroll
    for (int i = 0; i < 8; ++i)
        rows[i] = m0 + (i < 4 ? ty * 4 + i : 64 + ty * 4 + (i - 4));

#pragma unroll
    for (int i = 0; i < 8; ++i) {
#pragma unroll
        for (int jg = 0; jg < 2; ++jg) {
            const int cn = n0 + jg * 64 + tx * 4;
            if (cn >= N) continue;
            const long idx = (long)rows[i] * ldc + cn;
            *(float4*)&C[idx] = make_float4(acc[i][jg * 4 + 0], acc[i][jg * 4 + 1],
                                            acc[i][jg * 4 + 2], acc[i][jg * 4 + 3]);
        }
    }
}

// ---------------------------------------------------------------------------
// Transpose + bf16 split: out[i*ldo + j] = split(src[j*lds + i]), i<R, j<C
// ---------------------------------------------------------------------------
__global__ void trans_split_kernel(const float* __restrict__ src, int lds,
                                   __nv_bfloat16* __restrict__ dh,
                                   __nv_bfloat16* __restrict__ dl,
                                   int ldo, int R, int C)
{
    __shared__ float t[32][33];
    const int i0 = blockIdx.x * 32;
    const int j0 = blockIdx.y * 32;
    const int tx = threadIdx.x, ty = threadIdx.y;
    for (int jj = ty; jj < 32; jj += 8) {
        const int j = j0 + jj, i = i0 + tx;
        float v = 0.f;
        if (j < C && i < R) v = src[(long)j * lds + i];
        t[jj][tx] = v;
    }
    __syncthreads();
    for (int ii = ty; ii < 32; ii += 8) {
        const int i = i0 + ii, j = j0 + tx;
        if (i < R && j < C) {
            __nv_bfloat16 h, l;
            split_bf16(t[tx][ii], h, l);
            dh[(long)i * ldo + j] = h;
            dl[(long)i * ldo + j] = l;
        }
    }
}

// ---------------------------------------------------------------------------
// Reductions / splits
// ---------------------------------------------------------------------------
__global__ void reduce_sum(const float4* __restrict__ P, float4* __restrict__ out,
                           int n4, int S)
{
    int i = blockIdx.x * blockDim.x + threadIdx.x;
    if (i >= n4) return;
    float4 s = P[i];
    for (int k = 1; k < S; ++k) {
        float4 t = P[(long)k * n4 + i];
        s.x += t.x; s.y += t.y; s.z += t.z; s.w += t.w;
    }
    out[i] = s;
}

__global__ void reduce_split_hl(const float2* __restrict__ P,
                                __nv_bfloat162* __restrict__ Wh,
                                __nv_bfloat162* __restrict__ Wl,
                                int n2, int S)
{
    int i = blockIdx.x * blockDim.x + threadIdx.x;
    if (i >= n2) return;
    float2 s = P[i];
    for (int k = 1; k < S; ++k) {
        float2 t = P[(long)k * n2 + i];
        s.x += t.x; s.y += t.y;
    }
    __nv_bfloat162 h, l;
    split_bf16(s.x, h.x, l.x);
    split_bf16(s.y, h.y, l.y);
    Wh[i] = h; Wl[i] = l;
}

__global__ void reduce_split_h(const float2* __restrict__ P,
                               __nv_bfloat162* __restrict__ Wh,
                               int n2, int S)
{
    int i = blockIdx.x * blockDim.x + threadIdx.x;
    if (i >= n2) return;
    float2 s = P[i];
    for (int k = 1; k < S; ++k) {
        float2 t = P[(long)k * n2 + i];
        s.x += t.x; s.y += t.y;
    }
    __nv_bfloat162 h;
    h.x = __float2bfloat16_rn(s.x);
    h.y = __float2bfloat16_rn(s.y);
    Wh[i] = h;
}

__global__ void split_mat_bf16(const float2* __restrict__ src,
                               __nv_bfloat162* __restrict__ hi,
                               __nv_bfloat162* __restrict__ lo, long n2)
{
    long i = (long)blockIdx.x * blockDim.x + threadIdx.x;
    if (i >= n2) return;
    float2 v = src[i];
    __nv_bfloat162 h, l;
    split_bf16(v.x, h.x, l.x);
    split_bf16(v.y, h.y, l.y);
    hi[i] = h; lo[i] = l;
}

__global__ void reduce_G(const float* __restrict__ P, float* __restrict__ G, int S)
{
    int i = blockIdx.x * blockDim.x + threadIdx.x;
    if (i >= DM * DM) return;
    float s = 0.f;
    for (int k = 0; k < S; ++k) s += P[(long)k * DM * DM + i];
    if ((i / DM) == (i % DM)) s += RHO_F;
    G[i] = s;
}

__global__ void reduce_ns(const float4* __restrict__ P, const float4* __restrict__ Xc,
                          float4* __restrict__ Xn, int n4, int S)
{
    int i = blockIdx.x * blockDim.x + threadIdx.x;
    if (i >= n4) return;
    float4 s = P[i];
    for (int k = 1; k < S; ++k) {
        float4 t = P[(long)k * n4 + i];
        s.x += t.x; s.y += t.y; s.z += t.z; s.w += t.w;
    }
    float4 x = Xc[i];
    Xn[i] = make_float4(2.f * x.x - s.x, 2.f * x.y - s.y,
                        2.f * x.z - s.z, 2.f * x.w - s.w);
}

__global__ void ninf_kernel(const float* __restrict__ G)
{
    __shared__ float sm[DM];
    const int i = threadIdx.x;
    float s = 0.f;
    for (int j = 0; j < DM; ++j) s += fabsf(G[(long)j * DM + i]);
    sm[i] = s;
    __syncthreads();
    for (int o = DM / 2; o > 0; o >>= 1) {
        if (i < o) sm[i] = fmaxf(sm[i], sm[i + o]);
        __syncthreads();
    }
    if (i == 0) g_ninf = sm[0];
}

__global__ void x0_kernel(float* __restrict__ X)
{
    int i = blockIdx.x * blockDim.x + threadIdx.x;
    if (i >= DM * DM) return;
    float c = 2.0f / (RHO_F + g_ninf);
    X[i] = ((i / DM) == (i % DM)) ? c : 0.0f;
}

// ---------------------------------------------------------------------------
// Row-normalize kernels
// ---------------------------------------------------------------------------
__device__ __forceinline__ float block_sum128(float v, float* red)
{
    for (int o = 16; o > 0; o >>= 1) v += __shfl_xor_sync(0xffffffff, v, o);
    if ((threadIdx.x & 31) == 0) red[threadIdx.x >> 5] = v;
    __syncthreads();
    float tot = red[0] + red[1] + red[2] + red[3];
    __syncthreads();
    return tot;
}

__global__ void norm_center_kernel(const float* __restrict__ img,
                                   const float* __restrict__ mean,
                                   float* __restrict__ out)
{
    __shared__ float red[4];
    const int r = blockIdx.x, t = threadIdx.x;
    float4 v = ((const float4*)(img + (long)r * DM))[t];
    float ss = v.x * v.x + v.y * v.y + v.z * v.z + v.w * v.w;
    float inv = 1.0f / fmaxf(sqrtf(block_sum128(ss, red)), EPS_F);
    float4 mv = ((const float4*)mean)[t];
    float4 c = make_float4(v.x * inv - mv.x, v.y * inv - mv.y,
                           v.z * inv - mv.z, v.w * inv - mv.w);
    float ss2 = c.x * c.x + c.y * c.y + c.z * c.z + c.w * c.w;
    float inv2 = 1.0f / fmaxf(sqrtf(block_sum128(ss2, red)), EPS_F);
    ((float4*)(out + (long)r * DM))[t] =
        make_float4(c.x * inv2, c.y * inv2, c.z * inv2, c.w * inv2);
}

__global__ void norm_rows_kernel(const float* __restrict__ in, float* __restrict__ out)
{
    __shared__ float red[4];
    const int r = blockIdx.x, t = threadIdx.x;
    float4 v = ((const float4*)(in + (long)r * DM))[t];
    float ss = v.x * v.x + v.y * v.y + v.z * v.z + v.w * v.w;
    float inv = 1.0f / fmaxf(sqrtf(block_sum128(ss, red)), EPS_F);
    ((float4*)(out + (long)r * DM))[t] =
        make_float4(v.x * inv, v.y * inv, v.z * inv, v.w * inv);
}

__global__ void final_norm_kernel(const float* __restrict__ rec,
                                  const float* __restrict__ mean,
                                  float* __restrict__ out)
{
    __shared__ float red[4];
    const int r = blockIdx.x, t = threadIdx.x;
    float4 v = ((const float4*)(rec + (long)r * DM))[t];
    float ss = v.x * v.x + v.y * v.y + v.z * v.z + v.w * v.w;
    float inv = 1.0f / fmaxf(sqrtf(block_sum128(ss, red)), EPS_F);
    float4 mv = ((const float4*)mean)[t];
    float4 c = make_float4(v.x * inv + mv.x, v.y * inv + mv.y,
                           v.z * inv + mv.z, v.w * inv + mv.w);
    float ss2 = c.x * c.x + c.y * c.y + c.z * c.z + c.w * c.w;
    float inv2 = 1.0f / fmaxf(sqrtf(block_sum128(ss2, red)), EPS_F);
    ((float4*)(out + (long)r * DM))[t] =
        make_float4(c.x * inv2, c.y * inv2, c.z * inv2, c.w * inv2);
}

// ---------------------------------------------------------------------------
// Host orchestration
// ---------------------------------------------------------------------------
extern "C" void kernel_launch(void* const* d_in, const int* in_sizes, int n_in,
                              void* d_out, int out_size)
{
    const float* dImg  = (const float*)d_in[0];
    const float* dTxt  = (const float*)d_in[1];
    const float* dMean = (const float*)d_in[2];
    const float* dDict = (const float*)d_in[3];
    float* outRecon = (float*)d_out;
    float* outTxt   = (float*)d_out + (long)BROWS * DM;

    float *Q, *Z, *E, *P, *W, *Y, *G, *XA, *XB, *T;
    __nv_bfloat16 *Vh, *Vl, *Th, *Tl, *Dh, *Dl, *DTh, *DTl, *Eh, *El,
                  *Wh, *Wl, *Yh, *Yl;
    cudaGetSymbolAddress((void**)&Q,   g_Q);
    cudaGetSymbolAddress((void**)&Z,   g_Z);
    cudaGetSymbolAddress((void**)&Vh,  g_Vh);
    cudaGetSymbolAddress((void**)&Vl,  g_Vl);
    cudaGetSymbolAddress((void**)&Th,  g_Th);
    cudaGetSymbolAddress((void**)&Tl,  g_Tl);
    cudaGetSymbolAddress((void**)&Dh,  g_Dh);
    cudaGetSymbolAddress((void**)&Dl,  g_Dl);
    cudaGetSymbolAddress((void**)&DTh, g_DTh);
    cudaGetSymbolAddress((void**)&DTl, g_DTl);
    cudaGetSymbolAddress((void**)&E,   g_E);
    cudaGetSymbolAddress((void**)&Eh,  g_Eh);
    cudaGetSymbolAddress((void**)&El,  g_El);
    cudaGetSymbolAddress((void**)&P,   g_P);
    cudaGetSymbolAddress((void**)&W,   g_W);
    cudaGetSymbolAddress((void**)&Wh,  g_Wh);
    cudaGetSymbolAddress((void**)&Wl,  g_Wl);
    cudaGetSymbolAddress((void**)&Y,   g_Y);
    cudaGetSymbolAddress((void**)&Yh,  g_Yh);
    cudaGetSymbolAddress((void**)&Yl,  g_Yl);
    cudaGetSymbolAddress((void**)&G,   g_G);
    cudaGetSymbolAddress((void**)&XA,  g_XA);
    cudaGetSymbolAddress((void**)&XB,  g_XB);
    cudaGetSymbolAddress((void**)&T,   g_T);

    cudaFuncSetAttribute(bmma_gemm<0, 3>, cudaFuncAttributeMaxDynamicSharedMemorySize, BSMEM);
    cudaFuncSetAttribute(bmma_gemm<1, 3>, cudaFuncAttributeMaxDynamicSharedMemorySize, BSMEM);
    cudaFuncSetAttribute(bmma_gemm<2, 3>, cudaFuncAttributeMaxDynamicSharedMemorySize, BSMEM);
    cudaFuncSetAttribute(bmma_gemm<0, 1>, cudaFuncAttributeMaxDynamicSharedMemorySize, BSMEM);
    cudaFuncSetAttribute(bmma_gemm<3, 1>, cudaFuncAttributeMaxDynamicSharedMemorySize, BSMEM);

    const int NT = (CDICT + BN - 1) / BN;   // 79 tiles over N=10000
    const int KSG = CDICT / GSLICES;        // 400 (G split-K, 25 slices)
    const int KSmma = CPAD / KSPLIT;        // 2560 (loop split-K, 4 slices)

    // 0) zero-pad-sensitive buffers
    cudaMemsetAsync(Q,   0, sizeof(float) * (size_t)BROWS * CPAD, 0);
    cudaMemsetAsync(DTh, 0, sizeof(__nv_bfloat16) * (size_t)DM * CPAD, 0);
    cudaMemsetAsync(DTl, 0, sizeof(__nv_bfloat16) * (size_t)DM * CPAD, 0);
    cudaMemsetAsync(Dh,  0, sizeof(__nv_bfloat16) * (size_t)CPAD * DM, 0);
    cudaMemsetAsync(Dl,  0, sizeof(__nv_bfloat16) * (size_t)CPAD * DM, 0);
    cudaMemsetAsync(E,   0, sizeof(float) * (size_t)DM * CPAD, 0);

    // 1) centered inputs + text output; splits of Y and D / D^T
    norm_center_kernel<<<BROWS, 128>>>(dImg, dMean, Y);
    norm_rows_kernel<<<BROWS, 128>>>(dTxt, outTxt);
    split_mat_bf16<<<(BROWS * DM / 2 + 255) / 256, 256>>>(
        (const float2*)Y, (__nv_bfloat162*)Yh, (__nv_bfloat162*)Yl, BROWS * DM / 2);
    split_mat_bf16<<<(int)(((long)CDICT * DM / 2 + 255) / 256), 256>>>(
        (const float2*)dDict, (__nv_bfloat162*)Dh, (__nv_bfloat162*)Dl,
        (long)CDICT * DM / 2);
    trans_split_kernel<<<dim3(16, 313), dim3(32, 8)>>>(
        dDict, DM, DTh, DTl, CPAD, DM, CDICT);

    // 2) Aty = Y @ D^T -> Q (bf16x3 tensor path; Q pads stay zero)
    bmma_gemm<0, 3><<<dim3(NT, 8, 1), 256, BSMEM>>>(
        Yh, Yl, DTh, DTl, Q, BROWS, CDICT, DM, DM, CPAD, CPAD,
        nullptr, nullptr, nullptr, nullptr, 0);

    // 3) G = D^T D + rho I (fp32 SIMT, 25-way split-K -> 400 CTAs)
    gemm_kernel<true, false><<<dim3(4, 4, GSLICES), 256>>>(
        dDict, dDict, P, DM, DM, KSG, DM, DM, DM);
    reduce_G<<<(DM * DM + 255) / 256, 256>>>(P, G, GSLICES);

    // 4) Newton-Schulz inverse (fp32 SIMT, 8-way split-K -> 128 CTAs)
    ninf_kernel<<<1, DM>>>(G);
    x0_kernel<<<(DM * DM + 255) / 256, 256>>>(XA);
    float* Xc = XA; float* Xn = XB;
    for (int t = 0; t < NS_ITERS; ++t) {
        gemm_kernel<false, false><<<dim3(4, 4, NSPLIT), 256>>>(
            G, Xc, P, DM, DM, DM / NSPLIT, DM, DM, DM);
        reduce_sum<<<(DM * DM / 4 + 255) / 256, 256>>>(
            (const float4*)P, (float4*)T, DM * DM / 4, NSPLIT);
        gemm_kernel<false, false><<<dim3(4, 4, NSPLIT), 256>>>(
            Xc, T, P, DM, DM, DM / NSPLIT, DM, DM, DM);
        reduce_ns<<<(DM * DM / 4 + 255) / 256, 256>>>(
            (const float4*)P, (const float4*)Xc, (float4*)Xn, DM * DM / 4, NSPLIT);
        float* tmp = Xc; Xc = Xn; Xn = tmp;
    }

    // 5) E = G^{-1} @ D^T via bf16x3 tensor path (E only ever consumed as
    //    bf16 hi/lo, so the ~1e-5 bf16x3 error is below the split's own
    //    truncation).  Xc split into the currently-idle Wh/Wl buffers.
    split_mat_bf16<<<(DM * DM / 2 + 255) / 256, 256>>>(
        (const float2*)Xc, (__nv_bfloat162*)Wh, (__nv_bfloat162*)Wl, DM * DM / 2);
    bmma_gemm<0, 3><<<dim3(NT, 4, 1), 256, BSMEM>>>(
        Wh, Wl, DTh, DTl, E, DM, CDICT, DM, DM, CPAD, CPAD,
        nullptr, nullptr, nullptr, nullptr, 0);
    split_mat_bf16<<<(int)(((long)DM * CPAD / 2 + 255) / 256), 256>>>(
        (const float2*)E, (__nv_bfloat162*)Eh, (__nv_bfloat162*)El,
        (long)DM * CPAD / 2);

    // 6) q = (Aty - (Aty @ D) @ E) / rho  (bf16x3 tensor path, in place on Q)
    split_mat_bf16<<<(int)(((long)BROWS * CPAD / 2 + 255) / 256), 256>>>(
        (const float2*)Q, (__nv_bfloat162*)Th, (__nv_bfloat162*)Tl,
        (long)BROWS * CPAD / 2);
    bmma_gemm<0, 3><<<dim3(4, 8, KSPLIT), 256, BSMEM>>>(
        Th, Tl, Dh, Dl, P, BROWS, DM, KSmma, CPAD, DM, DM,
        nullptr, nullptr, nullptr, nullptr, 0);
    reduce_split_hl<<<(BROWS * DM / 2 + 255) / 256, 256>>>(
        (const float2*)P, (__nv_bfloat162*)Wh, (__nv_bfloat162*)Wl,
        BROWS * DM / 2, KSPLIT);
    bmma_gemm<1, 3><<<dim3(NT, 8, 1), 256, BSMEM>>>(
        Wh, Wl, Eh, El, Q, BROWS, CDICT, DM, DM, CPAD, CPAD,
        Q, nullptr, nullptr, nullptr, 0);

    // 7) ADMM loop, (z, v) state form: t = q + z - (vD)E;
    //    z' = max(t - thr, 0); v' = 2z' - t.  u is never materialized.
    cudaMemsetAsync(Vh, 0, sizeof(__nv_bfloat16) * (size_t)BROWS * CPAD, 0);
    cudaMemsetAsync(Vl, 0, sizeof(__nv_bfloat16) * (size_t)BROWS * CPAD, 0);
    cudaMemsetAsync(Z,  0, sizeof(float) * (size_t)BROWS * CPAD, 0);
    for (int it = 0; it < ADMM_ITERS; ++it) {
        if (it < CHEAP_ITERS) {
            const int wl = (it == CHEAP_ITERS - 1) ? 1 : 0;
            bmma_gemm<0, 1><<<dim3(4, 8, KSPLIT), 256, BSMEM>>>(
                Vh, nullptr, Dh, nullptr, P, BROWS, DM, KSmma, CPAD, DM, DM,
                nullptr, nullptr, nullptr, nullptr, 0);
            reduce_split_h<<<(BROWS * DM / 2 + 255) / 256, 256>>>(
                (const float2*)P, (__nv_bfloat162*)Wh, BROWS * DM / 2, KSPLIT);
            bmma_gemm<3, 1><<<dim3(NT, 8, 1), 256, BSMEM>>>(
                Wh, nullptr, Eh, nullptr, nullptr, BROWS, CDICT, DM, DM, CPAD, CPAD,
                Q, Z, Vh, Vl, wl);
        } else {
            const int last = (it == ADMM_ITERS - 1) ? 1 : 0;
            bmma_gemm<0, 3><<<dim3(4, 8, KSPLIT), 256, BSMEM>>>(
                Vh, Vl, Dh, Dl, P, BROWS, DM, KSmma, CPAD, DM, DM,
                nullptr, nullptr, nullptr, nullptr, 0);
            reduce_split_hl<<<(BROWS * DM / 2 + 255) / 256, 256>>>(
                (const float2*)P, (__nv_bfloat162*)Wh, (__nv_bfloat162*)Wl,
                BROWS * DM / 2, KSPLIT);
            bmma_gemm<2, 3><<<dim3(NT, 8, 1), 256, BSMEM>>>(
                Wh, Wl, Eh, El, nullptr, BROWS, CDICT, DM, DM, CPAD, CPAD,
                Q, Z, Vh, Vl, last);
        }
    }

    // 8) recon = normalize(normalize(z @ D) + mean)   (z in Vh/Vl; accurate)
    bmma_gemm<0, 3><<<dim3(4, 8, KSPLIT), 256, BSMEM>>>(
        Vh, Vl, Dh, Dl, P, BROWS, DM, KSmma, CPAD, DM, DM,
        nullptr, nullptr, nullptr, nullptr, 0);
    reduce_sum<<<(BROWS * DM / 4 + 255) / 256, 256>>>(
        (const float4*)P, (float4*)W, BROWS * DM / 4, KSPLIT);
    final_norm_kernel<<<BROWS, 128>>>(W, dMean, outRecon);
}

// round 17
// speedup vs baseline: 1.6385x; 1.2566x over previous
#include <cuda_runtime.h>
#include <cuda_bf16.h>
#include <math.h>
#include <stdint.h>

// ---------------------------------------------------------------------------
// Problem constants
// ---------------------------------------------------------------------------
#define BROWS 1024      // batch
#define CDICT 10000     // dictionary atoms
#define CPAD  10368     // padded dict dim: 9 * 1152, div by 32; >= CDICT
#define DM    512       // embedding dim
#define RHO_F 5.0f
#define THR_F 0.002f    // lam / rho
#define EPS_F 1e-12f
#define ADMM_ITERS 100
#define CHEAP_ITERS 97  // 1-product bf16 iters; remainder 3-product polish
#define NS_ITERS 8
#define KSPLIT 9        // loop split-K: 4*8*9 = 288 CTAs ~= 296 slots (2/SM)
#define GSLICES 25      // G split-K (Kslice=400, 400 CTAs)
#define NSPLIT 8        // NS split-K (Kslice=64, 128 CTAs)

// ---------------------------------------------------------------------------
// Scratch (static device globals -- no cudaMalloc allowed)
// ---------------------------------------------------------------------------
__device__ float          g_Q  [(size_t)BROWS * CPAD];  // Aty, then q (ld=CPAD)
__device__ float          g_Z  [(size_t)BROWS * CPAD];  // z state (fp32)
__device__ __nv_bfloat16  g_Vh [(size_t)BROWS * CPAD];  // bf16-hi of v
__device__ __nv_bfloat16  g_Vl [(size_t)BROWS * CPAD];  // bf16-lo of v
__device__ __nv_bfloat16  g_Th [(size_t)BROWS * CPAD];  // Aty split hi (setup)
__device__ __nv_bfloat16  g_Tl [(size_t)BROWS * CPAD];  // Aty split lo (setup)
__device__ __nv_bfloat16  g_Dh [(size_t)CPAD * DM];     // dict hi [CPAD x 512]
__device__ __nv_bfloat16  g_Dl [(size_t)CPAD * DM];
__device__ __nv_bfloat16  g_DTh[(size_t)DM * CPAD];     // D^T hi [512 x CPAD]
__device__ __nv_bfloat16  g_DTl[(size_t)DM * CPAD];
__device__ float          g_E  [(size_t)DM * CPAD];     // E = G^{-1} D^T (fp32)
__device__ __nv_bfloat16  g_Eh [(size_t)DM * CPAD];
__device__ __nv_bfloat16  g_El [(size_t)DM * CPAD];
__device__ float          g_P  [(size_t)GSLICES * DM * DM]; // split-K partials
__device__ float          g_W  [(size_t)BROWS * DM];
__device__ __nv_bfloat16  g_Wh [(size_t)BROWS * DM];
__device__ __nv_bfloat16  g_Wl [(size_t)BROWS * DM];
__device__ float          g_Y  [(size_t)BROWS * DM];
__device__ __nv_bfloat16  g_Yh [(size_t)BROWS * DM];
__device__ __nv_bfloat16  g_Yl [(size_t)BROWS * DM];
__device__ float g_G [DM * DM];
__device__ float g_XA[DM * DM];
__device__ float g_XB[DM * DM];
__device__ float g_T [DM * DM];
__device__ float g_ninf;

// ---------------------------------------------------------------------------
// helpers
// ---------------------------------------------------------------------------
__device__ __forceinline__ void split_bf16(float v, __nv_bfloat16& h, __nv_bfloat16& l)
{
    h = __float2bfloat16_rn(v);
    l = __float2bfloat16_rn(v - __bfloat162float(h));
}

__device__ __forceinline__ void mma16(float* c, const unsigned* a,
                                      unsigned b0, unsigned b1)
{
    asm volatile(
        "mma.sync.aligned.m16n8k16.row.col.f32.bf16.bf16.f32 "
        "{%0,%1,%2,%3}, {%4,%5,%6,%7}, {%8,%9}, {%0,%1,%2,%3};"
        : "+f"(c[0]), "+f"(c[1]), "+f"(c[2]), "+f"(c[3])
        : "r"(a[0]), "r"(a[1]), "r"(a[2]), "r"(a[3]), "r"(b0), "r"(b1));
}

__device__ __forceinline__ void ldsm4(unsigned* r, uint32_t a)
{
    asm volatile("ldmatrix.sync.aligned.m8n8.x4.shared.b16 {%0,%1,%2,%3}, [%4];"
                 : "=r"(r[0]), "=r"(r[1]), "=r"(r[2]), "=r"(r[3]) : "r"(a));
}

__device__ __forceinline__ void ldsm4t(unsigned* r, uint32_t a)
{
    asm volatile("ldmatrix.sync.aligned.m8n8.x4.trans.shared.b16 {%0,%1,%2,%3}, [%4];"
                 : "=r"(r[0]), "=r"(r[1]), "=r"(r[2]), "=r"(r[3]) : "r"(a));
}

__device__ __forceinline__ void cp16(uint32_t s, const void* g)
{
    asm volatile("cp.async.cg.shared.global [%0], [%1], 16;"
                 :: "r"(s), "l"(g) : "memory");
}

// ---------------------------------------------------------------------------
// bf16 MMA GEMM, templated on product count and epilogue:
//   PROD==3: acc = Ah*Bh + Ah*Bl + Al*Bh       PROD==1: acc = Ah*Bh
// EPI 0: plain partial store at C + z*M*ldc (split-K, external reduce)
// EPI 1: q = (Qp - acc)/rho -> C (fp32)                              [setup]
// EPI 2: ADMM (z,v)-form, polish: t=Q+Z-acc; z'=max(t-thr,0); Z=z';
//        v' = flag ? z' : 2z'-t; split -> Vh, Vl
// EPI 3: ADMM (z,v)-form, cheap: same math; writes Vh; Vl iff flag
// BM=BN=128, BK=32, 256 thr, 8 warps (32x64 warp tile), 2-stage cp.async,
// ldmatrix fragments (conflict-free strides 40 / 136 bf16).
// ---------------------------------------------------------------------------
#define BSTG  37888
#define BSMEM (2 * BSTG)

template<int EPI, int PROD>
__global__ void __launch_bounds__(256, 2)
bmma_gemm(const __nv_bfloat16* __restrict__ Ah, const __nv_bfloat16* __restrict__ Al,
          const __nv_bfloat16* __restrict__ Bh, const __nv_bfloat16* __restrict__ Bl,
          float* __restrict__ C, int M, int N, int Kslice,
          int lda, int ldb, int ldc,
          const float* __restrict__ Qp, float* __restrict__ Zp,
          __nv_bfloat16* __restrict__ Vh, __nv_bfloat16* __restrict__ Vl,
          int flag)
{
    extern __shared__ char smd[];
    const int tid  = threadIdx.x;
    const int lane = tid & 31, wid = tid >> 5;
    const int wm = (wid & 3) * 32;
    const int wn = (wid >> 2) * 64;
    const int m0 = blockIdx.y * 128, n0 = blockIdx.x * 128;
    const long k0 = (long)blockIdx.z * Kslice;
    const int nk = Kslice >> 5;

    const int aRow = wm + ((lane >> 3) & 1) * 8 + (lane & 7);
    const int aKof = (lane >> 4) * 8;
    const int bRow = ((lane >> 3) & 1) * 8 + (lane & 7);
    const int bNof = (lane >> 4) * 8;

    float c[2][8][4];
#pragma unroll
    for (int i = 0; i < 2; ++i)
#pragma unroll
        for (int j = 0; j < 8; ++j)
#pragma unroll
            for (int q = 0; q < 4; ++q) c[i][j][q] = 0.0f;

    auto load_tile = [&](int kt, int buf) {
        char* base = smd + buf * BSTG;
        const int kb = kt * 32;
#pragma unroll
        for (int cc = 0; cc < 2; ++cc) {        // A: 128 rows x 4 chunks (8 bf16)
            int ch  = tid * 2 + cc;
            int row = ch >> 2, kc = (ch & 3) * 8;
            uint32_t so = (uint32_t)__cvta_generic_to_shared(
                base + (row * 40 + kc) * 2);
            const long go = (long)(m0 + row) * lda + k0 + kb + kc;
            cp16(so, Ah + go);
            if (PROD == 3) cp16(so + 10240, Al + go);
        }
#pragma unroll
        for (int cc = 0; cc < 2; ++cc) {        // B: 32 rows x 16 chunks
            int ch  = tid * 2 + cc;
            int row = ch >> 4, nc = (ch & 15) * 8;
            uint32_t so = (uint32_t)__cvta_generic_to_shared(
                base + 20480 + (row * 136 + nc) * 2);
            const long go = (long)(k0 + kb + row) * ldb + n0 + nc;
            cp16(so, Bh + go);
            if (PROD == 3) cp16(so + 8704, Bl + go);
        }
    };

    load_tile(0, 0);
    asm volatile("cp.async.commit_group;" ::: "memory");

    for (int kt = 0; kt < nk; ++kt) {
        asm volatile("cp.async.wait_group 0;" ::: "memory");
        __syncthreads();
        if (kt + 1 < nk) load_tile(kt + 1, (kt + 1) & 1);
        asm volatile("cp.async.commit_group;" ::: "memory");

        const uint32_t sb = (uint32_t)__cvta_generic_to_shared(smd + (kt & 1) * BSTG);

#pragma unroll
        for (int ks = 0; ks < 2; ++ks) {
            unsigned ah[2][4], al[2][4];
#pragma unroll
            for (int i = 0; i < 2; ++i) {
                uint32_t ad = sb + ((aRow + i * 16) * 40 + ks * 16 + aKof) * 2;
                ldsm4(ah[i], ad);
                if (PROD == 3) ldsm4(al[i], ad + 10240);
            }
#pragma unroll
            for (int ng = 0; ng < 4; ++ng) {
                unsigned bh[4], bl[4];
                uint32_t bd = sb + 20480 +
                              ((bRow + ks * 16) * 136 + wn + ng * 16 + bNof) * 2;
                ldsm4t(bh, bd);
                if (PROD == 3) ldsm4t(bl, bd + 8704);
#pragma unroll
                for (int jj = 0; jj < 2; ++jj) {
                    const int j = ng * 2 + jj;
#pragma unroll
                    for (int i = 0; i < 2; ++i) {
                        mma16(c[i][j], ah[i], bh[jj * 2], bh[jj * 2 + 1]);
                        if (PROD == 3) {
                            mma16(c[i][j], ah[i], bl[jj * 2], bl[jj * 2 + 1]);
                            mma16(c[i][j], al[i], bh[jj * 2], bh[jj * 2 + 1]);
                        }
                    }
                }
            }
        }
    }

    // ---- epilogue ----
    const int gq = lane >> 2, tq = lane & 3;
#pragma unroll
    for (int i = 0; i < 2; ++i) {
        const int r0 = m0 + wm + i * 16 + gq;
#pragma unroll
        for (int j = 0; j < 8; ++j) {
            const int ccn = n0 + wn + j * 8 + 2 * tq;
            if (ccn >= N) continue;
            if (EPI == 0) {
                float* Cz = C + (long)blockIdx.z * (long)M * ldc;
                *(float2*)&Cz[(long)r0 * ldc + ccn] =
                    make_float2(c[i][j][0], c[i][j][1]);
                *(float2*)&Cz[(long)(r0 + 8) * ldc + ccn] =
                    make_float2(c[i][j][2], c[i][j][3]);
            } else if (EPI == 1) {
#pragma unroll
                for (int rr = 0; rr < 2; ++rr) {
                    const long idx = (long)(r0 + rr * 8) * ldc + ccn;
                    const float ir = 1.0f / RHO_F;
                    float2 qv = *(const float2*)&Qp[idx];
                    *(float2*)&C[idx] = make_float2(
                        (qv.x - c[i][j][rr * 2 + 0]) * ir,
                        (qv.y - c[i][j][rr * 2 + 1]) * ir);
                }
            } else if (EPI == 2) {   // polish ADMM, (z,v) form
#pragma unroll
                for (int rr = 0; rr < 2; ++rr) {
                    const long idx = (long)(r0 + rr * 8) * ldc + ccn;
                    float a0 = c[i][j][rr * 2 + 0], a1 = c[i][j][rr * 2 + 1];
                    float2 qv = *(const float2*)&Qp[idx];
                    float2 zv = *(const float2*)&Zp[idx];
                    float2 zn;
                    __nv_bfloat162 nh, nl;
                    {
                        float t = qv.x + zv.x - a0;
                        float z = fmaxf(t - THR_F, 0.f);
                        zn.x = z;
                        float vn = flag ? z : (2.f * z - t);
                        split_bf16(vn, nh.x, nl.x);
                    }
                    {
                        float t = qv.y + zv.y - a1;
                        float z = fmaxf(t - THR_F, 0.f);
                        zn.y = z;
                        float vn = flag ? z : (2.f * z - t);
                        split_bf16(vn, nh.y, nl.y);
                    }
                    *(float2*)&Zp[idx] = zn;
                    *(__nv_bfloat162*)&Vh[idx] = nh;
                    *(__nv_bfloat162*)&Vl[idx] = nl;
                }
            } else if (EPI == 3) {   // cheap ADMM, (z,v) form; Vl iff flag
#pragma unroll
                for (int rr = 0; rr < 2; ++rr) {
                    const long idx = (long)(r0 + rr * 8) * ldc + ccn;
                    float a0 = c[i][j][rr * 2 + 0], a1 = c[i][j][rr * 2 + 1];
                    float2 qv = *(const float2*)&Qp[idx];
                    float2 zv = *(const float2*)&Zp[idx];
                    float2 zn;
                    __nv_bfloat162 nh, nl;
                    {
                        float t = qv.x + zv.x - a0;
                        float z = fmaxf(t - THR_F, 0.f);
                        zn.x = z;
                        float vn = 2.f * z - t;
                        split_bf16(vn, nh.x, nl.x);
                    }
                    {
                        float t = qv.y + zv.y - a1;
                        float z = fmaxf(t - THR_F, 0.f);
                        zn.y = z;
                        float vn = 2.f * z - t;
                        split_bf16(vn, nh.y, nl.y);
                    }
                    *(float2*)&Zp[idx] = zn;
                    *(__nv_bfloat162*)&Vh[idx] = nh;
                    if (flag) *(__nv_bfloat162*)&Vl[idx] = nl;
                }
            }
        }
    }
}

// ---------------------------------------------------------------------------
// SIMT tiled SGEMM (setup path: G, NS -- full fp32 accuracy)
// ---------------------------------------------------------------------------
#define BM 128
#define BN 128
#define BKK 16

template<bool TA, bool TB>
__global__ void __launch_bounds__(256, 2)
gemm_kernel(const float* __restrict__ A, const float* __restrict__ B,
            float* __restrict__ C,
            int M, int N, int Kslice, int lda, int ldb, int ldc)
{
    __shared__ float As[BKK][BM + 4];
    __shared__ float Bs[BKK][BN + 4];

    const int tid = threadIdx.x;
    const int tx  = tid & 15;
    const int ty  = tid >> 4;
    const int m0  = blockIdx.y * BM;
    const int n0  = blockIdx.x * BN;

    const long k0 = (long)blockIdx.z * Kslice;
    if (TA) A += k0 * lda; else A += k0;
    if (TB) B += k0;       else B += k0 * ldb;
    C += (long)blockIdx.z * (long)M * ldc;

    float acc[8][8];
#pragma unroll
    for (int i = 0; i < 8; ++i)
#pragma unroll
        for (int j = 0; j < 8; ++j) acc[i][j] = 0.0f;

    const int nk = Kslice / BKK;
#pragma unroll 1
    for (int kt = 0; kt < nk; ++kt) {
        const int kbase = kt * BKK;
        if (!TA) {
#pragma unroll
            for (int p = 0; p < 2; ++p) {
                const int row = p * 64 + (tid >> 2);
                const int c4  = (tid & 3) * 4;
                float4 v = *(const float4*)&A[(long)(m0 + row) * lda + kbase + c4];
                As[c4 + 0][row] = v.x; As[c4 + 1][row] = v.y;
                As[c4 + 2][row] = v.z; As[c4 + 3][row] = v.w;
            }
        } else {
#pragma unroll
            for (int p = 0; p < 2; ++p) {
                const int kr = p * 8 + (tid >> 5);
                const int m4 = (tid & 31) * 4;
                float4 v = *(const float4*)&A[(long)(kbase + kr) * lda + m0 + m4];
                *(float4*)&As[kr][m4] = v;
            }
        }
        if (!TB) {
#pragma unroll
            for (int p = 0; p < 2; ++p) {
                const int kr  = p * 8 + (tid >> 5);
                const int nn4 = (tid & 31) * 4;
                const int gn  = n0 + nn4;
                float4 v = make_float4(0.f, 0.f, 0.f, 0.f);
                if (gn < N) v = *(const float4*)&B[(long)(kbase + kr) * ldb + gn];
                *(float4*)&Bs[kr][nn4] = v;
            }
        } else {
#pragma unroll
            for (int p = 0; p < 2; ++p) {
                const int nrow = p * 64 + (tid >> 2);
                const int c4   = (tid & 3) * 4;
                const int gn   = n0 + nrow;
                float4 v = make_float4(0.f, 0.f, 0.f, 0.f);
                if (gn < N) v = *(const float4*)&B[(long)gn * ldb + kbase + c4];
                Bs[c4 + 0][nrow] = v.x; Bs[c4 + 1][nrow] = v.y;
                Bs[c4 + 2][nrow] = v.z; Bs[c4 + 3][nrow] = v.w;
            }
        }
        __syncthreads();
#pragma unroll
        for (int kk = 0; kk < BKK; ++kk) {
            float a[8], b[8];
            *(float4*)&a[0] = *(const float4*)&As[kk][ty * 4];
            *(float4*)&a[4] = *(const float4*)&As[kk][64 + ty * 4];
            *(float4*)&b[0] = *(const float4*)&Bs[kk][tx * 4];
            *(float4*)&b[4] = *(const float4*)&Bs[kk][64 + tx * 4];
#pragma unroll
            for (int i = 0; i < 8; ++i)
#pragma unroll
                for (int j = 0; j < 8; ++j)
                    acc[i][j] = fmaf(a[i], b[j], acc[i][j]);
        }
        __syncthreads();
    }

    int rows[8];
#pragma unroll
    for (int i = 0; i < 8; ++i)
        rows[i] = m0 + (i < 4 ? ty * 4 + i : 64 + ty * 4 + (i - 4));

#pragma unroll
    for (int i = 0; i < 8; ++i) {
#pragma unroll
        for (int jg = 0; jg < 2; ++jg) {
            const int cn = n0 + jg * 64 + tx * 4;
            if (cn >= N) continue;
            const long idx = (long)rows[i] * ldc + cn;
            *(float4*)&C[idx] = make_float4(acc[i][jg * 4 + 0], acc[i][jg * 4 + 1],
                                            acc[i][jg * 4 + 2], acc[i][jg * 4 + 3]);
        }
    }
}

// ---------------------------------------------------------------------------
// Transpose + bf16 split: out[i*ldo + j] = split(src[j*lds + i]), i<R, j<C
// ---------------------------------------------------------------------------
__global__ void trans_split_kernel(const float* __restrict__ src, int lds,
                                   __nv_bfloat16* __restrict__ dh,
                                   __nv_bfloat16* __restrict__ dl,
                                   int ldo, int R, int C)
{
    __shared__ float t[32][33];
    const int i0 = blockIdx.x * 32;
    const int j0 = blockIdx.y * 32;
    const int tx = threadIdx.x, ty = threadIdx.y;
    for (int jj = ty; jj < 32; jj += 8) {
        const int j = j0 + jj, i = i0 + tx;
        float v = 0.f;
        if (j < C && i < R) v = src[(long)j * lds + i];
        t[jj][tx] = v;
    }
    __syncthreads();
    for (int ii = ty; ii < 32; ii += 8) {
        const int i = i0 + ii, j = j0 + tx;
        if (i < R && j < C) {
            __nv_bfloat16 h, l;
            split_bf16(t[tx][ii], h, l);
            dh[(long)i * ldo + j] = h;
            dl[(long)i * ldo + j] = l;
        }
    }
}

// ---------------------------------------------------------------------------
// Reductions / splits
// ---------------------------------------------------------------------------
__global__ void reduce_sum(const float4* __restrict__ P, float4* __restrict__ out,
                           int n4, int S)
{
    int i = blockIdx.x * blockDim.x + threadIdx.x;
    if (i >= n4) return;
    float4 s = P[i];
    for (int k = 1; k < S; ++k) {
        float4 t = P[(long)k * n4 + i];
        s.x += t.x; s.y += t.y; s.z += t.z; s.w += t.w;
    }
    out[i] = s;
}

__global__ void reduce_split_hl(const float2* __restrict__ P,
                                __nv_bfloat162* __restrict__ Wh,
                                __nv_bfloat162* __restrict__ Wl,
                                int n2, int S)
{
    int i = blockIdx.x * blockDim.x + threadIdx.x;
    if (i >= n2) return;
    float2 s = P[i];
    for (int k = 1; k < S; ++k) {
        float2 t = P[(long)k * n2 + i];
        s.x += t.x; s.y += t.y;
    }
    __nv_bfloat162 h, l;
    split_bf16(s.x, h.x, l.x);
    split_bf16(s.y, h.y, l.y);
    Wh[i] = h; Wl[i] = l;
}

__global__ void reduce_split_h(const float2* __restrict__ P,
                               __nv_bfloat162* __restrict__ Wh,
                               int n2, int S)
{
    int i = blockIdx.x * blockDim.x + threadIdx.x;
    if (i >= n2) return;
    float2 s = P[i];
    for (int k = 1; k < S; ++k) {
        float2 t = P[(long)k * n2 + i];
        s.x += t.x; s.y += t.y;
    }
    __nv_bfloat162 h;
    h.x = __float2bfloat16_rn(s.x);
    h.y = __float2bfloat16_rn(s.y);
    Wh[i] = h;
}

__global__ void split_mat_bf16(const float2* __restrict__ src,
                               __nv_bfloat162* __restrict__ hi,
                               __nv_bfloat162* __restrict__ lo, long n2)
{
    long i = (long)blockIdx.x * blockDim.x + threadIdx.x;
    if (i >= n2) return;
    float2 v = src[i];
    __nv_bfloat162 h, l;
    split_bf16(v.x, h.x, l.x);
    split_bf16(v.y, h.y, l.y);
    hi[i] = h; lo[i] = l;
}

__global__ void reduce_G(const float* __restrict__ P, float* __restrict__ G, int S)
{
    int i = blockIdx.x * blockDim.x + threadIdx.x;
    if (i >= DM * DM) return;
    float s = 0.f;
    for (int k = 0; k < S; ++k) s += P[(long)k * DM * DM + i];
    if ((i / DM) == (i % DM)) s += RHO_F;
    G[i] = s;
}

__global__ void reduce_ns(const float4* __restrict__ P, const float4* __restrict__ Xc,
                          float4* __restrict__ Xn, int n4, int S)
{
    int i = blockIdx.x * blockDim.x + threadIdx.x;
    if (i >= n4) return;
    float4 s = P[i];
    for (int k = 1; k < S; ++k) {
        float4 t = P[(long)k * n4 + i];
        s.x += t.x; s.y += t.y; s.z += t.z; s.w += t.w;
    }
    float4 x = Xc[i];
    Xn[i] = make_float4(2.f * x.x - s.x, 2.f * x.y - s.y,
                        2.f * x.z - s.z, 2.f * x.w - s.w);
}

__global__ void ninf_kernel(const float* __restrict__ G)
{
    __shared__ float sm[DM];
    const int i = threadIdx.x;
    float s = 0.f;
    for (int j = 0; j < DM; ++j) s += fabsf(G[(long)j * DM + i]);
    sm[i] = s;
    __syncthreads();
    for (int o = DM / 2; o > 0; o >>= 1) {
        if (i < o) sm[i] = fmaxf(sm[i], sm[i + o]);
        __syncthreads();
    }
    if (i == 0) g_ninf = sm[0];
}

__global__ void x0_kernel(float* __restrict__ X)
{
    int i = blockIdx.x * blockDim.x + threadIdx.x;
    if (i >= DM * DM) return;
    float c = 2.0f / (RHO_F + g_ninf);
    X[i] = ((i / DM) == (i % DM)) ? c : 0.0f;
}

// ---------------------------------------------------------------------------
// Row-normalize kernels
// ---------------------------------------------------------------------------
__device__ __forceinline__ float block_sum128(float v, float* red)
{
    for (int o = 16; o > 0; o >>= 1) v += __shfl_xor_sync(0xffffffff, v, o);
    if ((threadIdx.x & 31) == 0) red[threadIdx.x >> 5] = v;
    __syncthreads();
    float tot = red[0] + red[1] + red[2] + red[3];
    __syncthreads();
    return tot;
}

__global__ void norm_center_kernel(const float* __restrict__ img,
                                   const float* __restrict__ mean,
                                   float* __restrict__ out)
{
    __shared__ float red[4];
    const int r = blockIdx.x, t = threadIdx.x;
    float4 v = ((const float4*)(img + (long)r * DM))[t];
    float ss = v.x * v.x + v.y * v.y + v.z * v.z + v.w * v.w;
    float inv = 1.0f / fmaxf(sqrtf(block_sum128(ss, red)), EPS_F);
    float4 mv = ((const float4*)mean)[t];
    float4 c = make_float4(v.x * inv - mv.x, v.y * inv - mv.y,
                           v.z * inv - mv.z, v.w * inv - mv.w);
    float ss2 = c.x * c.x + c.y * c.y + c.z * c.z + c.w * c.w;
    float inv2 = 1.0f / fmaxf(sqrtf(block_sum128(ss2, red)), EPS_F);
    ((float4*)(out + (long)r * DM))[t] =
        make_float4(c.x * inv2, c.y * inv2, c.z * inv2, c.w * inv2);
}

__global__ void norm_rows_kernel(const float* __restrict__ in, float* __restrict__ out)
{
    __shared__ float red[4];
    const int r = blockIdx.x, t = threadIdx.x;
    float4 v = ((const float4*)(in + (long)r * DM))[t];
    float ss = v.x * v.x + v.y * v.y + v.z * v.z + v.w * v.w;
    float inv = 1.0f / fmaxf(sqrtf(block_sum128(ss, red)), EPS_F);
    ((float4*)(out + (long)r * DM))[t] =
        make_float4(v.x * inv, v.y * inv, v.z * inv, v.w * inv);
}

__global__ void final_norm_kernel(const float* __restrict__ rec,
                                  const float* __restrict__ mean,
                                  float* __restrict__ out)
{
    __shared__ float red[4];
    const int r = blockIdx.x, t = threadIdx.x;
    float4 v = ((const float4*)(rec + (long)r * DM))[t];
    float ss = v.x * v.x + v.y * v.y + v.z * v.z + v.w * v.w;
    float inv = 1.0f / fmaxf(sqrtf(block_sum128(ss, red)), EPS_F);
    float4 mv = ((const float4*)mean)[t];
    float4 c = make_float4(v.x * inv + mv.x, v.y * inv + mv.y,
                           v.z * inv + mv.z, v.w * inv + mv.w);
    float ss2 = c.x * c.x + c.y * c.y + c.z * c.z + c.w * c.w;
    float inv2 = 1.0f / fmaxf(sqrtf(block_sum128(ss2, red)), EPS_F);
    ((float4*)(out + (long)r * DM))[t] =
        make_float4(c.x * inv2, c.y * inv2, c.z * inv2, c.w * inv2);
}

// ---------------------------------------------------------------------------
// Host orchestration
// ---------------------------------------------------------------------------
extern "C" void kernel_launch(void* const* d_in, const int* in_sizes, int n_in,
                              void* d_out, int out_size)
{
    const float* dImg  = (const float*)d_in[0];
    const float* dTxt  = (const float*)d_in[1];
    const float* dMean = (const float*)d_in[2];
    const float* dDict = (const float*)d_in[3];
    float* outRecon = (float*)d_out;
    float* outTxt   = (float*)d_out + (long)BROWS * DM;

    float *Q, *Z, *E, *P, *W, *Y, *G, *XA, *XB, *T;
    __nv_bfloat16 *Vh, *Vl, *Th, *Tl, *Dh, *Dl, *DTh, *DTl, *Eh, *El,
                  *Wh, *Wl, *Yh, *Yl;
    cudaGetSymbolAddress((void**)&Q,   g_Q);
    cudaGetSymbolAddress((void**)&Z,   g_Z);
    cudaGetSymbolAddress((void**)&Vh,  g_Vh);
    cudaGetSymbolAddress((void**)&Vl,  g_Vl);
    cudaGetSymbolAddress((void**)&Th,  g_Th);
    cudaGetSymbolAddress((void**)&Tl,  g_Tl);
    cudaGetSymbolAddress((void**)&Dh,  g_Dh);
    cudaGetSymbolAddress((void**)&Dl,  g_Dl);
    cudaGetSymbolAddress((void**)&DTh, g_DTh);
    cudaGetSymbolAddress((void**)&DTl, g_DTl);
    cudaGetSymbolAddress((void**)&E,   g_E);
    cudaGetSymbolAddress((void**)&Eh,  g_Eh);
    cudaGetSymbolAddress((void**)&El,  g_El);
    cudaGetSymbolAddress((void**)&P,   g_P);
    cudaGetSymbolAddress((void**)&W,   g_W);
    cudaGetSymbolAddress((void**)&Wh,  g_Wh);
    cudaGetSymbolAddress((void**)&Wl,  g_Wl);
    cudaGetSymbolAddress((void**)&Y,   g_Y);
    cudaGetSymbolAddress((void**)&Yh,  g_Yh);
    cudaGetSymbolAddress((void**)&Yl,  g_Yl);
    cudaGetSymbolAddress((void**)&G,   g_G);
    cudaGetSymbolAddress((void**)&XA,  g_XA);
    cudaGetSymbolAddress((void**)&XB,  g_XB);
    cudaGetSymbolAddress((void**)&T,   g_T);

    cudaFuncSetAttribute(bmma_gemm<0, 3>, cudaFuncAttributeMaxDynamicSharedMemorySize, BSMEM);
    cudaFuncSetAttribute(bmma_gemm<1, 3>, cudaFuncAttributeMaxDynamicSharedMemorySize, BSMEM);
    cudaFuncSetAttribute(bmma_gemm<2, 3>, cudaFuncAttributeMaxDynamicSharedMemorySize, BSMEM);
    cudaFuncSetAttribute(bmma_gemm<0, 1>, cudaFuncAttributeMaxDynamicSharedMemorySize, BSMEM);
    cudaFuncSetAttribute(bmma_gemm<3, 1>, cudaFuncAttributeMaxDynamicSharedMemorySize, BSMEM);

    const int NT = (CDICT + BN - 1) / BN;   // 79 tiles over N=10000
    const int KSG = CDICT / GSLICES;        // 400 (G split-K, 25 slices)
    const int KSmma = CPAD / KSPLIT;        // 1152 (loop split-K, 9 slices)

    // 0) zero-pad-sensitive buffers
    cudaMemsetAsync(Q,   0, sizeof(float) * (size_t)BROWS * CPAD, 0);
    cudaMemsetAsync(DTh, 0, sizeof(__nv_bfloat16) * (size_t)DM * CPAD, 0);
    cudaMemsetAsync(DTl, 0, sizeof(__nv_bfloat16) * (size_t)DM * CPAD, 0);
    cudaMemsetAsync(Dh,  0, sizeof(__nv_bfloat16) * (size_t)CPAD * DM, 0);
    cudaMemsetAsync(Dl,  0, sizeof(__nv_bfloat16) * (size_t)CPAD * DM, 0);
    cudaMemsetAsync(E,   0, sizeof(float) * (size_t)DM * CPAD, 0);

    // 1) centered inputs + text output; splits of Y and D / D^T
    norm_center_kernel<<<BROWS, 128>>>(dImg, dMean, Y);
    norm_rows_kernel<<<BROWS, 128>>>(dTxt, outTxt);
    split_mat_bf16<<<(BROWS * DM / 2 + 255) / 256, 256>>>(
        (const float2*)Y, (__nv_bfloat162*)Yh, (__nv_bfloat162*)Yl, BROWS * DM / 2);
    split_mat_bf16<<<(int)(((long)CDICT * DM / 2 + 255) / 256), 256>>>(
        (const float2*)dDict, (__nv_bfloat162*)Dh, (__nv_bfloat162*)Dl,
        (long)CDICT * DM / 2);
    trans_split_kernel<<<dim3(16, (CPAD + 31) / 32), dim3(32, 8)>>>(
        dDict, DM, DTh, DTl, CPAD, DM, CDICT);

    // 2) Aty = Y @ D^T -> Q (bf16x3 tensor path; Q pads stay zero)
    bmma_gemm<0, 3><<<dim3(NT, 8, 1), 256, BSMEM>>>(
        Yh, Yl, DTh, DTl, Q, BROWS, CDICT, DM, DM, CPAD, CPAD,
        nullptr, nullptr, nullptr, nullptr, 0);

    // 3) G = D^T D + rho I (fp32 SIMT, 25-way split-K -> 400 CTAs)
    gemm_kernel<true, false><<<dim3(4, 4, GSLICES), 256>>>(
        dDict, dDict, P, DM, DM, KSG, DM, DM, DM);
    reduce_G<<<(DM * DM + 255) / 256, 256>>>(P, G, GSLICES);

    // 4) Newton-Schulz inverse (fp32 SIMT, 8-way split-K -> 128 CTAs)
    ninf_kernel<<<1, DM>>>(G);
    x0_kernel<<<(DM * DM + 255) / 256, 256>>>(XA);
    float* Xc = XA; float* Xn = XB;
    for (int t = 0; t < NS_ITERS; ++t) {
        gemm_kernel<false, false><<<dim3(4, 4, NSPLIT), 256>>>(
            G, Xc, P, DM, DM, DM / NSPLIT, DM, DM, DM);
        reduce_sum<<<(DM * DM / 4 + 255) / 256, 256>>>(
            (const float4*)P, (float4*)T, DM * DM / 4, NSPLIT);
        gemm_kernel<false, false><<<dim3(4, 4, NSPLIT), 256>>>(
            Xc, T, P, DM, DM, DM / NSPLIT, DM, DM, DM);
        reduce_ns<<<(DM * DM / 4 + 255) / 256, 256>>>(
            (const float4*)P, (const float4*)Xc, (float4*)Xn, DM * DM / 4, NSPLIT);
        float* tmp = Xc; Xc = Xn; Xn = tmp;
    }

    // 5) E = G^{-1} @ D^T via bf16x3 tensor path (E only ever consumed as
    //    bf16 hi/lo).  Xc split into the currently-idle Wh/Wl buffers.
    split_mat_bf16<<<(DM * DM / 2 + 255) / 256, 256>>>(
        (const float2*)Xc, (__nv_bfloat162*)Wh, (__nv_bfloat162*)Wl, DM * DM / 2);
    bmma_gemm<0, 3><<<dim3(NT, 4, 1), 256, BSMEM>>>(
        Wh, Wl, DTh, DTl, E, DM, CDICT, DM, DM, CPAD, CPAD,
        nullptr, nullptr, nullptr, nullptr, 0);
    split_mat_bf16<<<(int)(((long)DM * CPAD / 2 + 255) / 256), 256>>>(
        (const float2*)E, (__nv_bfloat162*)Eh, (__nv_bfloat162*)El,
        (long)DM * CPAD / 2);

    // 6) q = (Aty - (Aty @ D) @ E) / rho  (bf16x3 tensor path, in place on Q)
    split_mat_bf16<<<(int)(((long)BROWS * CPAD / 2 + 255) / 256), 256>>>(
        (const float2*)Q, (__nv_bfloat162*)Th, (__nv_bfloat162*)Tl,
        (long)BROWS * CPAD / 2);
    bmma_gemm<0, 3><<<dim3(4, 8, KSPLIT), 256, BSMEM>>>(
        Th, Tl, Dh, Dl, P, BROWS, DM, KSmma, CPAD, DM, DM,
        nullptr, nullptr, nullptr, nullptr, 0);
    reduce_split_hl<<<(BROWS * DM / 2 + 255) / 256, 256>>>(
        (const float2*)P, (__nv_bfloat162*)Wh, (__nv_bfloat162*)Wl,
        BROWS * DM / 2, KSPLIT);
    bmma_gemm<1, 3><<<dim3(NT, 8, 1), 256, BSMEM>>>(
        Wh, Wl, Eh, El, Q, BROWS, CDICT, DM, DM, CPAD, CPAD,
        Q, nullptr, nullptr, nullptr, 0);

    // 7) ADMM loop, (z, v) state form: t = q + z - (vD)E;
    //    z' = max(t - thr, 0); v' = 2z' - t.  u is never materialized.
    cudaMemsetAsync(Vh, 0, sizeof(__nv_bfloat16) * (size_t)BROWS * CPAD, 0);
    cudaMemsetAsync(Vl, 0, sizeof(__nv_bfloat16) * (size_t)BROWS * CPAD, 0);
    cudaMemsetAsync(Z,  0, sizeof(float) * (size_t)BROWS * CPAD, 0);
    for (int it = 0; it < ADMM_ITERS; ++it) {
        if (it < CHEAP_ITERS) {
            const int wl = (it == CHEAP_ITERS - 1) ? 1 : 0;
            bmma_gemm<0, 1><<<dim3(4, 8, KSPLIT), 256, BSMEM>>>(
                Vh, nullptr, Dh, nullptr, P, BROWS, DM, KSmma, CPAD, DM, DM,
                nullptr, nullptr, nullptr, nullptr, 0);
            reduce_split_h<<<(BROWS * DM / 2 + 255) / 256, 256>>>(
                (const float2*)P, (__nv_bfloat162*)Wh, BROWS * DM / 2, KSPLIT);
            bmma_gemm<3, 1><<<dim3(NT, 8, 1), 256, BSMEM>>>(
                Wh, nullptr, Eh, nullptr, nullptr, BROWS, CDICT, DM, DM, CPAD, CPAD,
                Q, Z, Vh, Vl, wl);
        } else {
            const int last = (it == ADMM_ITERS - 1) ? 1 : 0;
            bmma_gemm<0, 3><<<dim3(4, 8, KSPLIT), 256, BSMEM>>>(
                Vh, Vl, Dh, Dl, P, BROWS, DM, KSmma, CPAD, DM, DM,
                nullptr, nullptr, nullptr, nullptr, 0);
            reduce_split_hl<<<(BROWS * DM / 2 + 255) / 256, 256>>>(
                (const float2*)P, (__nv_bfloat162*)Wh, (__nv_bfloat162*)Wl,
                BROWS * DM / 2, KSPLIT);
            bmma_gemm<2, 3><<<dim3(NT, 8, 1), 256, BSMEM>>>(
                Wh, Wl, Eh, El, nullptr, BROWS, CDICT, DM, DM, CPAD, CPAD,
                Q, Z, Vh, Vl, last);
        }
    }

    // 8) recon = normalize(normalize(z @ D) + mean)   (z in Vh/Vl; accurate)
    bmma_gemm<0, 3><<<dim3(4, 8, KSPLIT), 256, BSMEM>>>(
        Vh, Vl, Dh, Dl, P, BROWS, DM, KSmma, CPAD, DM, DM,
        nullptr, nullptr, nullptr, nullptr, 0);
    reduce_sum<<<(BROWS * DM / 4 + 255) / 256, 256>>>(
        (const float4*)P, (float4*)W, BROWS * DM / 4, KSPLIT);
    final_norm_kernel<<<BROWS, 128>>>(W, dMean, outRecon);
}